// round 6
// baseline (speedup 1.0000x reference)
#include <cuda_runtime.h>
#include <cuda_bf16.h>
#include <math.h>
#include <stdint.h>

#define QL 2048
#define CL 2048
#define HD 1024
#define NH 16
#define DH 64
#define FF 4096
#define RL 4096
typedef __nv_bfloat16 bf16;
typedef __nv_bfloat162 bf162;

// ---------------- scratch ----------------
__device__ float g_v[CL * HD];
__device__ float g_scores[(size_t)NH * QL * CL];
__device__ float g_eseg[2 * NH * QL];
__device__ float g_attnout[QL * HD];
__device__ float g_ffnin[QL * HD];
__device__ float g_ffnout[QL * HD];
__device__ bf16 g_csh[QL * HD], g_csl[QL * HD];
__device__ bf16 g_ctxh[CL * HD], g_ctxl[CL * HD];
__device__ bf16 g_posh[RL * HD], g_posl[RL * HD];
__device__ bf16 g_qch[QL * HD], g_qcl[QL * HD];
__device__ bf16 g_qph[QL * HD], g_qpl[QL * HD];
__device__ bf16 g_kh[CL * HD], g_kl[CL * HD];
__device__ bf16 g_rh[RL * HD], g_rl[RL * HD];
__device__ bf16 g_ath[QL * HD], g_atl[QL * HD];
__device__ bf16 g_fih[QL * HD], g_fil[QL * HD];
__device__ bf16 g_fhh[(size_t)QL * FF], g_fhl[(size_t)QL * FF];
__device__ bf16 g_wqh[HD * HD], g_wql[HD * HD];
__device__ bf16 g_wkh[HD * HD], g_wkl[HD * HD];
__device__ bf16 g_wvh[HD * HD], g_wvl[HD * HD];
__device__ bf16 g_wrh[HD * HD], g_wrl[HD * HD];
__device__ bf16 g_woh[HD * HD], g_wol[HD * HD];
__device__ bf16 g_w1h[(size_t)FF * HD], g_w1l[(size_t)FF * HD];
__device__ bf16 g_w2h[(size_t)FF * HD], g_w2l[(size_t)FF * HD];
__device__ bf16 g_vth[HD * CL], g_vtl[HD * CL];

#define SWZ(o) ((o) ^ (((o) >> 3) & 0x70))

__device__ __forceinline__ uint32_t smem_u32(const void* p) {
    uint32_t a;
    asm("{ .reg .u64 t; cvta.to.shared.u64 t, %1; cvt.u32.u64 %0, t; }" : "=r"(a) : "l"(p));
    return a;
}
__device__ __forceinline__ void cpasync16(uint32_t s, const void* g) {
    asm volatile("cp.async.cg.shared.global [%0], [%1], 16;" :: "r"(s), "l"(g));
}
#define CP_COMMIT() asm volatile("cp.async.commit_group;")
#define CP_WAIT(n) asm volatile("cp.async.wait_group %0;" :: "n"(n))

__device__ __forceinline__ void splitbf(float x, bf16& h, bf16& l) {
    h = __float2bfloat16(x);
    l = __float2bfloat16(x - __bfloat162float(h));
}
__device__ __forceinline__ void wsplit2(bf16* oh, bf16* ol, long long off, float x, float y) {
    bf16 h0, l0, h1, l1;
    splitbf(x, h0, l0); splitbf(y, h1, l1);
    *(bf162*)(oh + off) = __halves2bfloat162(h0, h1);
    *(bf162*)(ol + off) = __halves2bfloat162(l0, l1);
}
__device__ __forceinline__ float warpSum(float v) {
#pragma unroll
    for (int o = 16; o; o >>= 1) v += __shfl_xor_sync(0xffffffffu, v, o);
    return v;
}
__device__ __forceinline__ float warpMax(float v) {
#pragma unroll
    for (int o = 16; o; o >>= 1) v = fmaxf(v, __shfl_xor_sync(0xffffffffu, v, o));
    return v;
}
__device__ __forceinline__ void mma_bf16(float* d, const uint32_t* a, const uint32_t* b) {
    asm volatile(
        "mma.sync.aligned.m16n8k16.row.col.f32.bf16.bf16.f32 "
        "{%0,%1,%2,%3}, {%4,%5,%6,%7}, {%8,%9}, {%0,%1,%2,%3};"
        : "+f"(d[0]), "+f"(d[1]), "+f"(d[2]), "+f"(d[3])
        : "r"(a[0]), "r"(a[1]), "r"(a[2]), "r"(a[3]), "r"(b[0]), "r"(b[1]));
}
__device__ __forceinline__ void ldm4(uint32_t* r, uint32_t base, int row0, int k0, int lane) {
    int row = row0 + (lane & 15);
    int kc = k0 + ((lane >> 4) << 3);
    uint32_t addr = base + SWZ((uint32_t)row * 128 + (uint32_t)kc * 2);
    asm volatile("ldmatrix.sync.aligned.m8n8.x4.shared.b16 {%0,%1,%2,%3}, [%4];"
                 : "=r"(r[0]), "=r"(r[1]), "=r"(r[2]), "=r"(r[3]) : "r"(addr));
}

// ---------------- converters ----------------
__global__ void __launch_bounds__(256) convT_kernel(
    const float* __restrict__ in, bf16* __restrict__ oh, bf16* __restrict__ ol, int R, int Cc)
{
    __shared__ float t[32][33];
    const int tx = threadIdx.x & 31, ty8 = threadIdx.x >> 5;
    const int r0 = blockIdx.y * 32, c0 = blockIdx.x * 32;
    for (int j = ty8; j < 32; j += 8) t[j][tx] = in[(long long)(r0 + j) * Cc + c0 + tx];
    __syncthreads();
    for (int j = ty8; j < 32; j += 8) {
        bf16 h, l; splitbf(t[tx][j], h, l);
        long long o = (long long)(c0 + j) * R + r0 + tx;
        oh[o] = h; ol[o] = l;
    }
}
__global__ void __launch_bounds__(256) conv_kernel(
    const float* __restrict__ in, bf16* __restrict__ oh, bf16* __restrict__ ol, int n)
{
    int i = blockIdx.x * 256 + threadIdx.x;
    if (i < n) { bf16 h, l; splitbf(in[i], h, l); oh[i] = h; ol[i] = l; }
}
__global__ void __launch_bounds__(256) split4_kernel(
    const float* __restrict__ in, bf16* __restrict__ oh, bf16* __restrict__ ol, int n4)
{
    int i = blockIdx.x * 256 + threadIdx.x;
    if (i >= n4) return;
    float4 v = *(const float4*)(in + i * 4);
    wsplit2(oh, ol, (long long)i * 4, v.x, v.y);
    wsplit2(oh, ol, (long long)i * 4 + 2, v.z, v.w);
}

// ---------------- HMMA GEMM: C[M,N] = A[M,K] @ B[N,K]^T, bf16 hi/lo ----------
// BM=128, BN=128, BK=64; 256 threads, 8 warps (4m x 2n), warp tile 32x64; 2-stage
#define ST_AH 0
#define ST_AL 16384
#define ST_BH 32768
#define ST_BL 49152
#define ST_SZ 65536
#define GM_SMEM (2 * ST_SZ)

__global__ void __launch_bounds__(256) hmma_gemm_kernel(
    const bf16* __restrict__ Ah, const bf16* __restrict__ Al,
    const bf16* __restrict__ Bh, const bf16* __restrict__ Bl,
    float* __restrict__ C, const float* __restrict__ biasC,
    bf16* __restrict__ O1h, bf16* __restrict__ O1l, const float* __restrict__ bias1,
    bf16* __restrict__ O2h, bf16* __restrict__ O2l, const float* __restrict__ bias2,
    int K, int lda, int ldb, int ldc, int relu)
{
    extern __shared__ char smem[];
    const uint32_t sbase = smem_u32(smem);
    const int tid = threadIdx.x, lane = tid & 31, w = tid >> 5;
    const int g = lane >> 2, tig = lane & 3;
    const int m0 = blockIdx.y * 128, n0 = blockIdx.x * 128;
    const int wm = (w >> 1) * 32, wn = (w & 1) * 64;

    auto load_stage = [&](int s, int k0) {
        uint32_t sb = sbase + s * ST_SZ;
#pragma unroll
        for (int i = 0; i < 4; i++) {
            int u = tid + (i << 8);
            int row = u >> 3, c16 = u & 7;
            uint32_t sw = SWZ((uint32_t)row * 128 + (uint32_t)(c16 << 4));
            const long long ga = (long long)(m0 + row) * lda + k0 + (c16 << 3);
            const long long gb = (long long)(n0 + row) * ldb + k0 + (c16 << 3);
            cpasync16(sb + ST_AH + sw, Ah + ga);
            cpasync16(sb + ST_AL + sw, Al + ga);
            cpasync16(sb + ST_BH + sw, Bh + gb);
            cpasync16(sb + ST_BL + sw, Bl + gb);
        }
    };

    float acc[2][8][4] = {};
    const int NC = K >> 6;
    load_stage(0, 0);
    CP_COMMIT();
    for (int c = 0; c < NC; c++) {
        if (c + 1 < NC) { load_stage((c + 1) & 1, (c + 1) << 6); CP_COMMIT(); CP_WAIT(1); }
        else CP_WAIT(0);
        __syncthreads();
        const uint32_t sb = sbase + (c & 1) * ST_SZ;
#pragma unroll
        for (int ks = 0; ks < 4; ks++) {
            uint32_t ah[2][4], al[2][4], bh[4][4], bl[4][4];
            ldm4(ah[0], sb + ST_AH, wm, ks * 16, lane);
            ldm4(ah[1], sb + ST_AH, wm + 16, ks * 16, lane);
            ldm4(al[0], sb + ST_AL, wm, ks * 16, lane);
            ldm4(al[1], sb + ST_AL, wm + 16, ks * 16, lane);
#pragma unroll
            for (int p = 0; p < 4; p++) {
                ldm4(bh[p], sb + ST_BH, wn + p * 16, ks * 16, lane);
                ldm4(bl[p], sb + ST_BL, wn + p * 16, ks * 16, lane);
            }
#pragma unroll
            for (int mt = 0; mt < 2; mt++)
#pragma unroll
                for (int nt = 0; nt < 8; nt++) {
                    const int p = nt >> 1, o = nt & 1;
                    uint32_t fbh[2] = { bh[p][o], bh[p][2 + o] };
                    uint32_t fbl[2] = { bl[p][o], bl[p][2 + o] };
                    mma_bf16(acc[mt][nt], ah[mt], fbh);
                    mma_bf16(acc[mt][nt], ah[mt], fbl);
                    mma_bf16(acc[mt][nt], al[mt], fbh);
                }
        }
        __syncthreads();
    }

#pragma unroll
    for (int mt = 0; mt < 2; mt++)
#pragma unroll
        for (int nt = 0; nt < 8; nt++) {
#pragma unroll
            for (int h = 0; h < 2; h++) {
                const int row = m0 + wm + mt * 16 + g + h * 8;
                const int col = n0 + wn + nt * 8 + 2 * tig;
                float x = acc[mt][nt][h * 2], y = acc[mt][nt][h * 2 + 1];
                const long long off = (long long)row * ldc + col;
                if (C) {
                    float b0 = biasC ? biasC[col] : 0.f, b1 = biasC ? biasC[col + 1] : 0.f;
                    float2 o = { x + b0, y + b1 };
                    *(float2*)(C + off) = o;
                }
                if (O1h) {
                    float b0 = bias1 ? bias1[col] : 0.f, b1 = bias1 ? bias1[col + 1] : 0.f;
                    float vx = x + b0, vy = y + b1;
                    if (relu) { vx = fmaxf(vx, 0.f); vy = fmaxf(vy, 0.f); }
                    wsplit2(O1h, O1l, off, vx, vy);
                }
                if (O2h) {
                    float b0 = bias2 ? bias2[col] : 0.f, b1 = bias2 ? bias2[col + 1] : 0.f;
                    wsplit2(O2h, O2l, off, x + b0, y + b1);
                }
            }
        }
}

// ---------------- HMMA score kernel (unchanged from R5) ----------------
#define S_QCH 0
#define S_QCL 16384
#define S_QPH 32768
#define S_QPL 49152
#define S_KH  65536
#define S_KL  81920
#define S_RH  98304
#define S_RL  131072
#define S_ST  163840
#define S_SMEM (163840 + 8 * 3200)

__global__ void __launch_bounds__(256) score_hmma_kernel(
    const float* __restrict__ mask, const unsigned char* __restrict__ segmat)
{
    extern __shared__ char smem[];
    const uint32_t sbase = smem_u32(smem);
    const int tid = threadIdx.x, lane = tid & 31, w = tid >> 5;
    const int g = lane >> 2, tig = lane & 3;
    const int n = blockIdx.z, q0 = blockIdx.y * 128, c0 = blockIdx.x * 128;
    const int nDH = n * DH;

    auto ldtile = [&](int dsth, int dstl, const bf16* srch, const bf16* srcl, long long rbase, int ldg) {
#pragma unroll
        for (int i = 0; i < 4; i++) {
            int u = tid + (i << 8);
            int row = u >> 3, c16 = u & 7;
            uint32_t sw = SWZ((uint32_t)row * 128 + (uint32_t)(c16 << 4));
            long long gofs = (rbase + row) * ldg + nDH + (c16 << 3);
            *(uint4*)(smem + dsth + sw) = *(const uint4*)(srch + gofs);
            *(uint4*)(smem + dstl + sw) = *(const uint4*)(srcl + gofs);
        }
    };
    ldtile(S_QCH, S_QCL, g_qch, g_qcl, q0, HD);
    ldtile(S_QPH, S_QPL, g_qph, g_qpl, q0, HD);
    ldtile(S_KH, S_KL, g_kh, g_kl, c0, HD);
    const int rstart = QL + c0 - q0 - 127;
#pragma unroll
    for (int i = 0; i < 8; i++) {
        int u = tid + (i << 8);
        int row = u >> 3, c16 = u & 7;
        int rg = rstart + row; if (rg > RL - 1) rg = RL - 1;
        uint32_t sw = SWZ((uint32_t)row * 128 + (uint32_t)(c16 << 4));
        long long gofs = (long long)rg * HD + nDH + (c16 << 3);
        *(uint4*)(smem + S_RH + sw) = *(const uint4*)(g_rh + gofs);
        *(uint4*)(smem + S_RL + sw) = *(const uint4*)(g_rl + gofs);
    }
    __syncthreads();

    const int w0 = w * 16;
    const float e0a = g_eseg[(0 * NH + n) * QL + q0 + w0 + g];
    const float e1a = g_eseg[(1 * NH + n) * QL + q0 + w0 + g];
    const float e0b = g_eseg[(0 * NH + n) * QL + q0 + w0 + g + 8];
    const float e1b = g_eseg[(1 * NH + n) * QL + q0 + w0 + g + 8];
    float* stg = (float*)(smem + S_ST + w * 3200);

    for (int ch = 0; ch < 4; ch++) {
        float accA[4][4] = {};
        float accB[6][4] = {};
        const int s0 = ch * 32 - w0 + 112;
#pragma unroll
        for (int ks = 0; ks < 4; ks++) {
            uint32_t ach[4], acl[4], aph[4], apl[4];
            ldm4(ach, sbase + S_QCH, w0, ks * 16, lane);
            ldm4(acl, sbase + S_QCL, w0, ks * 16, lane);
            ldm4(aph, sbase + S_QPH, w0, ks * 16, lane);
            ldm4(apl, sbase + S_QPL, w0, ks * 16, lane);
            uint32_t kh[2][4], kl[2][4];
            ldm4(kh[0], sbase + S_KH, ch * 32, ks * 16, lane);
            ldm4(kh[1], sbase + S_KH, ch * 32 + 16, ks * 16, lane);
            ldm4(kl[0], sbase + S_KL, ch * 32, ks * 16, lane);
            ldm4(kl[1], sbase + S_KL, ch * 32 + 16, ks * 16, lane);
#pragma unroll
            for (int nt = 0; nt < 4; nt++) {
                const int p = nt >> 1, o = nt & 1;
                uint32_t fbh[2] = { kh[p][o], kh[p][2 + o] };
                uint32_t fbl[2] = { kl[p][o], kl[p][2 + o] };
                mma_bf16(accA[nt], ach, fbh);
                mma_bf16(accA[nt], ach, fbl);
                mma_bf16(accA[nt], acl, fbh);
            }
            uint32_t rh[3][4], rl[3][4];
#pragma unroll
            for (int p = 0; p < 3; p++) {
                ldm4(rh[p], sbase + S_RH, s0 + p * 16, ks * 16, lane);
                ldm4(rl[p], sbase + S_RL, s0 + p * 16, ks * 16, lane);
            }
#pragma unroll
            for (int nt = 0; nt < 6; nt++) {
                const int p = nt >> 1, o = nt & 1;
                uint32_t fbh[2] = { rh[p][o], rh[p][2 + o] };
                uint32_t fbl[2] = { rl[p][o], rl[p][2 + o] };
                mma_bf16(accB[nt], aph, fbh);
                mma_bf16(accB[nt], aph, fbl);
                mma_bf16(accB[nt], apl, fbh);
            }
        }
#pragma unroll
        for (int nt = 0; nt < 6; nt++) {
            int cc = nt * 8 + 2 * tig;
            stg[g * 50 + cc] = accB[nt][0];
            stg[g * 50 + cc + 1] = accB[nt][1];
            stg[(g + 8) * 50 + cc] = accB[nt][2];
            stg[(g + 8) * 50 + cc + 1] = accB[nt][3];
        }
        __syncwarp();
#pragma unroll
        for (int nt = 0; nt < 4; nt++) {
            const int jl = nt * 8 + 2 * tig;
            const float bd0 = stg[g * 50 + jl - g + 15], bd1 = stg[g * 50 + jl - g + 16];
            const float bd2 = stg[(g + 8) * 50 + jl - g + 7], bd3 = stg[(g + 8) * 50 + jl - g + 8];
            const int qa = q0 + w0 + g, cc = c0 + ch * 32 + jl;
            const size_t ma = (size_t)qa * CL + cc;
            const size_t mb = (size_t)(qa + 8) * CL + cc;
            float2 mka = *(const float2*)(mask + ma);
            float2 mkb = *(const float2*)(mask + mb);
            uchar2 sga = *(const uchar2*)(segmat + ma);
            uchar2 sgb = *(const uchar2*)(segmat + mb);
            float2 oa, ob;
            oa.x = (accA[nt][0] + bd0 + (sga.x ? e1a : e0a)) * 0.125f - 1e30f * mka.x;
            oa.y = (accA[nt][1] + bd1 + (sga.y ? e1a : e0a)) * 0.125f - 1e30f * mka.y;
            ob.x = (accA[nt][2] + bd2 + (sgb.x ? e1b : e0b)) * 0.125f - 1e30f * mkb.x;
            ob.y = (accA[nt][3] + bd3 + (sgb.y ? e1b : e0b)) * 0.125f - 1e30f * mkb.y;
            *(float2*)(g_scores + ((size_t)n * QL + qa) * CL + cc) = oa;
            *(float2*)(g_scores + ((size_t)n * QL + qa + 8) * CL + cc) = ob;
        }
        __syncwarp();
    }
}

// ---------------- fused online-softmax + probs@V ----------------
// grid (QL/128, NH), 256 threads (8 warps x 16 q rows). Streams score rows,
// maintains running max/sum, accumulates O with rescaling. Writes split attn.
#define PV_V0 0
#define PV_V1 16384
#define PV_PH 32768
#define PV_PL 49152
#define PV_SMEM 65536

__global__ void __launch_bounds__(256) pv_fused_kernel()
{
    extern __shared__ char smem[];
    const uint32_t sbase = smem_u32(smem);
    const int tid = threadIdx.x, lane = tid & 31, w = tid >> 5;
    const int g = lane >> 2, tig = lane & 3;
    const int n = blockIdx.y, q0 = blockIdx.x * 128;
    const int w0 = w * 16;
    const int ri = lane >> 1, half = lane & 1;

    const bf16* vt_h = g_vth + (long long)(n * 64) * CL;
    const bf16* vt_l = g_vtl + (long long)(n * 64) * CL;

    auto loadV = [&](int s, int c0) {
        uint32_t sb = sbase + (s ? PV_V1 : PV_V0);
#pragma unroll
        for (int i = 0; i < 2; i++) {
            int u = tid + (i << 8);
            int row = u >> 3, c16 = u & 7;
            uint32_t sw = SWZ((uint32_t)row * 128 + (uint32_t)(c16 << 4));
            long long gofs = (long long)row * CL + c0 + (c16 << 3);
            cpasync16(sb + sw, vt_h + gofs);
            cpasync16(sb + 8192 + sw, vt_l + gofs);
        }
    };

    float m_run = -3.0e38f, l_run = 0.f;
    float accO[8][4] = {};
    const float* srow = g_scores + ((size_t)n * QL + q0 + w0 + ri) * CL + half * 32;

    loadV(0, 0); CP_COMMIT();
    for (int cb = 0; cb < CL / 64; cb++) {
        if (cb + 1 < CL / 64) { loadV((cb + 1) & 1, (cb + 1) * 64); CP_COMMIT(); CP_WAIT(1); }
        else CP_WAIT(0);
        __syncthreads();
        const uint32_t vb = sbase + ((cb & 1) ? PV_V1 : PV_V0);

        float4 sv[8];
#pragma unroll
        for (int j = 0; j < 8; j++) sv[j] = *(const float4*)(srow + (size_t)cb * 64 + j * 4);
        float cmax = -3.0e38f;
#pragma unroll
        for (int j = 0; j < 8; j++)
            cmax = fmaxf(cmax, fmaxf(fmaxf(sv[j].x, sv[j].y), fmaxf(sv[j].z, sv[j].w)));
        cmax = fmaxf(cmax, __shfl_xor_sync(0xffffffffu, cmax, 1));
        const float m_new = fmaxf(m_run, cmax);
        const float scale = __expf(m_run - m_new);
        m_run = m_new;
        float csum = 0.f;
#pragma unroll
        for (int j = 0; j < 8; j++) {
            float p0 = __expf(sv[j].x - m_new), p1 = __expf(sv[j].y - m_new);
            float p2 = __expf(sv[j].z - m_new), p3 = __expf(sv[j].w - m_new);
            csum += (p0 + p1) + (p2 + p3);
            const int c = half * 32 + j * 4;
            const uint32_t sw = SWZ((uint32_t)(w0 + ri) * 128 + (uint32_t)c * 2);
            bf16 h0, l0, h1, l1, h2, l2, h3, l3;
            splitbf(p0, h0, l0); splitbf(p1, h1, l1); splitbf(p2, h2, l2); splitbf(p3, h3, l3);
            *(bf162*)(smem + PV_PH + sw) = __halves2bfloat162(h0, h1);
            *(bf162*)(smem + PV_PH + sw + 4) = __halves2bfloat162(h2, h3);
            *(bf162*)(smem + PV_PL + sw) = __halves2bfloat162(l0, l1);
            *(bf162*)(smem + PV_PL + sw + 4) = __halves2bfloat162(l2, l3);
        }
        csum += __shfl_xor_sync(0xffffffffu, csum, 1);
        l_run = l_run * scale + csum;
        const float sA = __shfl_sync(0xffffffffu, scale, 2 * g);
        const float sB = __shfl_sync(0xffffffffu, scale, 2 * g + 16);
#pragma unroll
        for (int t = 0; t < 8; t++) {
            accO[t][0] *= sA; accO[t][1] *= sA;
            accO[t][2] *= sB; accO[t][3] *= sB;
        }
        __syncwarp();
#pragma unroll
        for (int ks = 0; ks < 4; ks++) {
            uint32_t aH[4], aL[4];
            ldm4(aH, sbase + PV_PH, w0, ks * 16, lane);
            ldm4(aL, sbase + PV_PL, w0, ks * 16, lane);
            uint32_t bH[4][4], bL[4][4];
#pragma unroll
            for (int p = 0; p < 4; p++) {
                ldm4(bH[p], vb, p * 16, ks * 16, lane);
                ldm4(bL[p], vb + 8192, p * 16, ks * 16, lane);
            }
#pragma unroll
            for (int t = 0; t < 8; t++) {
                const int p = t >> 1, o = t & 1;
                uint32_t fbh[2] = { bH[p][o], bH[p][2 + o] };
                uint32_t fbl[2] = { bL[p][o], bL[p][2 + o] };
                mma_bf16(accO[t], aH, fbh);
                mma_bf16(accO[t], aH, fbl);
                mma_bf16(accO[t], aL, fbh);
            }
        }
        __syncthreads();
    }
    const float li = 1.0f / l_run;
    const float lA = __shfl_sync(0xffffffffu, li, 2 * g);
    const float lB = __shfl_sync(0xffffffffu, li, 2 * g + 16);
#pragma unroll
    for (int t = 0; t < 8; t++) {
        const int dloc = (t >> 1) * 16 + (t & 1) * 8 + 2 * tig;
        const long long col = (long long)n * 64 + dloc;
        const long long offA = (long long)(q0 + w0 + g) * HD + col;
        const long long offB = (long long)(q0 + w0 + g + 8) * HD + col;
        wsplit2(g_ath, g_atl, offA, accO[t][0] * lA, accO[t][1] * lA);
        wsplit2(g_ath, g_atl, offB, accO[t][2] * lB, accO[t][3] * lB);
    }
}

// ---------------- eseg ----------------
__global__ void __launch_bounds__(256) eseg_kernel(
    const float* __restrict__ cb, const float* __restrict__ sb, const float* __restrict__ seg)
{
    int idx = blockIdx.x * 256 + threadIdx.x;
    if (idx >= 2 * NH * QL) return;
    int s = idx / (NH * QL), n = (idx / QL) % NH, qi = idx % QL;
    const bf16* qh = g_qch + (long long)qi * HD + n * DH;
    const bf16* ql = g_qcl + (long long)qi * HD + n * DH;
    const float* cbr = cb + n * DH;
    const float* sbr = sb + n * DH;
    const float* sg = seg + s * (NH * DH) + n * DH;
    float acc = 0.f;
#pragma unroll
    for (int d = 0; d < DH; d++) {
        float q = __bfloat162float(qh[d]) + __bfloat162float(ql[d]) - cbr[d] + sbr[d];
        acc += q * sg[d];
    }
    g_eseg[idx] = acc;
}

// ---------------- residual + LN ----------------
__global__ void __launch_bounds__(256) ln_kernel(
    const float* __restrict__ x, const float* __restrict__ res,
    const float* __restrict__ g, const float* __restrict__ b,
    float* __restrict__ out, bf16* __restrict__ oh, bf16* __restrict__ ol)
{
    const int row = blockIdx.x;
    __shared__ float buf[HD];
    __shared__ float red[8];
    __shared__ float s_mean, s_rstd;
    const int tid = threadIdx.x;
    float lsum = 0.f;
    for (int i = tid; i < HD; i += 256) {
        float v = x[(long long)row * HD + i] + res[(long long)row * HD + i];
        buf[i] = v; lsum += v;
    }
    lsum = warpSum(lsum);
    if ((tid & 31) == 0) red[tid >> 5] = lsum;
    __syncthreads();
    if (tid == 0) {
        float s = 0.f;
#pragma unroll
        for (int i = 0; i < 8; i++) s += red[i];
        s_mean = s * (1.0f / HD);
    }
    __syncthreads();
    const float m = s_mean;
    float lv = 0.f;
    for (int i = tid; i < HD; i += 256) { float d = buf[i] - m; lv += d * d; }
    lv = warpSum(lv);
    __syncthreads();
    if ((tid & 31) == 0) red[tid >> 5] = lv;
    __syncthreads();
    if (tid == 0) {
        float s = 0.f;
#pragma unroll
        for (int i = 0; i < 8; i++) s += red[i];
        s_rstd = rsqrtf(s * (1.0f / HD) + 1e-12f);
    }
    __syncthreads();
    const float rs = s_rstd;
    for (int i = tid; i < HD; i += 256) {
        float o = (buf[i] - m) * rs * g[i] + b[i];
        if (out) out[(long long)row * HD + i] = o;
        if (oh) { bf16 h, l; splitbf(o, h, l); oh[(long long)row * HD + i] = h; ol[(long long)row * HD + i] = l; }
    }
}

// ---------------- launch ----------------
extern "C" void kernel_launch(void* const* d_in, const int* in_sizes, int n_in,
                              void* d_out, int out_size)
{
    const float* cs = (const float*)d_in[0];
    const float* mask = (const float*)d_in[1];
    const float* ctx = (const float*)d_in[2];
    const float* pos = (const float*)d_in[3];
    const float* cb = (const float*)d_in[4];
    const float* pb = (const float*)d_in[5];
    const float* seg = (const float*)d_in[6];
    const unsigned char* segm = (const unsigned char*)d_in[7];
    const float* sbb = (const float*)d_in[8];
    const float* Wq = (const float*)d_in[9];
    const float* Wk = (const float*)d_in[10];
    const float* Wv = (const float*)d_in[11];
    const float* Wr = (const float*)d_in[12];
    const float* Wo = (const float*)d_in[13];
    const float* g1 = (const float*)d_in[14];
    const float* be1 = (const float*)d_in[15];
    const float* W1 = (const float*)d_in[16];
    const float* bf1 = (const float*)d_in[17];
    const float* W2 = (const float*)d_in[18];
    const float* bf2 = (const float*)d_in[19];
    const float* g2 = (const float*)d_in[20];
    const float* be2 = (const float*)d_in[21];
    float* out = (float*)d_out;

#define SYM(T, name, sym) T* name; cudaGetSymbolAddress((void**)&name, sym)
    SYM(float, pv, g_v); SYM(float, pao, g_attnout);
    SYM(float, pfi, g_ffnin); SYM(float, pfo, g_ffnout);
    SYM(bf16, csh, g_csh); SYM(bf16, csl, g_csl);
    SYM(bf16, ctxh, g_ctxh); SYM(bf16, ctxl, g_ctxl);
    SYM(bf16, posh, g_posh); SYM(bf16, posl, g_posl);
    SYM(bf16, qch, g_qch); SYM(bf16, qcl, g_qcl);
    SYM(bf16, qph, g_qph); SYM(bf16, qpl, g_qpl);
    SYM(bf16, kh, g_kh); SYM(bf16, kl, g_kl);
    SYM(bf16, rh, g_rh); SYM(bf16, rl, g_rl);
    SYM(bf16, ath, g_ath); SYM(bf16, atl, g_atl);
    SYM(bf16, fih, g_fih); SYM(bf16, fil, g_fil);
    SYM(bf16, fhh, g_fhh); SYM(bf16, fhl, g_fhl);
    SYM(bf16, wqh, g_wqh); SYM(bf16, wql, g_wql);
    SYM(bf16, wkh, g_wkh); SYM(bf16, wkl, g_wkl);
    SYM(bf16, wvh, g_wvh); SYM(bf16, wvl, g_wvl);
    SYM(bf16, wrh, g_wrh); SYM(bf16, wrl, g_wrl);
    SYM(bf16, woh, g_woh); SYM(bf16, wol, g_wol);
    SYM(bf16, w1h, g_w1h); SYM(bf16, w1l, g_w1l);
    SYM(bf16, w2h, g_w2h); SYM(bf16, w2l, g_w2l);
    SYM(bf16, vth, g_vth); SYM(bf16, vtl, g_vtl);
#undef SYM

    cudaFuncSetAttribute(hmma_gemm_kernel, cudaFuncAttributeMaxDynamicSharedMemorySize, GM_SMEM);
    cudaFuncSetAttribute(score_hmma_kernel, cudaFuncAttributeMaxDynamicSharedMemorySize, S_SMEM);
    cudaFuncSetAttribute(pv_fused_kernel, cudaFuncAttributeMaxDynamicSharedMemorySize, PV_SMEM);

    dim3 blk(256);
    split4_kernel<<<(QL * HD / 4) / 256, blk>>>(cs, csh, csl, QL * HD / 4);
    split4_kernel<<<(CL * HD / 4) / 256, blk>>>(ctx, ctxh, ctxl, CL * HD / 4);
    split4_kernel<<<(RL * HD / 4) / 256, blk>>>(pos, posh, posl, RL * HD / 4);
    convT_kernel<<<dim3(HD / 32, HD / 32), blk>>>(Wq, wqh, wql, HD, HD);
    convT_kernel<<<dim3(HD / 32, HD / 32), blk>>>(Wk, wkh, wkl, HD, HD);
    convT_kernel<<<dim3(HD / 32, HD / 32), blk>>>(Wv, wvh, wvl, HD, HD);
    convT_kernel<<<dim3(HD / 32, HD / 32), blk>>>(Wr, wrh, wrl, HD, HD);
    conv_kernel<<<(HD * HD) / 256, blk>>>(Wo, woh, wol, HD * HD);
    convT_kernel<<<dim3(FF / 32, HD / 32), blk>>>(W1, w1h, w1l, HD, FF);
    convT_kernel<<<dim3(HD / 32, FF / 32), blk>>>(W2, w2h, w2l, FF, HD);

    // projections
    hmma_gemm_kernel<<<dim3(HD / 128, QL / 128), blk, GM_SMEM>>>(
        csh, csl, wqh, wql, nullptr, nullptr, qch, qcl, cb, qph, qpl, pb, HD, HD, HD, HD, 0);
    hmma_gemm_kernel<<<dim3(HD / 128, CL / 128), blk, GM_SMEM>>>(
        ctxh, ctxl, wkh, wkl, nullptr, nullptr, kh, kl, nullptr, nullptr, nullptr, nullptr, HD, HD, HD, HD, 0);
    hmma_gemm_kernel<<<dim3(HD / 128, CL / 128), blk, GM_SMEM>>>(
        ctxh, ctxl, wvh, wvl, pv, nullptr, nullptr, nullptr, nullptr, nullptr, nullptr, nullptr, HD, HD, HD, HD, 0);
    hmma_gemm_kernel<<<dim3(HD / 128, RL / 128), blk, GM_SMEM>>>(
        posh, posl, wrh, wrl, nullptr, nullptr, rh, rl, nullptr, nullptr, nullptr, nullptr, HD, HD, HD, HD, 0);

    convT_kernel<<<dim3(HD / 32, CL / 32), blk>>>(pv, vth, vtl, CL, HD);
    eseg_kernel<<<(2 * NH * QL) / 256, blk>>>(cb, sbb, seg);

    score_hmma_kernel<<<dim3(CL / 128, QL / 128, NH), blk, S_SMEM>>>(mask, segm);

    // fused online softmax + probs@V
    pv_fused_kernel<<<dim3(QL / 128, NH), blk, PV_SMEM>>>();

    // attn_out = attn @ Wo^T
    hmma_gemm_kernel<<<dim3(HD / 128, QL / 128), blk, GM_SMEM>>>(
        ath, atl, woh, wol, pao, nullptr, nullptr, nullptr, nullptr, nullptr, nullptr, nullptr, HD, HD, HD, HD, 0);

    ln_kernel<<<QL, blk>>>(pao, cs, g1, be1, pfi, fih, fil);

    hmma_gemm_kernel<<<dim3(FF / 128, QL / 128), blk, GM_SMEM>>>(
        fih, fil, w1h, w1l, nullptr, nullptr, fhh, fhl, bf1, nullptr, nullptr, nullptr, HD, HD, HD, FF, 1);
    hmma_gemm_kernel<<<dim3(HD / 128, QL / 128), blk, GM_SMEM>>>(
        fhh, fhl, w2h, w2l, pfo, bf2, nullptr, nullptr, nullptr, nullptr, nullptr, nullptr, FF, FF, FF, HD, 0);

    ln_kernel<<<QL, blk>>>(pfo, pfi, g2, be2, out, nullptr, nullptr);
}

// round 7
// speedup vs baseline: 1.0392x; 1.0392x over previous
#include <cuda_runtime.h>
#include <cuda_bf16.h>
#include <math.h>
#include <stdint.h>

#define QL 2048
#define CL 2048
#define HD 1024
#define NH 16
#define DH 64
#define FF 4096
#define RL 4096
typedef __nv_bfloat16 bf16;
typedef __nv_bfloat162 bf162;

// ---------------- scratch ----------------
__device__ float g_v[CL * HD];
__device__ float g_scores[(size_t)NH * QL * CL];
__device__ float g_eseg[2 * NH * QL];
__device__ float g_attnout[QL * HD];
__device__ float g_ffnin[QL * HD];
__device__ float g_ffnout[QL * HD];
__device__ bf16 g_csh[QL * HD], g_csl[QL * HD];
__device__ bf16 g_ctxh[CL * HD], g_ctxl[CL * HD];
__device__ bf16 g_posh[RL * HD], g_posl[RL * HD];
__device__ bf16 g_qch[QL * HD], g_qcl[QL * HD];
__device__ bf16 g_qph[QL * HD], g_qpl[QL * HD];
__device__ bf16 g_kh[CL * HD], g_kl[CL * HD];
__device__ bf16 g_rh[RL * HD], g_rl[RL * HD];
__device__ bf16 g_ath[QL * HD], g_atl[QL * HD];
__device__ bf16 g_fih[QL * HD], g_fil[QL * HD];
__device__ bf16 g_fhh[(size_t)QL * FF], g_fhl[(size_t)QL * FF];
__device__ bf16 g_wqh[HD * HD], g_wql[HD * HD];
__device__ bf16 g_wkh[HD * HD], g_wkl[HD * HD];
__device__ bf16 g_wvh[HD * HD], g_wvl[HD * HD];
__device__ bf16 g_wrh[HD * HD], g_wrl[HD * HD];
__device__ bf16 g_woh[HD * HD], g_wol[HD * HD];
__device__ bf16 g_w1h[(size_t)FF * HD], g_w1l[(size_t)FF * HD];
__device__ bf16 g_w2h[(size_t)FF * HD], g_w2l[(size_t)FF * HD];
__device__ bf16 g_vth[HD * CL], g_vtl[HD * CL];

#define SWZ(o) ((o) ^ (((o) >> 3) & 0x70))

__device__ __forceinline__ uint32_t smem_u32(const void* p) {
    uint32_t a;
    asm("{ .reg .u64 t; cvta.to.shared.u64 t, %1; cvt.u32.u64 %0, t; }" : "=r"(a) : "l"(p));
    return a;
}
__device__ __forceinline__ void cpasync16(uint32_t s, const void* g) {
    asm volatile("cp.async.cg.shared.global [%0], [%1], 16;" :: "r"(s), "l"(g));
}
#define CP_COMMIT() asm volatile("cp.async.commit_group;")
#define CP_WAIT(n) asm volatile("cp.async.wait_group %0;" :: "n"(n))

__device__ __forceinline__ void splitbf(float x, bf16& h, bf16& l) {
    h = __float2bfloat16(x);
    l = __float2bfloat16(x - __bfloat162float(h));
}
__device__ __forceinline__ void wsplit2(bf16* oh, bf16* ol, long long off, float x, float y) {
    bf16 h0, l0, h1, l1;
    splitbf(x, h0, l0); splitbf(y, h1, l1);
    *(bf162*)(oh + off) = __halves2bfloat162(h0, h1);
    *(bf162*)(ol + off) = __halves2bfloat162(l0, l1);
}
__device__ __forceinline__ float warpSum(float v) {
#pragma unroll
    for (int o = 16; o; o >>= 1) v += __shfl_xor_sync(0xffffffffu, v, o);
    return v;
}
__device__ __forceinline__ float warpMax(float v) {
#pragma unroll
    for (int o = 16; o; o >>= 1) v = fmaxf(v, __shfl_xor_sync(0xffffffffu, v, o));
    return v;
}
__device__ __forceinline__ void mma_bf16(float* d, const uint32_t* a, const uint32_t* b) {
    asm volatile(
        "mma.sync.aligned.m16n8k16.row.col.f32.bf16.bf16.f32 "
        "{%0,%1,%2,%3}, {%4,%5,%6,%7}, {%8,%9}, {%0,%1,%2,%3};"
        : "+f"(d[0]), "+f"(d[1]), "+f"(d[2]), "+f"(d[3])
        : "r"(a[0]), "r"(a[1]), "r"(a[2]), "r"(a[3]), "r"(b[0]), "r"(b[1]));
}
__device__ __forceinline__ void ldm4(uint32_t* r, uint32_t base, int row0, int k0, int lane) {
    int row = row0 + (lane & 15);
    int kc = k0 + ((lane >> 4) << 3);
    uint32_t addr = base + SWZ((uint32_t)row * 128 + (uint32_t)kc * 2);
    asm volatile("ldmatrix.sync.aligned.m8n8.x4.shared.b16 {%0,%1,%2,%3}, [%4];"
                 : "=r"(r[0]), "=r"(r[1]), "=r"(r[2]), "=r"(r[3]) : "r"(addr));
}

// ---------------- converters ----------------
__global__ void __launch_bounds__(256) convT_kernel(
    const float* __restrict__ in, bf16* __restrict__ oh, bf16* __restrict__ ol, int R, int Cc)
{
    __shared__ float t[32][33];
    const int tx = threadIdx.x & 31, ty8 = threadIdx.x >> 5;
    const int r0 = blockIdx.y * 32, c0 = blockIdx.x * 32;
    for (int j = ty8; j < 32; j += 8) t[j][tx] = in[(long long)(r0 + j) * Cc + c0 + tx];
    __syncthreads();
    for (int j = ty8; j < 32; j += 8) {
        bf16 h, l; splitbf(t[tx][j], h, l);
        long long o = (long long)(c0 + j) * R + r0 + tx;
        oh[o] = h; ol[o] = l;
    }
}
__global__ void __launch_bounds__(256) conv_kernel(
    const float* __restrict__ in, bf16* __restrict__ oh, bf16* __restrict__ ol, int n)
{
    int i = blockIdx.x * 256 + threadIdx.x;
    if (i < n) { bf16 h, l; splitbf(in[i], h, l); oh[i] = h; ol[i] = l; }
}
__global__ void __launch_bounds__(256) split4_kernel(
    const float* __restrict__ in, bf16* __restrict__ oh, bf16* __restrict__ ol, int n4)
{
    int i = blockIdx.x * 256 + threadIdx.x;
    if (i >= n4) return;
    float4 v = *(const float4*)(in + i * 4);
    wsplit2(oh, ol, (long long)i * 4, v.x, v.y);
    wsplit2(oh, ol, (long long)i * 4 + 2, v.z, v.w);
}

// ---------------- HMMA GEMM (R5 shape): BM=128, BN=64, BK=64, 256 thr -------
#define ST_AH 0
#define ST_AL 16384
#define ST_BH 32768
#define ST_BL 40960
#define ST_SZ 49152
#define GM_SMEM (2 * ST_SZ)

__global__ void __launch_bounds__(256) hmma_gemm_kernel(
    const bf16* __restrict__ Ah, const bf16* __restrict__ Al,
    const bf16* __restrict__ Bh, const bf16* __restrict__ Bl,
    float* __restrict__ C, const float* __restrict__ biasC,
    bf16* __restrict__ O1h, bf16* __restrict__ O1l, const float* __restrict__ bias1,
    bf16* __restrict__ O2h, bf16* __restrict__ O2l, const float* __restrict__ bias2,
    int K, int lda, int ldb, int ldc, int relu)
{
    extern __shared__ char smem[];
    const uint32_t sbase = smem_u32(smem);
    const int tid = threadIdx.x, lane = tid & 31, w = tid >> 5;
    const int g = lane >> 2, tig = lane & 3;
    const int m0 = blockIdx.y * 128, n0 = blockIdx.x * 64;
    const int wm = (w >> 1) * 32, wn = (w & 1) * 32;

    auto load_stage = [&](int s, int k0) {
        uint32_t sb = sbase + s * ST_SZ;
#pragma unroll
        for (int i = 0; i < 4; i++) {
            int u = tid + (i << 8);
            int row = u >> 3, c16 = u & 7;
            uint32_t sw = SWZ((uint32_t)row * 128 + (uint32_t)(c16 << 4));
            const long long ga = (long long)(m0 + row) * lda + k0 + (c16 << 3);
            cpasync16(sb + ST_AH + sw, Ah + ga);
            cpasync16(sb + ST_AL + sw, Al + ga);
        }
#pragma unroll
        for (int i = 0; i < 2; i++) {
            int u = tid + (i << 8);
            int row = u >> 3, c16 = u & 7;
            uint32_t sw = SWZ((uint32_t)row * 128 + (uint32_t)(c16 << 4));
            const long long gb = (long long)(n0 + row) * ldb + k0 + (c16 << 3);
            cpasync16(sb + ST_BH + sw, Bh + gb);
            cpasync16(sb + ST_BL + sw, Bl + gb);
        }
    };

    float acc[2][4][4] = {};
    const int NC = K >> 6;
    load_stage(0, 0);
    CP_COMMIT();
    for (int c = 0; c < NC; c++) {
        if (c + 1 < NC) { load_stage((c + 1) & 1, (c + 1) << 6); CP_COMMIT(); CP_WAIT(1); }
        else CP_WAIT(0);
        __syncthreads();
        const uint32_t sb = sbase + (c & 1) * ST_SZ;
#pragma unroll
        for (int ks = 0; ks < 4; ks++) {
            uint32_t ah[2][4], al[2][4], bh[2][4], bl[2][4];
            ldm4(ah[0], sb + ST_AH, wm, ks * 16, lane);
            ldm4(ah[1], sb + ST_AH, wm + 16, ks * 16, lane);
            ldm4(al[0], sb + ST_AL, wm, ks * 16, lane);
            ldm4(al[1], sb + ST_AL, wm + 16, ks * 16, lane);
            ldm4(bh[0], sb + ST_BH, wn, ks * 16, lane);
            ldm4(bh[1], sb + ST_BH, wn + 16, ks * 16, lane);
            ldm4(bl[0], sb + ST_BL, wn, ks * 16, lane);
            ldm4(bl[1], sb + ST_BL, wn + 16, ks * 16, lane);
#pragma unroll
            for (int mt = 0; mt < 2; mt++)
#pragma unroll
                for (int nt = 0; nt < 4; nt++) {
                    const int p = nt >> 1, o = nt & 1;
                    uint32_t fbh[2] = { bh[p][o], bh[p][2 + o] };
                    uint32_t fbl[2] = { bl[p][o], bl[p][2 + o] };
                    mma_bf16(acc[mt][nt], ah[mt], fbh);
                    mma_bf16(acc[mt][nt], ah[mt], fbl);
                    mma_bf16(acc[mt][nt], al[mt], fbh);
                }
        }
        __syncthreads();
    }

#pragma unroll
    for (int mt = 0; mt < 2; mt++)
#pragma unroll
        for (int nt = 0; nt < 4; nt++) {
#pragma unroll
            for (int h = 0; h < 2; h++) {
                const int row = m0 + wm + mt * 16 + g + h * 8;
                const int col = n0 + wn + nt * 8 + 2 * tig;
                float x = acc[mt][nt][h * 2], y = acc[mt][nt][h * 2 + 1];
                const long long off = (long long)row * ldc + col;
                if (C) {
                    float b0 = biasC ? biasC[col] : 0.f, b1 = biasC ? biasC[col + 1] : 0.f;
                    float2 o = { x + b0, y + b1 };
                    *(float2*)(C + off) = o;
                }
                if (O1h) {
                    float b0 = bias1 ? bias1[col] : 0.f, b1 = bias1 ? bias1[col + 1] : 0.f;
                    float vx = x + b0, vy = y + b1;
                    if (relu) { vx = fmaxf(vx, 0.f); vy = fmaxf(vy, 0.f); }
                    wsplit2(O1h, O1l, off, vx, vy);
                }
                if (O2h) {
                    float b0 = bias2 ? bias2[col] : 0.f, b1 = bias2 ? bias2[col + 1] : 0.f;
                    wsplit2(O2h, O2l, off, x + b0, y + b1);
                }
            }
        }
}

// ---------------- HMMA score kernel (unchanged) ----------------
#define S_QCH 0
#define S_QCL 16384
#define S_QPH 32768
#define S_QPL 49152
#define S_KH  65536
#define S_KL  81920
#define S_RH  98304
#define S_RL  131072
#define S_ST  163840
#define S_SMEM (163840 + 8 * 3200)

__global__ void __launch_bounds__(256) score_hmma_kernel(
    const float* __restrict__ mask, const unsigned char* __restrict__ segmat)
{
    extern __shared__ char smem[];
    const uint32_t sbase = smem_u32(smem);
    const int tid = threadIdx.x, lane = tid & 31, w = tid >> 5;
    const int g = lane >> 2, tig = lane & 3;
    const int n = blockIdx.z, q0 = blockIdx.y * 128, c0 = blockIdx.x * 128;
    const int nDH = n * DH;

    auto ldtile = [&](int dsth, int dstl, const bf16* srch, const bf16* srcl, long long rbase, int ldg) {
#pragma unroll
        for (int i = 0; i < 4; i++) {
            int u = tid + (i << 8);
            int row = u >> 3, c16 = u & 7;
            uint32_t sw = SWZ((uint32_t)row * 128 + (uint32_t)(c16 << 4));
            long long gofs = (rbase + row) * ldg + nDH + (c16 << 3);
            *(uint4*)(smem + dsth + sw) = *(const uint4*)(srch + gofs);
            *(uint4*)(smem + dstl + sw) = *(const uint4*)(srcl + gofs);
        }
    };
    ldtile(S_QCH, S_QCL, g_qch, g_qcl, q0, HD);
    ldtile(S_QPH, S_QPL, g_qph, g_qpl, q0, HD);
    ldtile(S_KH, S_KL, g_kh, g_kl, c0, HD);
    const int rstart = QL + c0 - q0 - 127;
#pragma unroll
    for (int i = 0; i < 8; i++) {
        int u = tid + (i << 8);
        int row = u >> 3, c16 = u & 7;
        int rg = rstart + row; if (rg > RL - 1) rg = RL - 1;
        uint32_t sw = SWZ((uint32_t)row * 128 + (uint32_t)(c16 << 4));
        long long gofs = (long long)rg * HD + nDH + (c16 << 3);
        *(uint4*)(smem + S_RH + sw) = *(const uint4*)(g_rh + gofs);
        *(uint4*)(smem + S_RL + sw) = *(const uint4*)(g_rl + gofs);
    }
    __syncthreads();

    const int w0 = w * 16;
    const float e0a = g_eseg[(0 * NH + n) * QL + q0 + w0 + g];
    const float e1a = g_eseg[(1 * NH + n) * QL + q0 + w0 + g];
    const float e0b = g_eseg[(0 * NH + n) * QL + q0 + w0 + g + 8];
    const float e1b = g_eseg[(1 * NH + n) * QL + q0 + w0 + g + 8];
    float* stg = (float*)(smem + S_ST + w * 3200);

    for (int ch = 0; ch < 4; ch++) {
        float accA[4][4] = {};
        float accB[6][4] = {};
        const int s0 = ch * 32 - w0 + 112;
#pragma unroll
        for (int ks = 0; ks < 4; ks++) {
            uint32_t ach[4], acl[4], aph[4], apl[4];
            ldm4(ach, sbase + S_QCH, w0, ks * 16, lane);
            ldm4(acl, sbase + S_QCL, w0, ks * 16, lane);
            ldm4(aph, sbase + S_QPH, w0, ks * 16, lane);
            ldm4(apl, sbase + S_QPL, w0, ks * 16, lane);
            uint32_t kh[2][4], kl[2][4];
            ldm4(kh[0], sbase + S_KH, ch * 32, ks * 16, lane);
            ldm4(kh[1], sbase + S_KH, ch * 32 + 16, ks * 16, lane);
            ldm4(kl[0], sbase + S_KL, ch * 32, ks * 16, lane);
            ldm4(kl[1], sbase + S_KL, ch * 32 + 16, ks * 16, lane);
#pragma unroll
            for (int nt = 0; nt < 4; nt++) {
                const int p = nt >> 1, o = nt & 1;
                uint32_t fbh[2] = { kh[p][o], kh[p][2 + o] };
                uint32_t fbl[2] = { kl[p][o], kl[p][2 + o] };
                mma_bf16(accA[nt], ach, fbh);
                mma_bf16(accA[nt], ach, fbl);
                mma_bf16(accA[nt], acl, fbh);
            }
            uint32_t rh[3][4], rl[3][4];
#pragma unroll
            for (int p = 0; p < 3; p++) {
                ldm4(rh[p], sbase + S_RH, s0 + p * 16, ks * 16, lane);
                ldm4(rl[p], sbase + S_RL, s0 + p * 16, ks * 16, lane);
            }
#pragma unroll
            for (int nt = 0; nt < 6; nt++) {
                const int p = nt >> 1, o = nt & 1;
                uint32_t fbh[2] = { rh[p][o], rh[p][2 + o] };
                uint32_t fbl[2] = { rl[p][o], rl[p][2 + o] };
                mma_bf16(accB[nt], aph, fbh);
                mma_bf16(accB[nt], aph, fbl);
                mma_bf16(accB[nt], apl, fbh);
            }
        }
#pragma unroll
        for (int nt = 0; nt < 6; nt++) {
            int cc = nt * 8 + 2 * tig;
            stg[g * 50 + cc] = accB[nt][0];
            stg[g * 50 + cc + 1] = accB[nt][1];
            stg[(g + 8) * 50 + cc] = accB[nt][2];
            stg[(g + 8) * 50 + cc + 1] = accB[nt][3];
        }
        __syncwarp();
#pragma unroll
        for (int nt = 0; nt < 4; nt++) {
            const int jl = nt * 8 + 2 * tig;
            const float bd0 = stg[g * 50 + jl - g + 15], bd1 = stg[g * 50 + jl - g + 16];
            const float bd2 = stg[(g + 8) * 50 + jl - g + 7], bd3 = stg[(g + 8) * 50 + jl - g + 8];
            const int qa = q0 + w0 + g, cc = c0 + ch * 32 + jl;
            const size_t ma = (size_t)qa * CL + cc;
            const size_t mb = (size_t)(qa + 8) * CL + cc;
            float2 mka = *(const float2*)(mask + ma);
            float2 mkb = *(const float2*)(mask + mb);
            uchar2 sga = *(const uchar2*)(segmat + ma);
            uchar2 sgb = *(const uchar2*)(segmat + mb);
            float2 oa, ob;
            oa.x = (accA[nt][0] + bd0 + (sga.x ? e1a : e0a)) * 0.125f - 1e30f * mka.x;
            oa.y = (accA[nt][1] + bd1 + (sga.y ? e1a : e0a)) * 0.125f - 1e30f * mka.y;
            ob.x = (accA[nt][2] + bd2 + (sgb.x ? e1b : e0b)) * 0.125f - 1e30f * mkb.x;
            ob.y = (accA[nt][3] + bd3 + (sgb.y ? e1b : e0b)) * 0.125f - 1e30f * mkb.y;
            *(float2*)(g_scores + ((size_t)n * QL + qa) * CL + cc) = oa;
            *(float2*)(g_scores + ((size_t)n * QL + qa + 8) * CL + cc) = ob;
        }
        __syncwarp();
    }
}

// ---------------- fused online-softmax + probs@V (coalesced scores) ---------
#define PV_V0 0
#define PV_V1 16384
#define PV_PH 32768
#define PV_PL 49152
#define PV_SC 65536
#define PV_SCW 68            /* padded row stride in floats */
#define PV_SMEM (65536 + 128 * PV_SCW * 4)

__global__ void __launch_bounds__(256) pv_fused_kernel()
{
    extern __shared__ char smem[];
    const uint32_t sbase = smem_u32(smem);
    const int tid = threadIdx.x, lane = tid & 31, w = tid >> 5;
    const int g = lane >> 2, tig = lane & 3;
    const int n = blockIdx.y, q0 = blockIdx.x * 128;
    const int w0 = w * 16;
    const int ri = lane >> 1, half = lane & 1;

    const bf16* vt_h = g_vth + (long long)(n * 64) * CL;
    const bf16* vt_l = g_vtl + (long long)(n * 64) * CL;
    float* sc = (float*)(smem + PV_SC);

    auto loadV = [&](int s, int c0) {
        uint32_t sb = sbase + (s ? PV_V1 : PV_V0);
#pragma unroll
        for (int i = 0; i < 2; i++) {
            int u = tid + (i << 8);
            int row = u >> 3, c16 = u & 7;
            uint32_t sw = SWZ((uint32_t)row * 128 + (uint32_t)(c16 << 4));
            long long gofs = (long long)row * CL + c0 + (c16 << 3);
            cpasync16(sb + sw, vt_h + gofs);
            cpasync16(sb + 8192 + sw, vt_l + gofs);
        }
    };

    float m_run = -3.0e38f, l_run = 0.f;
    float accO[8][4] = {};
    const float* sgbase = g_scores + ((size_t)n * QL + q0) * CL;

    loadV(0, 0); CP_COMMIT();
    for (int cb = 0; cb < CL / 64; cb++) {
        // coalesced block-wide stage of the 128x64 score tile
#pragma unroll
        for (int i = 0; i < 8; i++) {
            int u = tid + (i << 8);         // 2048 uint4
            int row = u >> 4, c16 = u & 15;
            uint4 v = *(const uint4*)(sgbase + (size_t)row * CL + cb * 64 + c16 * 4);
            *(uint4*)(sc + row * PV_SCW + c16 * 4) = v;
        }
        if (cb + 1 < CL / 64) { loadV((cb + 1) & 1, (cb + 1) * 64); CP_COMMIT(); CP_WAIT(1); }
        else CP_WAIT(0);
        __syncthreads();
        const uint32_t vb = sbase + ((cb & 1) ? PV_V1 : PV_V0);

        const float* srow = sc + (w0 + ri) * PV_SCW + half * 32;
        float4 sv[8];
#pragma unroll
        for (int j = 0; j < 8; j++) sv[j] = *(const float4*)(srow + j * 4);
        float cmax = -3.0e38f;
#pragma unroll
        for (int j = 0; j < 8; j++)
            cmax = fmaxf(cmax, fmaxf(fmaxf(sv[j].x, sv[j].y), fmaxf(sv[j].z, sv[j].w)));
        cmax = fmaxf(cmax, __shfl_xor_sync(0xffffffffu, cmax, 1));
        const float m_new = fmaxf(m_run, cmax);
        const float scale = __expf(m_run - m_new);
        m_run = m_new;
        float csum = 0.f;
#pragma unroll
        for (int j = 0; j < 8; j++) {
            float p0 = __expf(sv[j].x - m_new), p1 = __expf(sv[j].y - m_new);
            float p2 = __expf(sv[j].z - m_new), p3 = __expf(sv[j].w - m_new);
            csum += (p0 + p1) + (p2 + p3);
            const int c = half * 32 + j * 4;
            const uint32_t sw = SWZ((uint32_t)(w0 + ri) * 128 + (uint32_t)c * 2);
            bf16 h0, l0, h1, l1, h2, l2, h3, l3;
            splitbf(p0, h0, l0); splitbf(p1, h1, l1); splitbf(p2, h2, l2); splitbf(p3, h3, l3);
            *(bf162*)(smem + PV_PH + sw) = __halves2bfloat162(h0, h1);
            *(bf162*)(smem + PV_PH + sw + 4) = __halves2bfloat162(h2, h3);
            *(bf162*)(smem + PV_PL + sw) = __halves2bfloat162(l0, l1);
            *(bf162*)(smem + PV_PL + sw + 4) = __halves2bfloat162(l2, l3);
        }
        csum += __shfl_xor_sync(0xffffffffu, csum, 1);
        l_run = l_run * scale + csum;
        const float sA = __shfl_sync(0xffffffffu, scale, 2 * g);
        const float sB = __shfl_sync(0xffffffffu, scale, 2 * g + 16);
#pragma unroll
        for (int t = 0; t < 8; t++) {
            accO[t][0] *= sA; accO[t][1] *= sA;
            accO[t][2] *= sB; accO[t][3] *= sB;
        }
        __syncwarp();
#pragma unroll
        for (int ks = 0; ks < 4; ks++) {
            uint32_t aH[4], aL[4];
            ldm4(aH, sbase + PV_PH, w0, ks * 16, lane);
            ldm4(aL, sbase + PV_PL, w0, ks * 16, lane);
            uint32_t bH[4][4], bL[4][4];
#pragma unroll
            for (int p = 0; p < 4; p++) {
                ldm4(bH[p], vb, p * 16, ks * 16, lane);
                ldm4(bL[p], vb + 8192, p * 16, ks * 16, lane);
            }
#pragma unroll
            for (int t = 0; t < 8; t++) {
                const int p = t >> 1, o = t & 1;
                uint32_t fbh[2] = { bH[p][o], bH[p][2 + o] };
                uint32_t fbl[2] = { bL[p][o], bL[p][2 + o] };
                mma_bf16(accO[t], aH, fbh);
                mma_bf16(accO[t], aH, fbl);
                mma_bf16(accO[t], aL, fbh);
            }
        }
        __syncthreads();
    }
    const float li = 1.0f / l_run;
    const float lA = __shfl_sync(0xffffffffu, li, 2 * g);
    const float lB = __shfl_sync(0xffffffffu, li, 2 * g + 16);
#pragma unroll
    for (int t = 0; t < 8; t++) {
        const int dloc = (t >> 1) * 16 + (t & 1) * 8 + 2 * tig;
        const long long col = (long long)n * 64 + dloc;
        const long long offA = (long long)(q0 + w0 + g) * HD + col;
        const long long offB = (long long)(q0 + w0 + g + 8) * HD + col;
        wsplit2(g_ath, g_atl, offA, accO[t][0] * lA, accO[t][1] * lA);
        wsplit2(g_ath, g_atl, offB, accO[t][2] * lB, accO[t][3] * lB);
    }
}

// ---------------- eseg ----------------
__global__ void __launch_bounds__(256) eseg_kernel(
    const float* __restrict__ cb, const float* __restrict__ sb, const float* __restrict__ seg)
{
    int idx = blockIdx.x * 256 + threadIdx.x;
    if (idx >= 2 * NH * QL) return;
    int s = idx / (NH * QL), n = (idx / QL) % NH, qi = idx % QL;
    const bf16* qh = g_qch + (long long)qi * HD + n * DH;
    const bf16* ql = g_qcl + (long long)qi * HD + n * DH;
    const float* cbr = cb + n * DH;
    const float* sbr = sb + n * DH;
    const float* sg = seg + s * (NH * DH) + n * DH;
    float acc = 0.f;
#pragma unroll
    for (int d = 0; d < DH; d++) {
        float q = __bfloat162float(qh[d]) + __bfloat162float(ql[d]) - cbr[d] + sbr[d];
        acc += q * sg[d];
    }
    g_eseg[idx] = acc;
}

// ---------------- residual + LN ----------------
__global__ void __launch_bounds__(256) ln_kernel(
    const float* __restrict__ x, const float* __restrict__ res,
    const float* __restrict__ g, const float* __restrict__ b,
    float* __restrict__ out, bf16* __restrict__ oh, bf16* __restrict__ ol)
{
    const int row = blockIdx.x;
    __shared__ float buf[HD];
    __shared__ float red[8];
    __shared__ float s_mean, s_rstd;
    const int tid = threadIdx.x;
    float lsum = 0.f;
    for (int i = tid; i < HD; i += 256) {
        float v = x[(long long)row * HD + i] + res[(long long)row * HD + i];
        buf[i] = v; lsum += v;
    }
    lsum = warpSum(lsum);
    if ((tid & 31) == 0) red[tid >> 5] = lsum;
    __syncthreads();
    if (tid == 0) {
        float s = 0.f;
#pragma unroll
        for (int i = 0; i < 8; i++) s += red[i];
        s_mean = s * (1.0f / HD);
    }
    __syncthreads();
    const float m = s_mean;
    float lv = 0.f;
    for (int i = tid; i < HD; i += 256) { float d = buf[i] - m; lv += d * d; }
    lv = warpSum(lv);
    __syncthreads();
    if ((tid & 31) == 0) red[tid >> 5] = lv;
    __syncthreads();
    if (tid == 0) {
        float s = 0.f;
#pragma unroll
        for (int i = 0; i < 8; i++) s += red[i];
        s_rstd = rsqrtf(s * (1.0f / HD) + 1e-12f);
    }
    __syncthreads();
    const float rs = s_rstd;
    for (int i = tid; i < HD; i += 256) {
        float o = (buf[i] - m) * rs * g[i] + b[i];
        if (out) out[(long long)row * HD + i] = o;
        if (oh) { bf16 h, l; splitbf(o, h, l); oh[(long long)row * HD + i] = h; ol[(long long)row * HD + i] = l; }
    }
}

// ---------------- launch ----------------
extern "C" void kernel_launch(void* const* d_in, const int* in_sizes, int n_in,
                              void* d_out, int out_size)
{
    const float* cs = (const float*)d_in[0];
    const float* mask = (const float*)d_in[1];
    const float* ctx = (const float*)d_in[2];
    const float* pos = (const float*)d_in[3];
    const float* cb = (const float*)d_in[4];
    const float* pb = (const float*)d_in[5];
    const float* seg = (const float*)d_in[6];
    const unsigned char* segm = (const unsigned char*)d_in[7];
    const float* sbb = (const float*)d_in[8];
    const float* Wq = (const float*)d_in[9];
    const float* Wk = (const float*)d_in[10];
    const float* Wv = (const float*)d_in[11];
    const float* Wr = (const float*)d_in[12];
    const float* Wo = (const float*)d_in[13];
    const float* g1 = (const float*)d_in[14];
    const float* be1 = (const float*)d_in[15];
    const float* W1 = (const float*)d_in[16];
    const float* bf1 = (const float*)d_in[17];
    const float* W2 = (const float*)d_in[18];
    const float* bf2 = (const float*)d_in[19];
    const float* g2 = (const float*)d_in[20];
    const float* be2 = (const float*)d_in[21];
    float* out = (float*)d_out;

#define SYM(T, name, sym) T* name; cudaGetSymbolAddress((void**)&name, sym)
    SYM(float, pv, g_v); SYM(float, pao, g_attnout);
    SYM(float, pfi, g_ffnin); SYM(float, pfo, g_ffnout);
    SYM(bf16, csh, g_csh); SYM(bf16, csl, g_csl);
    SYM(bf16, ctxh, g_ctxh); SYM(bf16, ctxl, g_ctxl);
    SYM(bf16, posh, g_posh); SYM(bf16, posl, g_posl);
    SYM(bf16, qch, g_qch); SYM(bf16, qcl, g_qcl);
    SYM(bf16, qph, g_qph); SYM(bf16, qpl, g_qpl);
    SYM(bf16, kh, g_kh); SYM(bf16, kl, g_kl);
    SYM(bf16, rh, g_rh); SYM(bf16, rl, g_rl);
    SYM(bf16, ath, g_ath); SYM(bf16, atl, g_atl);
    SYM(bf16, fih, g_fih); SYM(bf16, fil, g_fil);
    SYM(bf16, fhh, g_fhh); SYM(bf16, fhl, g_fhl);
    SYM(bf16, wqh, g_wqh); SYM(bf16, wql, g_wql);
    SYM(bf16, wkh, g_wkh); SYM(bf16, wkl, g_wkl);
    SYM(bf16, wvh, g_wvh); SYM(bf16, wvl, g_wvl);
    SYM(bf16, wrh, g_wrh); SYM(bf16, wrl, g_wrl);
    SYM(bf16, woh, g_woh); SYM(bf16, wol, g_wol);
    SYM(bf16, w1h, g_w1h); SYM(bf16, w1l, g_w1l);
    SYM(bf16, w2h, g_w2h); SYM(bf16, w2l, g_w2l);
    SYM(bf16, vth, g_vth); SYM(bf16, vtl, g_vtl);
#undef SYM

    cudaFuncSetAttribute(hmma_gemm_kernel, cudaFuncAttributeMaxDynamicSharedMemorySize, GM_SMEM);
    cudaFuncSetAttribute(score_hmma_kernel, cudaFuncAttributeMaxDynamicSharedMemorySize, S_SMEM);
    cudaFuncSetAttribute(pv_fused_kernel, cudaFuncAttributeMaxDynamicSharedMemorySize, PV_SMEM);

    dim3 blk(256);
    split4_kernel<<<(QL * HD / 4) / 256, blk>>>(cs, csh, csl, QL * HD / 4);
    split4_kernel<<<(CL * HD / 4) / 256, blk>>>(ctx, ctxh, ctxl, CL * HD / 4);
    split4_kernel<<<(RL * HD / 4) / 256, blk>>>(pos, posh, posl, RL * HD / 4);
    convT_kernel<<<dim3(HD / 32, HD / 32), blk>>>(Wq, wqh, wql, HD, HD);
    convT_kernel<<<dim3(HD / 32, HD / 32), blk>>>(Wk, wkh, wkl, HD, HD);
    convT_kernel<<<dim3(HD / 32, HD / 32), blk>>>(Wv, wvh, wvl, HD, HD);
    convT_kernel<<<dim3(HD / 32, HD / 32), blk>>>(Wr, wrh, wrl, HD, HD);
    conv_kernel<<<(HD * HD) / 256, blk>>>(Wo, woh, wol, HD * HD);
    convT_kernel<<<dim3(FF / 32, HD / 32), blk>>>(W1, w1h, w1l, HD, FF);
    convT_kernel<<<dim3(HD / 32, FF / 32), blk>>>(W2, w2h, w2l, FF, HD);

    // projections
    hmma_gemm_kernel<<<dim3(HD / 64, QL / 128), blk, GM_SMEM>>>(
        csh, csl, wqh, wql, nullptr, nullptr, qch, qcl, cb, qph, qpl, pb, HD, HD, HD, HD, 0);
    hmma_gemm_kernel<<<dim3(HD / 64, CL / 128), blk, GM_SMEM>>>(
        ctxh, ctxl, wkh, wkl, nullptr, nullptr, kh, kl, nullptr, nullptr, nullptr, nullptr, HD, HD, HD, HD, 0);
    hmma_gemm_kernel<<<dim3(HD / 64, CL / 128), blk, GM_SMEM>>>(
        ctxh, ctxl, wvh, wvl, pv, nullptr, nullptr, nullptr, nullptr, nullptr, nullptr, nullptr, HD, HD, HD, HD, 0);
    hmma_gemm_kernel<<<dim3(HD / 64, RL / 128), blk, GM_SMEM>>>(
        posh, posl, wrh, wrl, nullptr, nullptr, rh, rl, nullptr, nullptr, nullptr, nullptr, HD, HD, HD, HD, 0);

    convT_kernel<<<dim3(HD / 32, CL / 32), blk>>>(pv, vth, vtl, CL, HD);
    eseg_kernel<<<(2 * NH * QL) / 256, blk>>>(cb, sbb, seg);

    score_hmma_kernel<<<dim3(CL / 128, QL / 128, NH), blk, S_SMEM>>>(mask, segm);
    pv_fused_kernel<<<dim3(QL / 128, NH), blk, PV_SMEM>>>();

    hmma_gemm_kernel<<<dim3(HD / 64, QL / 128), blk, GM_SMEM>>>(
        ath, atl, woh, wol, pao, nullptr, nullptr, nullptr, nullptr, nullptr, nullptr, nullptr, HD, HD, HD, HD, 0);

    ln_kernel<<<QL, blk>>>(pao, cs, g1, be1, pfi, fih, fil);

    hmma_gemm_kernel<<<dim3(FF / 64, QL / 128), blk, GM_SMEM>>>(
        fih, fil, w1h, w1l, nullptr, nullptr, fhh, fhl, bf1, nullptr, nullptr, nullptr, HD, HD, HD, FF, 1);
    hmma_gemm_kernel<<<dim3(HD / 64, QL / 128), blk, GM_SMEM>>>(
        fhh, fhl, w2h, w2l, pfo, bf2, nullptr, nullptr, nullptr, nullptr, nullptr, nullptr, FF, FF, FF, HD, 0);

    ln_kernel<<<QL, blk>>>(pfo, pfi, g2, be2, out, nullptr, nullptr);
}

// round 8
// speedup vs baseline: 1.0530x; 1.0132x over previous
#include <cuda_runtime.h>
#include <cuda_bf16.h>
#include <math.h>
#include <stdint.h>

#define QL 2048
#define CL 2048
#define HD 1024
#define NH 16
#define DH 64
#define FF 4096
#define RL 4096
typedef __nv_bfloat16 bf16;
typedef __nv_bfloat162 bf162;

// ---------------- scratch ----------------
__device__ float g_v[CL * HD];
__device__ float g_scores[(size_t)NH * QL * CL];
__device__ float g_eseg[2 * NH * QL];
__device__ float g_attnout[QL * HD];
__device__ float g_ffnin[QL * HD];
__device__ float g_ffnout[QL * HD];
__device__ bf16 g_csh[QL * HD], g_csl[QL * HD];
__device__ bf16 g_ctxh[CL * HD], g_ctxl[CL * HD];
__device__ bf16 g_posh[RL * HD], g_posl[RL * HD];
__device__ bf16 g_qch[QL * HD], g_qcl[QL * HD];
__device__ bf16 g_qph[QL * HD], g_qpl[QL * HD];
__device__ bf16 g_kh[CL * HD], g_kl[CL * HD];
__device__ bf16 g_rh[RL * HD], g_rl[RL * HD];
__device__ bf16 g_ath[QL * HD], g_atl[QL * HD];
__device__ bf16 g_fih[QL * HD], g_fil[QL * HD];
__device__ bf16 g_fhh[(size_t)QL * FF], g_fhl[(size_t)QL * FF];
__device__ bf16 g_wqh[HD * HD], g_wql[HD * HD];
__device__ bf16 g_wkh[HD * HD], g_wkl[HD * HD];
__device__ bf16 g_wvh[HD * HD], g_wvl[HD * HD];
__device__ bf16 g_wrh[HD * HD], g_wrl[HD * HD];
__device__ bf16 g_woh[HD * HD], g_wol[HD * HD];
__device__ bf16 g_w1h[(size_t)FF * HD], g_w1l[(size_t)FF * HD];
__device__ bf16 g_w2h[(size_t)FF * HD], g_w2l[(size_t)FF * HD];
__device__ bf16 g_vth[HD * CL], g_vtl[HD * CL];

#define SWZ(o) ((o) ^ (((o) >> 3) & 0x70))

__device__ __forceinline__ uint32_t smem_u32(const void* p) {
    uint32_t a;
    asm("{ .reg .u64 t; cvta.to.shared.u64 t, %1; cvt.u32.u64 %0, t; }" : "=r"(a) : "l"(p));
    return a;
}
__device__ __forceinline__ void cpasync16(uint32_t s, const void* g) {
    asm volatile("cp.async.cg.shared.global [%0], [%1], 16;" :: "r"(s), "l"(g));
}
#define CP_COMMIT() asm volatile("cp.async.commit_group;")
#define CP_WAIT(n) asm volatile("cp.async.wait_group %0;" :: "n"(n))

__device__ __forceinline__ void splitbf(float x, bf16& h, bf16& l) {
    h = __float2bfloat16(x);
    l = __float2bfloat16(x - __bfloat162float(h));
}
__device__ __forceinline__ void wsplit2(bf16* oh, bf16* ol, long long off, float x, float y) {
    bf16 h0, l0, h1, l1;
    splitbf(x, h0, l0); splitbf(y, h1, l1);
    *(bf162*)(oh + off) = __halves2bfloat162(h0, h1);
    *(bf162*)(ol + off) = __halves2bfloat162(l0, l1);
}
__device__ __forceinline__ float warpSum(float v) {
#pragma unroll
    for (int o = 16; o; o >>= 1) v += __shfl_xor_sync(0xffffffffu, v, o);
    return v;
}
__device__ __forceinline__ float warpMax(float v) {
#pragma unroll
    for (int o = 16; o; o >>= 1) v = fmaxf(v, __shfl_xor_sync(0xffffffffu, v, o));
    return v;
}
__device__ __forceinline__ void mma_bf16(float* d, const uint32_t* a, const uint32_t* b) {
    asm volatile(
        "mma.sync.aligned.m16n8k16.row.col.f32.bf16.bf16.f32 "
        "{%0,%1,%2,%3}, {%4,%5,%6,%7}, {%8,%9}, {%0,%1,%2,%3};"
        : "+f"(d[0]), "+f"(d[1]), "+f"(d[2]), "+f"(d[3])
        : "r"(a[0]), "r"(a[1]), "r"(a[2]), "r"(a[3]), "r"(b[0]), "r"(b[1]));
}
__device__ __forceinline__ void ldm4(uint32_t* r, uint32_t base, int row0, int k0, int lane) {
    int row = row0 + (lane & 15);
    int kc = k0 + ((lane >> 4) << 3);
    uint32_t addr = base + SWZ((uint32_t)row * 128 + (uint32_t)kc * 2);
    asm volatile("ldmatrix.sync.aligned.m8n8.x4.shared.b16 {%0,%1,%2,%3}, [%4];"
                 : "=r"(r[0]), "=r"(r[1]), "=r"(r[2]), "=r"(r[3]) : "r"(addr));
}

// ---------------- converters ----------------
__global__ void __launch_bounds__(256) convT_kernel(
    const float* __restrict__ in, bf16* __restrict__ oh, bf16* __restrict__ ol, int R, int Cc)
{
    __shared__ float t[32][33];
    const int tx = threadIdx.x & 31, ty8 = threadIdx.x >> 5;
    const int r0 = blockIdx.y * 32, c0 = blockIdx.x * 32;
    for (int j = ty8; j < 32; j += 8) t[j][tx] = in[(long long)(r0 + j) * Cc + c0 + tx];
    __syncthreads();
    for (int j = ty8; j < 32; j += 8) {
        bf16 h, l; splitbf(t[tx][j], h, l);
        long long o = (long long)(c0 + j) * R + r0 + tx;
        oh[o] = h; ol[o] = l;
    }
}
__global__ void __launch_bounds__(256) conv_kernel(
    const float* __restrict__ in, bf16* __restrict__ oh, bf16* __restrict__ ol, int n)
{
    int i = blockIdx.x * 256 + threadIdx.x;
    if (i < n) { bf16 h, l; splitbf(in[i], h, l); oh[i] = h; ol[i] = l; }
}
__global__ void __launch_bounds__(256) split4_kernel(
    const float* __restrict__ in, bf16* __restrict__ oh, bf16* __restrict__ ol, int n4)
{
    int i = blockIdx.x * 256 + threadIdx.x;
    if (i >= n4) return;
    float4 v = *(const float4*)(in + i * 4);
    wsplit2(oh, ol, (long long)i * 4, v.x, v.y);
    wsplit2(oh, ol, (long long)i * 4 + 2, v.z, v.w);
}

// ---------------- HMMA GEMM: BM=128, BN=64, BK=64, 256 thr, 2-stage ---------
#define ST_AH 0
#define ST_AL 16384
#define ST_BH 32768
#define ST_BL 40960
#define ST_SZ 49152
#define GM_SMEM (2 * ST_SZ)

__global__ void __launch_bounds__(256) hmma_gemm_kernel(
    const bf16* __restrict__ Ah, const bf16* __restrict__ Al,
    const bf16* __restrict__ Bh, const bf16* __restrict__ Bl,
    float* __restrict__ C, const float* __restrict__ biasC,
    bf16* __restrict__ O1h, bf16* __restrict__ O1l, const float* __restrict__ bias1,
    bf16* __restrict__ O2h, bf16* __restrict__ O2l, const float* __restrict__ bias2,
    int K, int lda, int ldb, int ldc, int relu)
{
    extern __shared__ char smem[];
    const uint32_t sbase = smem_u32(smem);
    const int tid = threadIdx.x, lane = tid & 31, w = tid >> 5;
    const int g = lane >> 2, tig = lane & 3;
    const int m0 = blockIdx.y * 128, n0 = blockIdx.x * 64;
    const int wm = (w >> 1) * 32, wn = (w & 1) * 32;

    auto load_stage = [&](int s, int k0) {
        uint32_t sb = sbase + s * ST_SZ;
#pragma unroll
        for (int i = 0; i < 4; i++) {
            int u = tid + (i << 8);
            int row = u >> 3, c16 = u & 7;
            uint32_t sw = SWZ((uint32_t)row * 128 + (uint32_t)(c16 << 4));
            const long long ga = (long long)(m0 + row) * lda + k0 + (c16 << 3);
            cpasync16(sb + ST_AH + sw, Ah + ga);
            cpasync16(sb + ST_AL + sw, Al + ga);
        }
#pragma unroll
        for (int i = 0; i < 2; i++) {
            int u = tid + (i << 8);
            int row = u >> 3, c16 = u & 7;
            uint32_t sw = SWZ((uint32_t)row * 128 + (uint32_t)(c16 << 4));
            const long long gb = (long long)(n0 + row) * ldb + k0 + (c16 << 3);
            cpasync16(sb + ST_BH + sw, Bh + gb);
            cpasync16(sb + ST_BL + sw, Bl + gb);
        }
    };

    float acc[2][4][4] = {};
    const int NC = K >> 6;
    load_stage(0, 0);
    CP_COMMIT();
    for (int c = 0; c < NC; c++) {
        if (c + 1 < NC) { load_stage((c + 1) & 1, (c + 1) << 6); CP_COMMIT(); CP_WAIT(1); }
        else CP_WAIT(0);
        __syncthreads();
        const uint32_t sb = sbase + (c & 1) * ST_SZ;
#pragma unroll
        for (int ks = 0; ks < 4; ks++) {
            uint32_t ah[2][4], al[2][4], bh[2][4], bl[2][4];
            ldm4(ah[0], sb + ST_AH, wm, ks * 16, lane);
            ldm4(ah[1], sb + ST_AH, wm + 16, ks * 16, lane);
            ldm4(al[0], sb + ST_AL, wm, ks * 16, lane);
            ldm4(al[1], sb + ST_AL, wm + 16, ks * 16, lane);
            ldm4(bh[0], sb + ST_BH, wn, ks * 16, lane);
            ldm4(bh[1], sb + ST_BH, wn + 16, ks * 16, lane);
            ldm4(bl[0], sb + ST_BL, wn, ks * 16, lane);
            ldm4(bl[1], sb + ST_BL, wn + 16, ks * 16, lane);
#pragma unroll
            for (int mt = 0; mt < 2; mt++)
#pragma unroll
                for (int nt = 0; nt < 4; nt++) {
                    const int p = nt >> 1, o = nt & 1;
                    uint32_t fbh[2] = { bh[p][o], bh[p][2 + o] };
                    uint32_t fbl[2] = { bl[p][o], bl[p][2 + o] };
                    mma_bf16(acc[mt][nt], ah[mt], fbh);
                    mma_bf16(acc[mt][nt], ah[mt], fbl);
                    mma_bf16(acc[mt][nt], al[mt], fbh);
                }
        }
        __syncthreads();
    }

#pragma unroll
    for (int mt = 0; mt < 2; mt++)
#pragma unroll
        for (int nt = 0; nt < 4; nt++) {
#pragma unroll
            for (int h = 0; h < 2; h++) {
                const int row = m0 + wm + mt * 16 + g + h * 8;
                const int col = n0 + wn + nt * 8 + 2 * tig;
                float x = acc[mt][nt][h * 2], y = acc[mt][nt][h * 2 + 1];
                const long long off = (long long)row * ldc + col;
                if (C) {
                    float b0 = biasC ? biasC[col] : 0.f, b1 = biasC ? biasC[col + 1] : 0.f;
                    float2 o = { x + b0, y + b1 };
                    *(float2*)(C + off) = o;
                }
                if (O1h) {
                    float b0 = bias1 ? bias1[col] : 0.f, b1 = bias1 ? bias1[col + 1] : 0.f;
                    float vx = x + b0, vy = y + b1;
                    if (relu) { vx = fmaxf(vx, 0.f); vy = fmaxf(vy, 0.f); }
                    wsplit2(O1h, O1l, off, vx, vy);
                }
                if (O2h) {
                    float b0 = bias2 ? bias2[col] : 0.f, b1 = bias2 ? bias2[col + 1] : 0.f;
                    wsplit2(O2h, O2l, off, x + b0, y + b1);
                }
            }
        }
}

// ---------------- HMMA score kernel ----------------
#define S_QCH 0
#define S_QCL 16384
#define S_QPH 32768
#define S_QPL 49152
#define S_KH  65536
#define S_KL  81920
#define S_RH  98304
#define S_RL  131072
#define S_ST  163840
#define S_SMEM (163840 + 8 * 3200)

__global__ void __launch_bounds__(256) score_hmma_kernel(
    const float* __restrict__ mask, const unsigned char* __restrict__ segmat)
{
    extern __shared__ char smem[];
    const uint32_t sbase = smem_u32(smem);
    const int tid = threadIdx.x, lane = tid & 31, w = tid >> 5;
    const int g = lane >> 2, tig = lane & 3;
    const int n = blockIdx.z, q0 = blockIdx.y * 128, c0 = blockIdx.x * 128;
    const int nDH = n * DH;

    auto ldtile = [&](int dsth, int dstl, const bf16* srch, const bf16* srcl, long long rbase, int ldg) {
#pragma unroll
        for (int i = 0; i < 4; i++) {
            int u = tid + (i << 8);
            int row = u >> 3, c16 = u & 7;
            uint32_t sw = SWZ((uint32_t)row * 128 + (uint32_t)(c16 << 4));
            long long gofs = (rbase + row) * ldg + nDH + (c16 << 3);
            *(uint4*)(smem + dsth + sw) = *(const uint4*)(srch + gofs);
            *(uint4*)(smem + dstl + sw) = *(const uint4*)(srcl + gofs);
        }
    };
    ldtile(S_QCH, S_QCL, g_qch, g_qcl, q0, HD);
    ldtile(S_QPH, S_QPL, g_qph, g_qpl, q0, HD);
    ldtile(S_KH, S_KL, g_kh, g_kl, c0, HD);
    const int rstart = QL + c0 - q0 - 127;
#pragma unroll
    for (int i = 0; i < 8; i++) {
        int u = tid + (i << 8);
        int row = u >> 3, c16 = u & 7;
        int rg = rstart + row; if (rg > RL - 1) rg = RL - 1;
        uint32_t sw = SWZ((uint32_t)row * 128 + (uint32_t)(c16 << 4));
        long long gofs = (long long)rg * HD + nDH + (c16 << 3);
        *(uint4*)(smem + S_RH + sw) = *(const uint4*)(g_rh + gofs);
        *(uint4*)(smem + S_RL + sw) = *(const uint4*)(g_rl + gofs);
    }
    __syncthreads();

    const int w0 = w * 16;
    const float e0a = g_eseg[(0 * NH + n) * QL + q0 + w0 + g];
    const float e1a = g_eseg[(1 * NH + n) * QL + q0 + w0 + g];
    const float e0b = g_eseg[(0 * NH + n) * QL + q0 + w0 + g + 8];
    const float e1b = g_eseg[(1 * NH + n) * QL + q0 + w0 + g + 8];
    float* stg = (float*)(smem + S_ST + w * 3200);

    for (int ch = 0; ch < 4; ch++) {
        float accA[4][4] = {};
        float accB[6][4] = {};
        const int s0 = ch * 32 - w0 + 112;
#pragma unroll
        for (int ks = 0; ks < 4; ks++) {
            uint32_t ach[4], acl[4], aph[4], apl[4];
            ldm4(ach, sbase + S_QCH, w0, ks * 16, lane);
            ldm4(acl, sbase + S_QCL, w0, ks * 16, lane);
            ldm4(aph, sbase + S_QPH, w0, ks * 16, lane);
            ldm4(apl, sbase + S_QPL, w0, ks * 16, lane);
            uint32_t kh[2][4], kl[2][4];
            ldm4(kh[0], sbase + S_KH, ch * 32, ks * 16, lane);
            ldm4(kh[1], sbase + S_KH, ch * 32 + 16, ks * 16, lane);
            ldm4(kl[0], sbase + S_KL, ch * 32, ks * 16, lane);
            ldm4(kl[1], sbase + S_KL, ch * 32 + 16, ks * 16, lane);
#pragma unroll
            for (int nt = 0; nt < 4; nt++) {
                const int p = nt >> 1, o = nt & 1;
                uint32_t fbh[2] = { kh[p][o], kh[p][2 + o] };
                uint32_t fbl[2] = { kl[p][o], kl[p][2 + o] };
                mma_bf16(accA[nt], ach, fbh);
                mma_bf16(accA[nt], ach, fbl);
                mma_bf16(accA[nt], acl, fbh);
            }
            uint32_t rh[3][4], rl[3][4];
#pragma unroll
            for (int p = 0; p < 3; p++) {
                ldm4(rh[p], sbase + S_RH, s0 + p * 16, ks * 16, lane);
                ldm4(rl[p], sbase + S_RL, s0 + p * 16, ks * 16, lane);
            }
#pragma unroll
            for (int nt = 0; nt < 6; nt++) {
                const int p = nt >> 1, o = nt & 1;
                uint32_t fbh[2] = { rh[p][o], rh[p][2 + o] };
                uint32_t fbl[2] = { rl[p][o], rl[p][2 + o] };
                mma_bf16(accB[nt], aph, fbh);
                mma_bf16(accB[nt], aph, fbl);
                mma_bf16(accB[nt], apl, fbh);
            }
        }
#pragma unroll
        for (int nt = 0; nt < 6; nt++) {
            int cc = nt * 8 + 2 * tig;
            stg[g * 50 + cc] = accB[nt][0];
            stg[g * 50 + cc + 1] = accB[nt][1];
            stg[(g + 8) * 50 + cc] = accB[nt][2];
            stg[(g + 8) * 50 + cc + 1] = accB[nt][3];
        }
        __syncwarp();
#pragma unroll
        for (int nt = 0; nt < 4; nt++) {
            const int jl = nt * 8 + 2 * tig;
            const float bd0 = stg[g * 50 + jl - g + 15], bd1 = stg[g * 50 + jl - g + 16];
            const float bd2 = stg[(g + 8) * 50 + jl - g + 7], bd3 = stg[(g + 8) * 50 + jl - g + 8];
            const int qa = q0 + w0 + g, cc = c0 + ch * 32 + jl;
            const size_t ma = (size_t)qa * CL + cc;
            const size_t mb = (size_t)(qa + 8) * CL + cc;
            float2 mka = *(const float2*)(mask + ma);
            float2 mkb = *(const float2*)(mask + mb);
            uchar2 sga = *(const uchar2*)(segmat + ma);
            uchar2 sgb = *(const uchar2*)(segmat + mb);
            float2 oa, ob;
            oa.x = (accA[nt][0] + bd0 + (sga.x ? e1a : e0a)) * 0.125f - 1e30f * mka.x;
            oa.y = (accA[nt][1] + bd1 + (sga.y ? e1a : e0a)) * 0.125f - 1e30f * mka.y;
            ob.x = (accA[nt][2] + bd2 + (sgb.x ? e1b : e0b)) * 0.125f - 1e30f * mkb.x;
            ob.y = (accA[nt][3] + bd3 + (sgb.y ? e1b : e0b)) * 0.125f - 1e30f * mkb.y;
            *(float2*)(g_scores + ((size_t)n * QL + qa) * CL + cc) = oa;
            *(float2*)(g_scores + ((size_t)n * QL + qa + 8) * CL + cc) = ob;
        }
        __syncwarp();
    }
}

// ---------------- fused online-softmax + probs@V (pipelined) ----------------
#define PV_V0 0
#define PV_V1 16384
#define PV_PH 32768
#define PV_PL 49152
#define PV_SC 65536
#define PV_SCW 68            /* padded row stride in floats (272B, 16B-mult) */
#define PV_SMEM (65536 + 128 * PV_SCW * 4)

__global__ void __launch_bounds__(256) pv_fused_kernel()
{
    extern __shared__ char smem[];
    const uint32_t sbase = smem_u32(smem);
    const int tid = threadIdx.x, lane = tid & 31, w = tid >> 5;
    const int g = lane >> 2, tig = lane & 3;
    const int n = blockIdx.y, q0 = blockIdx.x * 128;
    const int w0 = w * 16;
    const int ri = lane >> 1, half = lane & 1;

    const bf16* vt_h = g_vth + (long long)(n * 64) * CL;
    const bf16* vt_l = g_vtl + (long long)(n * 64) * CL;
    float* sc = (float*)(smem + PV_SC);
    const float* sgbase = g_scores + ((size_t)n * QL + q0) * CL;

    auto loadV = [&](int s, int c0) {
        uint32_t sb = sbase + (s ? PV_V1 : PV_V0);
#pragma unroll
        for (int i = 0; i < 2; i++) {
            int u = tid + (i << 8);
            int row = u >> 3, c16 = u & 7;
            uint32_t sw = SWZ((uint32_t)row * 128 + (uint32_t)(c16 << 4));
            long long gofs = (long long)row * CL + c0 + (c16 << 3);
            cpasync16(sb + sw, vt_h + gofs);
            cpasync16(sb + 8192 + sw, vt_l + gofs);
        }
    };
    auto loadSC = [&](int cb) {
#pragma unroll
        for (int i = 0; i < 8; i++) {
            int u = tid + (i << 8);         // 2048 uint4
            int row = u >> 4, c16 = u & 15;
            cpasync16(sbase + PV_SC + (uint32_t)row * (PV_SCW * 4) + (uint32_t)(c16 << 4),
                      sgbase + (size_t)row * CL + cb * 64 + c16 * 4);
        }
    };

    float m_run = -3.0e38f, l_run = 0.f;
    float accO[8][4] = {};

    loadSC(0); loadV(0, 0); CP_COMMIT();
    for (int cb = 0; cb < CL / 64; cb++) {
        CP_WAIT(0);
        __syncthreads();

        // ---- softmax phase (reads sc, writes P) ----
        const float* srow = sc + (w0 + ri) * PV_SCW + half * 32;
        float4 sv[8];
#pragma unroll
        for (int j = 0; j < 8; j++) sv[j] = *(const float4*)(srow + j * 4);
        float cmax = -3.0e38f;
#pragma unroll
        for (int j = 0; j < 8; j++)
            cmax = fmaxf(cmax, fmaxf(fmaxf(sv[j].x, sv[j].y), fmaxf(sv[j].z, sv[j].w)));
        cmax = fmaxf(cmax, __shfl_xor_sync(0xffffffffu, cmax, 1));
        const float m_new = fmaxf(m_run, cmax);
        const float scale = __expf(m_run - m_new);
        m_run = m_new;
        float csum = 0.f;
#pragma unroll
        for (int j = 0; j < 8; j++) {
            float p0 = __expf(sv[j].x - m_new), p1 = __expf(sv[j].y - m_new);
            float p2 = __expf(sv[j].z - m_new), p3 = __expf(sv[j].w - m_new);
            csum += (p0 + p1) + (p2 + p3);
            const int c = half * 32 + j * 4;
            const uint32_t sw = SWZ((uint32_t)(w0 + ri) * 128 + (uint32_t)c * 2);
            bf16 h0, l0, h1, l1, h2, l2, h3, l3;
            splitbf(p0, h0, l0); splitbf(p1, h1, l1); splitbf(p2, h2, l2); splitbf(p3, h3, l3);
            *(bf162*)(smem + PV_PH + sw) = __halves2bfloat162(h0, h1);
            *(bf162*)(smem + PV_PH + sw + 4) = __halves2bfloat162(h2, h3);
            *(bf162*)(smem + PV_PL + sw) = __halves2bfloat162(l0, l1);
            *(bf162*)(smem + PV_PL + sw + 4) = __halves2bfloat162(l2, l3);
        }
        csum += __shfl_xor_sync(0xffffffffu, csum, 1);
        l_run = l_run * scale + csum;
        const float sA = __shfl_sync(0xffffffffu, scale, 2 * g);
        const float sB = __shfl_sync(0xffffffffu, scale, 2 * g + 16);
#pragma unroll
        for (int t = 0; t < 8; t++) {
            accO[t][0] *= sA; accO[t][1] *= sA;
            accO[t][2] *= sB; accO[t][3] *= sB;
        }
        __syncthreads();   // sc consumed, P visible to own warp

        // ---- prefetch next tiles (overlaps with MMA phase) ----
        if (cb + 1 < CL / 64) {
            loadSC(cb + 1);
            loadV((cb + 1) & 1, (cb + 1) * 64);
            CP_COMMIT();
        }

        // ---- PV MMA phase (reads P + current V) ----
        const uint32_t vb = sbase + ((cb & 1) ? PV_V1 : PV_V0);
#pragma unroll
        for (int ks = 0; ks < 4; ks++) {
            uint32_t aH[4], aL[4];
            ldm4(aH, sbase + PV_PH, w0, ks * 16, lane);
            ldm4(aL, sbase + PV_PL, w0, ks * 16, lane);
            uint32_t bH[4][4], bL[4][4];
#pragma unroll
            for (int p = 0; p < 4; p++) {
                ldm4(bH[p], vb, p * 16, ks * 16, lane);
                ldm4(bL[p], vb + 8192, p * 16, ks * 16, lane);
            }
#pragma unroll
            for (int t = 0; t < 8; t++) {
                const int p = t >> 1, o = t & 1;
                uint32_t fbh[2] = { bH[p][o], bH[p][2 + o] };
                uint32_t fbl[2] = { bL[p][o], bL[p][2 + o] };
                mma_bf16(accO[t], aH, fbh);
                mma_bf16(accO[t], aH, fbl);
                mma_bf16(accO[t], aL, fbh);
            }
        }
    }
    const float li = 1.0f / l_run;
    const float lA = __shfl_sync(0xffffffffu, li, 2 * g);
    const float lB = __shfl_sync(0xffffffffu, li, 2 * g + 16);
#pragma unroll
    for (int t = 0; t < 8; t++) {
        const int dloc = (t >> 1) * 16 + (t & 1) * 8 + 2 * tig;
        const long long col = (long long)n * 64 + dloc;
        const long long offA = (long long)(q0 + w0 + g) * HD + col;
        const long long offB = (long long)(q0 + w0 + g + 8) * HD + col;
        wsplit2(g_ath, g_atl, offA, accO[t][0] * lA, accO[t][1] * lA);
        wsplit2(g_ath, g_atl, offB, accO[t][2] * lB, accO[t][3] * lB);
    }
}

// ---------------- eseg ----------------
__global__ void __launch_bounds__(256) eseg_kernel(
    const float* __restrict__ cb, const float* __restrict__ sb, const float* __restrict__ seg)
{
    int idx = blockIdx.x * 256 + threadIdx.x;
    if (idx >= 2 * NH * QL) return;
    int s = idx / (NH * QL), n = (idx / QL) % NH, qi = idx % QL;
    const bf16* qh = g_qch + (long long)qi * HD + n * DH;
    const bf16* ql = g_qcl + (long long)qi * HD + n * DH;
    const float* cbr = cb + n * DH;
    const float* sbr = sb + n * DH;
    const float* sg = seg + s * (NH * DH) + n * DH;
    float acc = 0.f;
#pragma unroll
    for (int d = 0; d < DH; d++) {
        float q = __bfloat162float(qh[d]) + __bfloat162float(ql[d]) - cbr[d] + sbr[d];
        acc += q * sg[d];
    }
    g_eseg[idx] = acc;
}

// ---------------- residual + LN ----------------
__global__ void __launch_bounds__(256) ln_kernel(
    const float* __restrict__ x, const float* __restrict__ res,
    const float* __restrict__ g, const float* __restrict__ b,
    float* __restrict__ out, bf16* __restrict__ oh, bf16* __restrict__ ol)
{
    const int row = blockIdx.x;
    __shared__ float buf[HD];
    __shared__ float red[8];
    __shared__ float s_mean, s_rstd;
    const int tid = threadIdx.x;
    float lsum = 0.f;
    for (int i = tid; i < HD; i += 256) {
        float v = x[(long long)row * HD + i] + res[(long long)row * HD + i];
        buf[i] = v; lsum += v;
    }
    lsum = warpSum(lsum);
    if ((tid & 31) == 0) red[tid >> 5] = lsum;
    __syncthreads();
    if (tid == 0) {
        float s = 0.f;
#pragma unroll
        for (int i = 0; i < 8; i++) s += red[i];
        s_mean = s * (1.0f / HD);
    }
    __syncthreads();
    const float m = s_mean;
    float lv = 0.f;
    for (int i = tid; i < HD; i += 256) { float d = buf[i] - m; lv += d * d; }
    lv = warpSum(lv);
    __syncthreads();
    if ((tid & 31) == 0) red[tid >> 5] = lv;
    __syncthreads();
    if (tid == 0) {
        float s = 0.f;
#pragma unroll
        for (int i = 0; i < 8; i++) s += red[i];
        s_rstd = rsqrtf(s * (1.0f / HD) + 1e-12f);
    }
    __syncthreads();
    const float rs = s_rstd;
    for (int i = tid; i < HD; i += 256) {
        float o = (buf[i] - m) * rs * g[i] + b[i];
        if (out) out[(long long)row * HD + i] = o;
        if (oh) { bf16 h, l; splitbf(o, h, l); oh[(long long)row * HD + i] = h; ol[(long long)row * HD + i] = l; }
    }
}

// ---------------- launch ----------------
extern "C" void kernel_launch(void* const* d_in, const int* in_sizes, int n_in,
                              void* d_out, int out_size)
{
    const float* cs = (const float*)d_in[0];
    const float* mask = (const float*)d_in[1];
    const float* ctx = (const float*)d_in[2];
    const float* pos = (const float*)d_in[3];
    const float* cb = (const float*)d_in[4];
    const float* pb = (const float*)d_in[5];
    const float* seg = (const float*)d_in[6];
    const unsigned char* segm = (const unsigned char*)d_in[7];
    const float* sbb = (const float*)d_in[8];
    const float* Wq = (const float*)d_in[9];
    const float* Wk = (const float*)d_in[10];
    const float* Wv = (const float*)d_in[11];
    const float* Wr = (const float*)d_in[12];
    const float* Wo = (const float*)d_in[13];
    const float* g1 = (const float*)d_in[14];
    const float* be1 = (const float*)d_in[15];
    const float* W1 = (const float*)d_in[16];
    const float* bf1 = (const float*)d_in[17];
    const float* W2 = (const float*)d_in[18];
    const float* bf2 = (const float*)d_in[19];
    const float* g2 = (const float*)d_in[20];
    const float* be2 = (const float*)d_in[21];
    float* out = (float*)d_out;

#define SYM(T, name, sym) T* name; cudaGetSymbolAddress((void**)&name, sym)
    SYM(float, pv, g_v); SYM(float, pao, g_attnout);
    SYM(float, pfi, g_ffnin); SYM(float, pfo, g_ffnout);
    SYM(bf16, csh, g_csh); SYM(bf16, csl, g_csl);
    SYM(bf16, ctxh, g_ctxh); SYM(bf16, ctxl, g_ctxl);
    SYM(bf16, posh, g_posh); SYM(bf16, posl, g_posl);
    SYM(bf16, qch, g_qch); SYM(bf16, qcl, g_qcl);
    SYM(bf16, qph, g_qph); SYM(bf16, qpl, g_qpl);
    SYM(bf16, kh, g_kh); SYM(bf16, kl, g_kl);
    SYM(bf16, rh, g_rh); SYM(bf16, rl, g_rl);
    SYM(bf16, ath, g_ath); SYM(bf16, atl, g_atl);
    SYM(bf16, fih, g_fih); SYM(bf16, fil, g_fil);
    SYM(bf16, fhh, g_fhh); SYM(bf16, fhl, g_fhl);
    SYM(bf16, wqh, g_wqh); SYM(bf16, wql, g_wql);
    SYM(bf16, wkh, g_wkh); SYM(bf16, wkl, g_wkl);
    SYM(bf16, wvh, g_wvh); SYM(bf16, wvl, g_wvl);
    SYM(bf16, wrh, g_wrh); SYM(bf16, wrl, g_wrl);
    SYM(bf16, woh, g_woh); SYM(bf16, wol, g_wol);
    SYM(bf16, w1h, g_w1h); SYM(bf16, w1l, g_w1l);
    SYM(bf16, w2h, g_w2h); SYM(bf16, w2l, g_w2l);
    SYM(bf16, vth, g_vth); SYM(bf16, vtl, g_vtl);
#undef SYM

    cudaFuncSetAttribute(hmma_gemm_kernel, cudaFuncAttributeMaxDynamicSharedMemorySize, GM_SMEM);
    cudaFuncSetAttribute(score_hmma_kernel, cudaFuncAttributeMaxDynamicSharedMemorySize, S_SMEM);
    cudaFuncSetAttribute(pv_fused_kernel, cudaFuncAttributeMaxDynamicSharedMemorySize, PV_SMEM);

    dim3 blk(256);
    // --- ordered so launch index 5 (ncu -s 5 -c 1) is the biggest projection GEMM ---
    split4_kernel<<<(RL * HD / 4) / 256, blk>>>(pos, posh, posl, RL * HD / 4);     // 0
    convT_kernel<<<dim3(HD / 32, HD / 32), blk>>>(Wr, wrh, wrl, HD, HD);           // 1
    split4_kernel<<<(QL * HD / 4) / 256, blk>>>(cs, csh, csl, QL * HD / 4);        // 2
    split4_kernel<<<(CL * HD / 4) / 256, blk>>>(ctx, ctxh, ctxl, CL * HD / 4);     // 3
    convT_kernel<<<dim3(HD / 32, HD / 32), blk>>>(Wq, wqh, wql, HD, HD);           // 4
    hmma_gemm_kernel<<<dim3(HD / 64, RL / 128), blk, GM_SMEM>>>(                   // 5 <- profiled
        posh, posl, wrh, wrl, nullptr, nullptr, rh, rl, nullptr, nullptr, nullptr, nullptr, HD, HD, HD, HD, 0);

    convT_kernel<<<dim3(HD / 32, HD / 32), blk>>>(Wk, wkh, wkl, HD, HD);
    convT_kernel<<<dim3(HD / 32, HD / 32), blk>>>(Wv, wvh, wvl, HD, HD);
    conv_kernel<<<(HD * HD) / 256, blk>>>(Wo, woh, wol, HD * HD);
    convT_kernel<<<dim3(FF / 32, HD / 32), blk>>>(W1, w1h, w1l, HD, FF);
    convT_kernel<<<dim3(HD / 32, FF / 32), blk>>>(W2, w2h, w2l, FF, HD);

    hmma_gemm_kernel<<<dim3(HD / 64, QL / 128), blk, GM_SMEM>>>(
        csh, csl, wqh, wql, nullptr, nullptr, qch, qcl, cb, qph, qpl, pb, HD, HD, HD, HD, 0);
    hmma_gemm_kernel<<<dim3(HD / 64, CL / 128), blk, GM_SMEM>>>(
        ctxh, ctxl, wkh, wkl, nullptr, nullptr, kh, kl, nullptr, nullptr, nullptr, nullptr, HD, HD, HD, HD, 0);
    hmma_gemm_kernel<<<dim3(HD / 64, CL / 128), blk, GM_SMEM>>>(
        ctxh, ctxl, wvh, wvl, pv, nullptr, nullptr, nullptr, nullptr, nullptr, nullptr, nullptr, HD, HD, HD, HD, 0);

    convT_kernel<<<dim3(HD / 32, CL / 32), blk>>>(pv, vth, vtl, CL, HD);
    eseg_kernel<<<(2 * NH * QL) / 256, blk>>>(cb, sbb, seg);

    score_hmma_kernel<<<dim3(CL / 128, QL / 128, NH), blk, S_SMEM>>>(mask, segm);
    pv_fused_kernel<<<dim3(QL / 128, NH), blk, PV_SMEM>>>();

    hmma_gemm_kernel<<<dim3(HD / 64, QL / 128), blk, GM_SMEM>>>(
        ath, atl, woh, wol, pao, nullptr, nullptr, nullptr, nullptr, nullptr, nullptr, nullptr, HD, HD, HD, HD, 0);

    ln_kernel<<<QL, blk>>>(pao, cs, g1, be1, pfi, fih, fil);

    hmma_gemm_kernel<<<dim3(FF / 64, QL / 128), blk, GM_SMEM>>>(
        fih, fil, w1h, w1l, nullptr, nullptr, fhh, fhl, bf1, nullptr, nullptr, nullptr, HD, HD, HD, FF, 1);
    hmma_gemm_kernel<<<dim3(HD / 64, QL / 128), blk, GM_SMEM>>>(
        fhh, fhl, w2h, w2l, pfo, bf2, nullptr, nullptr, nullptr, nullptr, nullptr, nullptr, FF, FF, FF, HD, 0);

    ln_kernel<<<QL, blk>>>(pfo, pfi, g2, be2, out, nullptr, nullptr);
}

// round 9
// speedup vs baseline: 1.4352x; 1.3630x over previous
#include <cuda_runtime.h>
#include <cuda_fp16.h>
#include <math.h>
#include <stdint.h>

#define QL 2048
#define CL 2048
#define HD 1024
#define NH 16
#define DH 64
#define FF 4096
#define RL 4096
typedef __half half_t;
typedef __half2 half2_t;

// ---------------- scratch ----------------
__device__ float g_v[CL * HD];
__device__ float g_scores[(size_t)NH * QL * CL];
__device__ float g_eseg[2 * NH * QL];
__device__ float g_attnout[QL * HD];
__device__ float g_ffnin[QL * HD];
__device__ float g_ffnout[QL * HD];
// A-side single-fp16 buffers
__device__ half_t g_csh[QL * HD];
__device__ half_t g_ctxh[CL * HD];
__device__ half_t g_posh[RL * HD];
__device__ half_t g_qch[QL * HD];
__device__ half_t g_qph[QL * HD];
__device__ half_t g_ath[QL * HD];
__device__ half_t g_fih[QL * HD];
__device__ half_t g_fhh[(size_t)QL * FF];
// B-side hi/lo fp16 buffers
__device__ half_t g_kh[CL * HD], g_kl[CL * HD];
__device__ half_t g_rh[RL * HD], g_rl[RL * HD];
__device__ half_t g_vth[HD * CL], g_vtl[HD * CL];
__device__ half_t g_wqh[HD * HD], g_wql[HD * HD];
__device__ half_t g_wkh[HD * HD], g_wkl[HD * HD];
__device__ half_t g_wvh[HD * HD], g_wvl[HD * HD];
__device__ half_t g_wrh[HD * HD], g_wrl[HD * HD];
__device__ half_t g_woh[HD * HD], g_wol[HD * HD];
__device__ half_t g_w1h[(size_t)FF * HD], g_w1l[(size_t)FF * HD];
__device__ half_t g_w2h[(size_t)FF * HD], g_w2l[(size_t)FF * HD];

#define SWZ(o) ((o) ^ (((o) >> 3) & 0x70))

__device__ __forceinline__ uint32_t smem_u32(const void* p) {
    uint32_t a;
    asm("{ .reg .u64 t; cvta.to.shared.u64 t, %1; cvt.u32.u64 %0, t; }" : "=r"(a) : "l"(p));
    return a;
}
__device__ __forceinline__ void cpasync16(uint32_t s, const void* g) {
    asm volatile("cp.async.cg.shared.global [%0], [%1], 16;" :: "r"(s), "l"(g));
}
#define CP_COMMIT() asm volatile("cp.async.commit_group;")
#define CP_WAIT(n) asm volatile("cp.async.wait_group %0;" :: "n"(n))

__device__ __forceinline__ void splith(float x, half_t& h, half_t& l) {
    h = __float2half_rn(x);
    l = __float2half_rn(x - __half2float(h));
}
__device__ __forceinline__ void wsplit2(half_t* oh, half_t* ol, long long off, float x, float y) {
    half_t h0, l0, h1, l1;
    splith(x, h0, l0); splith(y, h1, l1);
    *(half2_t*)(oh + off) = __halves2half2(h0, h1);
    *(half2_t*)(ol + off) = __halves2half2(l0, l1);
}
__device__ __forceinline__ void wone2(half_t* o, long long off, float x, float y) {
    *(half2_t*)(o + off) = __floats2half2_rn(x, y);
}
__device__ __forceinline__ float warpSum(float v) {
#pragma unroll
    for (int o = 16; o; o >>= 1) v += __shfl_xor_sync(0xffffffffu, v, o);
    return v;
}
__device__ __forceinline__ void mma_f16(float* d, const uint32_t* a, const uint32_t* b) {
    asm volatile(
        "mma.sync.aligned.m16n8k16.row.col.f32.f16.f16.f32 "
        "{%0,%1,%2,%3}, {%4,%5,%6,%7}, {%8,%9}, {%0,%1,%2,%3};"
        : "+f"(d[0]), "+f"(d[1]), "+f"(d[2]), "+f"(d[3])
        : "r"(a[0]), "r"(a[1]), "r"(a[2]), "r"(a[3]), "r"(b[0]), "r"(b[1]));
}
__device__ __forceinline__ void ldm4(uint32_t* r, uint32_t base, int row0, int k0, int lane) {
    int row = row0 + (lane & 15);
    int kc = k0 + ((lane >> 4) << 3);
    uint32_t addr = base + SWZ((uint32_t)row * 128 + (uint32_t)kc * 2);
    asm volatile("ldmatrix.sync.aligned.m8n8.x4.shared.b16 {%0,%1,%2,%3}, [%4];"
                 : "=r"(r[0]), "=r"(r[1]), "=r"(r[2]), "=r"(r[3]) : "r"(addr));
}

// ---------------- converters ----------------
__global__ void __launch_bounds__(256) cvt4_kernel(
    const float* __restrict__ in, half_t* __restrict__ o, int n4)
{
    int i = blockIdx.x * 256 + threadIdx.x;
    if (i >= n4) return;
    float4 v = *(const float4*)(in + i * 4);
    wone2(o, (long long)i * 4, v.x, v.y);
    wone2(o, (long long)i * 4 + 2, v.z, v.w);
}
__global__ void __launch_bounds__(256) convT_kernel(
    const float* __restrict__ in, half_t* __restrict__ oh, half_t* __restrict__ ol, int R, int Cc)
{
    __shared__ float t[32][33];
    const int tx = threadIdx.x & 31, ty8 = threadIdx.x >> 5;
    const int r0 = blockIdx.y * 32, c0 = blockIdx.x * 32;
    for (int j = ty8; j < 32; j += 8) t[j][tx] = in[(long long)(r0 + j) * Cc + c0 + tx];
    __syncthreads();
    for (int j = ty8; j < 32; j += 8) {
        half_t h, l; splith(t[tx][j], h, l);
        long long o = (long long)(c0 + j) * R + r0 + tx;
        oh[o] = h; ol[o] = l;
    }
}
__global__ void __launch_bounds__(256) conv_kernel(
    const float* __restrict__ in, half_t* __restrict__ oh, half_t* __restrict__ ol, int n)
{
    int i = blockIdx.x * 256 + threadIdx.x;
    if (i < n) { half_t h, l; splith(in[i], h, l); oh[i] = h; ol[i] = l; }
}

// ---------------- HMMA GEMM: C[M,N]=A[M,K]@B[N,K]^T, A fp16 x1, B fp16 hi/lo
// BM=128, BN=64, BK=64, 256 threads (8 warps 4m x 2n, warp tile 32x32), 2-stage
#define ST_A 0
#define ST_BH 16384
#define ST_BL 24576
#define ST_SZ 32768
#define GM_SMEM (2 * ST_SZ)

__global__ void __launch_bounds__(256) hmma_gemm_kernel(
    const half_t* __restrict__ A,
    const half_t* __restrict__ Bh, const half_t* __restrict__ Bl,
    float* __restrict__ C, const float* __restrict__ biasC,
    half_t* __restrict__ O1h, half_t* __restrict__ O1l, const float* __restrict__ bias1, int relu1,
    half_t* __restrict__ O2h, const float* __restrict__ bias2,
    int K, int lda, int ldb, int ldc)
{
    extern __shared__ char smem[];
    const uint32_t sbase = smem_u32(smem);
    const int tid = threadIdx.x, lane = tid & 31, w = tid >> 5;
    const int g = lane >> 2, tig = lane & 3;
    const int m0 = blockIdx.y * 128, n0 = blockIdx.x * 64;
    const int wm = (w >> 1) * 32, wn = (w & 1) * 32;

    auto load_stage = [&](int s, int k0) {
        uint32_t sb = sbase + s * ST_SZ;
#pragma unroll
        for (int i = 0; i < 4; i++) {
            int u = tid + (i << 8);
            int row = u >> 3, c16 = u & 7;
            uint32_t sw = SWZ((uint32_t)row * 128 + (uint32_t)(c16 << 4));
            cpasync16(sb + ST_A + sw, A + (long long)(m0 + row) * lda + k0 + (c16 << 3));
        }
#pragma unroll
        for (int i = 0; i < 2; i++) {
            int u = tid + (i << 8);
            int row = u >> 3, c16 = u & 7;
            uint32_t sw = SWZ((uint32_t)row * 128 + (uint32_t)(c16 << 4));
            const long long gb = (long long)(n0 + row) * ldb + k0 + (c16 << 3);
            cpasync16(sb + ST_BH + sw, Bh + gb);
            cpasync16(sb + ST_BL + sw, Bl + gb);
        }
    };

    float acc[2][4][4] = {};
    const int NC = K >> 6;
    load_stage(0, 0);
    CP_COMMIT();
    for (int c = 0; c < NC; c++) {
        if (c + 1 < NC) { load_stage((c + 1) & 1, (c + 1) << 6); CP_COMMIT(); CP_WAIT(1); }
        else CP_WAIT(0);
        __syncthreads();
        const uint32_t sb = sbase + (c & 1) * ST_SZ;
#pragma unroll
        for (int ks = 0; ks < 4; ks++) {
            uint32_t ah[2][4], bh[2][4], bl[2][4];
            ldm4(ah[0], sb + ST_A, wm, ks * 16, lane);
            ldm4(ah[1], sb + ST_A, wm + 16, ks * 16, lane);
            ldm4(bh[0], sb + ST_BH, wn, ks * 16, lane);
            ldm4(bh[1], sb + ST_BH, wn + 16, ks * 16, lane);
            ldm4(bl[0], sb + ST_BL, wn, ks * 16, lane);
            ldm4(bl[1], sb + ST_BL, wn + 16, ks * 16, lane);
#pragma unroll
            for (int mt = 0; mt < 2; mt++)
#pragma unroll
                for (int nt = 0; nt < 4; nt++) {
                    const int p = nt >> 1, o = nt & 1;
                    uint32_t fbh[2] = { bh[p][o], bh[p][2 + o] };
                    uint32_t fbl[2] = { bl[p][o], bl[p][2 + o] };
                    mma_f16(acc[mt][nt], ah[mt], fbh);
                    mma_f16(acc[mt][nt], ah[mt], fbl);
                }
        }
        __syncthreads();
    }

#pragma unroll
    for (int mt = 0; mt < 2; mt++)
#pragma unroll
        for (int nt = 0; nt < 4; nt++) {
#pragma unroll
            for (int h = 0; h < 2; h++) {
                const int row = m0 + wm + mt * 16 + g + h * 8;
                const int col = n0 + wn + nt * 8 + 2 * tig;
                float x = acc[mt][nt][h * 2], y = acc[mt][nt][h * 2 + 1];
                const long long off = (long long)row * ldc + col;
                if (C) {
                    float b0 = biasC ? biasC[col] : 0.f, b1 = biasC ? biasC[col + 1] : 0.f;
                    float2 o = { x + b0, y + b1 };
                    *(float2*)(C + off) = o;
                }
                if (O1h) {
                    float b0 = bias1 ? bias1[col] : 0.f, b1 = bias1 ? bias1[col + 1] : 0.f;
                    float vx = x + b0, vy = y + b1;
                    if (relu1) { vx = fmaxf(vx, 0.f); vy = fmaxf(vy, 0.f); }
                    if (O1l) wsplit2(O1h, O1l, off, vx, vy);
                    else wone2(O1h, off, vx, vy);
                }
                if (O2h) {
                    float b0 = bias2 ? bias2[col] : 0.f, b1 = bias2 ? bias2[col + 1] : 0.f;
                    wone2(O2h, off, x + b0, y + b1);
                }
            }
        }
}

// ---------------- HMMA score kernel: A = qc/qp fp16 x1; B = k/r fp16 hi/lo --
#define S_QC 0
#define S_QP 16384
#define S_KH 32768
#define S_KL 49152
#define S_RH 65536
#define S_RL 98304
#define S_ST 131072
#define S_SMEM (131072 + 8 * 3200)

__global__ void __launch_bounds__(256) score_hmma_kernel(
    const float* __restrict__ mask, const unsigned char* __restrict__ segmat)
{
    extern __shared__ char smem[];
    const uint32_t sbase = smem_u32(smem);
    const int tid = threadIdx.x, lane = tid & 31, w = tid >> 5;
    const int g = lane >> 2, tig = lane & 3;
    const int n = blockIdx.z, q0 = blockIdx.y * 128, c0 = blockIdx.x * 128;
    const int nDH = n * DH;

    // q tiles (single) + k tiles (hi/lo): 1024 16B units each buffer
#pragma unroll
    for (int i = 0; i < 4; i++) {
        int u = tid + (i << 8);
        int row = u >> 3, c16 = u & 7;
        uint32_t sw = SWZ((uint32_t)row * 128 + (uint32_t)(c16 << 4));
        long long gq = (long long)(q0 + row) * HD + nDH + (c16 << 3);
        long long gk = (long long)(c0 + row) * HD + nDH + (c16 << 3);
        *(uint4*)(smem + S_QC + sw) = *(const uint4*)(g_qch + gq);
        *(uint4*)(smem + S_QP + sw) = *(const uint4*)(g_qph + gq);
        *(uint4*)(smem + S_KH + sw) = *(const uint4*)(g_kh + gk);
        *(uint4*)(smem + S_KL + sw) = *(const uint4*)(g_kl + gk);
    }
    const int rstart = QL + c0 - q0 - 127;
#pragma unroll
    for (int i = 0; i < 8; i++) {
        int u = tid + (i << 8);
        int row = u >> 3, c16 = u & 7;
        int rg = rstart + row; if (rg > RL - 1) rg = RL - 1;
        uint32_t sw = SWZ((uint32_t)row * 128 + (uint32_t)(c16 << 4));
        long long gofs = (long long)rg * HD + nDH + (c16 << 3);
        *(uint4*)(smem + S_RH + sw) = *(const uint4*)(g_rh + gofs);
        *(uint4*)(smem + S_RL + sw) = *(const uint4*)(g_rl + gofs);
    }
    __syncthreads();

    const int w0 = w * 16;
    const float e0a = g_eseg[(0 * NH + n) * QL + q0 + w0 + g];
    const float e1a = g_eseg[(1 * NH + n) * QL + q0 + w0 + g];
    const float e0b = g_eseg[(0 * NH + n) * QL + q0 + w0 + g + 8];
    const float e1b = g_eseg[(1 * NH + n) * QL + q0 + w0 + g + 8];
    float* stg = (float*)(smem + S_ST + w * 3200);

    for (int ch = 0; ch < 4; ch++) {
        float accA[4][4] = {};
        float accB[6][4] = {};
        const int s0 = ch * 32 - w0 + 112;
#pragma unroll
        for (int ks = 0; ks < 4; ks++) {
            uint32_t aqc[4], aqp[4];
            ldm4(aqc, sbase + S_QC, w0, ks * 16, lane);
            ldm4(aqp, sbase + S_QP, w0, ks * 16, lane);
            uint32_t kh[2][4], kl[2][4];
            ldm4(kh[0], sbase + S_KH, ch * 32, ks * 16, lane);
            ldm4(kh[1], sbase + S_KH, ch * 32 + 16, ks * 16, lane);
            ldm4(kl[0], sbase + S_KL, ch * 32, ks * 16, lane);
            ldm4(kl[1], sbase + S_KL, ch * 32 + 16, ks * 16, lane);
#pragma unroll
            for (int nt = 0; nt < 4; nt++) {
                const int p = nt >> 1, o = nt & 1;
                uint32_t fbh[2] = { kh[p][o], kh[p][2 + o] };
                uint32_t fbl[2] = { kl[p][o], kl[p][2 + o] };
                mma_f16(accA[nt], aqc, fbh);
                mma_f16(accA[nt], aqc, fbl);
            }
            uint32_t rh[3][4], rl[3][4];
#pragma unroll
            for (int p = 0; p < 3; p++) {
                ldm4(rh[p], sbase + S_RH, s0 + p * 16, ks * 16, lane);
                ldm4(rl[p], sbase + S_RL, s0 + p * 16, ks * 16, lane);
            }
#pragma unroll
            for (int nt = 0; nt < 6; nt++) {
                const int p = nt >> 1, o = nt & 1;
                uint32_t fbh[2] = { rh[p][o], rh[p][2 + o] };
                uint32_t fbl[2] = { rl[p][o], rl[p][2 + o] };
                mma_f16(accB[nt], aqp, fbh);
                mma_f16(accB[nt], aqp, fbl);
            }
        }
#pragma unroll
        for (int nt = 0; nt < 6; nt++) {
            int cc = nt * 8 + 2 * tig;
            stg[g * 50 + cc] = accB[nt][0];
            stg[g * 50 + cc + 1] = accB[nt][1];
            stg[(g + 8) * 50 + cc] = accB[nt][2];
            stg[(g + 8) * 50 + cc + 1] = accB[nt][3];
        }
        __syncwarp();
#pragma unroll
        for (int nt = 0; nt < 4; nt++) {
            const int jl = nt * 8 + 2 * tig;
            const float bd0 = stg[g * 50 + jl - g + 15], bd1 = stg[g * 50 + jl - g + 16];
            const float bd2 = stg[(g + 8) * 50 + jl - g + 7], bd3 = stg[(g + 8) * 50 + jl - g + 8];
            const int qa = q0 + w0 + g, cc = c0 + ch * 32 + jl;
            const size_t ma = (size_t)qa * CL + cc;
            const size_t mb = (size_t)(qa + 8) * CL + cc;
            float2 mka = *(const float2*)(mask + ma);
            float2 mkb = *(const float2*)(mask + mb);
            uchar2 sga = *(const uchar2*)(segmat + ma);
            uchar2 sgb = *(const uchar2*)(segmat + mb);
            float2 oa, ob;
            oa.x = (accA[nt][0] + bd0 + (sga.x ? e1a : e0a)) * 0.125f - 1e30f * mka.x;
            oa.y = (accA[nt][1] + bd1 + (sga.y ? e1a : e0a)) * 0.125f - 1e30f * mka.y;
            ob.x = (accA[nt][2] + bd2 + (sgb.x ? e1b : e0b)) * 0.125f - 1e30f * mkb.x;
            ob.y = (accA[nt][3] + bd3 + (sgb.y ? e1b : e0b)) * 0.125f - 1e30f * mkb.y;
            *(float2*)(g_scores + ((size_t)n * QL + qa) * CL + cc) = oa;
            *(float2*)(g_scores + ((size_t)n * QL + qa + 8) * CL + cc) = ob;
        }
        __syncwarp();
    }
}

// ---------------- fused online-softmax + probs@V (P fp16 x1, V hi/lo) -------
#define PV_V0 0
#define PV_V1 16384
#define PV_P 32768
#define PV_SC 49152
#define PV_SCW 68
#define PV_SMEM (49152 + 128 * PV_SCW * 4)

__global__ void __launch_bounds__(256) pv_fused_kernel()
{
    extern __shared__ char smem[];
    const uint32_t sbase = smem_u32(smem);
    const int tid = threadIdx.x, lane = tid & 31, w = tid >> 5;
    const int g = lane >> 2, tig = lane & 3;
    const int n = blockIdx.y, q0 = blockIdx.x * 128;
    const int w0 = w * 16;
    const int ri = lane >> 1, half = lane & 1;

    const half_t* vt_h = g_vth + (long long)(n * 64) * CL;
    const half_t* vt_l = g_vtl + (long long)(n * 64) * CL;
    float* sc = (float*)(smem + PV_SC);
    const float* sgbase = g_scores + ((size_t)n * QL + q0) * CL;

    auto loadV = [&](int s, int c0) {
        uint32_t sb = sbase + (s ? PV_V1 : PV_V0);
#pragma unroll
        for (int i = 0; i < 2; i++) {
            int u = tid + (i << 8);
            int row = u >> 3, c16 = u & 7;
            uint32_t sw = SWZ((uint32_t)row * 128 + (uint32_t)(c16 << 4));
            long long gofs = (long long)row * CL + c0 + (c16 << 3);
            cpasync16(sb + sw, vt_h + gofs);
            cpasync16(sb + 8192 + sw, vt_l + gofs);
        }
    };
    auto loadSC = [&](int cb) {
#pragma unroll
        for (int i = 0; i < 8; i++) {
            int u = tid + (i << 8);
            int row = u >> 4, c16 = u & 15;
            cpasync16(sbase + PV_SC + (uint32_t)row * (PV_SCW * 4) + (uint32_t)(c16 << 4),
                      sgbase + (size_t)row * CL + cb * 64 + c16 * 4);
        }
    };

    float m_run = -3.0e38f, l_run = 0.f;
    float accO[8][4] = {};

    loadSC(0); loadV(0, 0); CP_COMMIT();
    for (int cb = 0; cb < CL / 64; cb++) {
        CP_WAIT(0);
        __syncthreads();

        const float* srow = sc + (w0 + ri) * PV_SCW + half * 32;
        float4 sv[8];
#pragma unroll
        for (int j = 0; j < 8; j++) sv[j] = *(const float4*)(srow + j * 4);
        float cmax = -3.0e38f;
#pragma unroll
        for (int j = 0; j < 8; j++)
            cmax = fmaxf(cmax, fmaxf(fmaxf(sv[j].x, sv[j].y), fmaxf(sv[j].z, sv[j].w)));
        cmax = fmaxf(cmax, __shfl_xor_sync(0xffffffffu, cmax, 1));
        const float m_new = fmaxf(m_run, cmax);
        const float scale = __expf(m_run - m_new);
        m_run = m_new;
        float csum = 0.f;
#pragma unroll
        for (int j = 0; j < 8; j++) {
            float p0 = __expf(sv[j].x - m_new), p1 = __expf(sv[j].y - m_new);
            float p2 = __expf(sv[j].z - m_new), p3 = __expf(sv[j].w - m_new);
            csum += (p0 + p1) + (p2 + p3);
            const int c = half * 32 + j * 4;
            const uint32_t sw = SWZ((uint32_t)(w0 + ri) * 128 + (uint32_t)c * 2);
            *(half2_t*)(smem + PV_P + sw) = __floats2half2_rn(p0, p1);
            *(half2_t*)(smem + PV_P + sw + 4) = __floats2half2_rn(p2, p3);
        }
        csum += __shfl_xor_sync(0xffffffffu, csum, 1);
        l_run = l_run * scale + csum;
        const float sA = __shfl_sync(0xffffffffu, scale, 2 * g);
        const float sB = __shfl_sync(0xffffffffu, scale, 2 * g + 16);
#pragma unroll
        for (int t = 0; t < 8; t++) {
            accO[t][0] *= sA; accO[t][1] *= sA;
            accO[t][2] *= sB; accO[t][3] *= sB;
        }
        __syncthreads();

        if (cb + 1 < CL / 64) {
            loadSC(cb + 1);
            loadV((cb + 1) & 1, (cb + 1) * 64);
            CP_COMMIT();
        }

        const uint32_t vb = sbase + ((cb & 1) ? PV_V1 : PV_V0);
#pragma unroll
        for (int ks = 0; ks < 4; ks++) {
            uint32_t aP[4];
            ldm4(aP, sbase + PV_P, w0, ks * 16, lane);
            uint32_t bH[4][4], bL[4][4];
#pragma unroll
            for (int p = 0; p < 4; p++) {
                ldm4(bH[p], vb, p * 16, ks * 16, lane);
                ldm4(bL[p], vb + 8192, p * 16, ks * 16, lane);
            }
#pragma unroll
            for (int t = 0; t < 8; t++) {
                const int p = t >> 1, o = t & 1;
                uint32_t fbh[2] = { bH[p][o], bH[p][2 + o] };
                uint32_t fbl[2] = { bL[p][o], bL[p][2 + o] };
                mma_f16(accO[t], aP, fbh);
                mma_f16(accO[t], aP, fbl);
            }
        }
    }
    const float li = 1.0f / l_run;
    const float lA = __shfl_sync(0xffffffffu, li, 2 * g);
    const float lB = __shfl_sync(0xffffffffu, li, 2 * g + 16);
#pragma unroll
    for (int t = 0; t < 8; t++) {
        const int dloc = (t >> 1) * 16 + (t & 1) * 8 + 2 * tig;
        const long long col = (long long)n * 64 + dloc;
        const long long offA = (long long)(q0 + w0 + g) * HD + col;
        const long long offB = (long long)(q0 + w0 + g + 8) * HD + col;
        wone2(g_ath, offA, accO[t][0] * lA, accO[t][1] * lA);
        wone2(g_ath, offB, accO[t][2] * lB, accO[t][3] * lB);
    }
}

// ---------------- eseg ----------------
__global__ void __launch_bounds__(256) eseg_kernel(
    const float* __restrict__ cb, const float* __restrict__ sb, const float* __restrict__ seg)
{
    int idx = blockIdx.x * 256 + threadIdx.x;
    if (idx >= 2 * NH * QL) return;
    int s = idx / (NH * QL), n = (idx / QL) % NH, qi = idx % QL;
    const half_t* qh = g_qch + (long long)qi * HD + n * DH;
    const float* cbr = cb + n * DH;
    const float* sbr = sb + n * DH;
    const float* sg = seg + s * (NH * DH) + n * DH;
    float acc = 0.f;
#pragma unroll
    for (int d = 0; d < DH; d++) {
        float q = __half2float(qh[d]) - cbr[d] + sbr[d];
        acc += q * sg[d];
    }
    g_eseg[idx] = acc;
}

// ---------------- residual + LN ----------------
__global__ void __launch_bounds__(256) ln_kernel(
    const float* __restrict__ x, const float* __restrict__ res,
    const float* __restrict__ g, const float* __restrict__ b,
    float* __restrict__ out, half_t* __restrict__ oh)
{
    const int row = blockIdx.x;
    __shared__ float buf[HD];
    __shared__ float red[8];
    __shared__ float s_mean, s_rstd;
    const int tid = threadIdx.x;
    float lsum = 0.f;
    for (int i = tid; i < HD; i += 256) {
        float v = x[(long long)row * HD + i] + res[(long long)row * HD + i];
        buf[i] = v; lsum += v;
    }
    lsum = warpSum(lsum);
    if ((tid & 31) == 0) red[tid >> 5] = lsum;
    __syncthreads();
    if (tid == 0) {
        float s = 0.f;
#pragma unroll
        for (int i = 0; i < 8; i++) s += red[i];
        s_mean = s * (1.0f / HD);
    }
    __syncthreads();
    const float m = s_mean;
    float lv = 0.f;
    for (int i = tid; i < HD; i += 256) { float d = buf[i] - m; lv += d * d; }
    lv = warpSum(lv);
    __syncthreads();
    if ((tid & 31) == 0) red[tid >> 5] = lv;
    __syncthreads();
    if (tid == 0) {
        float s = 0.f;
#pragma unroll
        for (int i = 0; i < 8; i++) s += red[i];
        s_rstd = rsqrtf(s * (1.0f / HD) + 1e-12f);
    }
    __syncthreads();
    const float rs = s_rstd;
    for (int i = tid; i < HD; i += 256) {
        float o = (buf[i] - m) * rs * g[i] + b[i];
        if (out) out[(long long)row * HD + i] = o;
        if (oh) oh[(long long)row * HD + i] = __float2half_rn(o);
    }
}

// ---------------- launch ----------------
extern "C" void kernel_launch(void* const* d_in, const int* in_sizes, int n_in,
                              void* d_out, int out_size)
{
    const float* cs = (const float*)d_in[0];
    const float* mask = (const float*)d_in[1];
    const float* ctx = (const float*)d_in[2];
    const float* pos = (const float*)d_in[3];
    const float* cb = (const float*)d_in[4];
    const float* pb = (const float*)d_in[5];
    const float* seg = (const float*)d_in[6];
    const unsigned char* segm = (const unsigned char*)d_in[7];
    const float* sbb = (const float*)d_in[8];
    const float* Wq = (const float*)d_in[9];
    const float* Wk = (const float*)d_in[10];
    const float* Wv = (const float*)d_in[11];
    const float* Wr = (const float*)d_in[12];
    const float* Wo = (const float*)d_in[13];
    const float* g1 = (const float*)d_in[14];
    const float* be1 = (const float*)d_in[15];
    const float* W1 = (const float*)d_in[16];
    const float* bf1 = (const float*)d_in[17];
    const float* W2 = (const float*)d_in[18];
    const float* bf2 = (const float*)d_in[19];
    const float* g2 = (const float*)d_in[20];
    const float* be2 = (const float*)d_in[21];
    float* out = (float*)d_out;

#define SYM(T, name, sym) T* name; cudaGetSymbolAddress((void**)&name, sym)
    SYM(float, pv, g_v); SYM(float, pao, g_attnout);
    SYM(float, pfi, g_ffnin); SYM(float, pfo, g_ffnout);
    SYM(half_t, csh, g_csh); SYM(half_t, ctxh, g_ctxh); SYM(half_t, posh, g_posh);
    SYM(half_t, qch, g_qch); SYM(half_t, qph, g_qph);
    SYM(half_t, kh, g_kh); SYM(half_t, kl, g_kl);
    SYM(half_t, rh, g_rh); SYM(half_t, rl, g_rl);
    SYM(half_t, ath, g_ath); SYM(half_t, fih, g_fih); SYM(half_t, fhh, g_fhh);
    SYM(half_t, wqh, g_wqh); SYM(half_t, wql, g_wql);
    SYM(half_t, wkh, g_wkh); SYM(half_t, wkl, g_wkl);
    SYM(half_t, wvh, g_wvh); SYM(half_t, wvl, g_wvl);
    SYM(half_t, wrh, g_wrh); SYM(half_t, wrl, g_wrl);
    SYM(half_t, woh, g_woh); SYM(half_t, wol, g_wol);
    SYM(half_t, w1h, g_w1h); SYM(half_t, w1l, g_w1l);
    SYM(half_t, w2h, g_w2h); SYM(half_t, w2l, g_w2l);
    SYM(half_t, vth, g_vth); SYM(half_t, vtl, g_vtl);
#undef SYM

    cudaFuncSetAttribute(hmma_gemm_kernel, cudaFuncAttributeMaxDynamicSharedMemorySize, GM_SMEM);
    cudaFuncSetAttribute(score_hmma_kernel, cudaFuncAttributeMaxDynamicSharedMemorySize, S_SMEM);
    cudaFuncSetAttribute(pv_fused_kernel, cudaFuncAttributeMaxDynamicSharedMemorySize, PV_SMEM);

    dim3 blk(256);
    cvt4_kernel<<<(QL * HD / 4) / 256, blk>>>(cs, csh, QL * HD / 4);
    cvt4_kernel<<<(CL * HD / 4) / 256, blk>>>(ctx, ctxh, CL * HD / 4);
    cvt4_kernel<<<(RL * HD / 4) / 256, blk>>>(pos, posh, RL * HD / 4);
    convT_kernel<<<dim3(HD / 32, HD / 32), blk>>>(Wq, wqh, wql, HD, HD);
    convT_kernel<<<dim3(HD / 32, HD / 32), blk>>>(Wk, wkh, wkl, HD, HD);
    convT_kernel<<<dim3(HD / 32, HD / 32), blk>>>(Wv, wvh, wvl, HD, HD);
    convT_kernel<<<dim3(HD / 32, HD / 32), blk>>>(Wr, wrh, wrl, HD, HD);
    conv_kernel<<<(HD * HD) / 256, blk>>>(Wo, woh, wol, HD * HD);
    convT_kernel<<<dim3(FF / 32, HD / 32), blk>>>(W1, w1h, w1l, HD, FF);
    convT_kernel<<<dim3(HD / 32, FF / 32), blk>>>(W2, w2h, w2l, FF, HD);

    // projections
    hmma_gemm_kernel<<<dim3(HD / 64, QL / 128), blk, GM_SMEM>>>(
        csh, wqh, wql, nullptr, nullptr, qch, nullptr, cb, 0, qph, pb, HD, HD, HD, HD);
    hmma_gemm_kernel<<<dim3(HD / 64, CL / 128), blk, GM_SMEM>>>(
        ctxh, wkh, wkl, nullptr, nullptr, kh, kl, nullptr, 0, nullptr, nullptr, HD, HD, HD, HD);
    hmma_gemm_kernel<<<dim3(HD / 64, CL / 128), blk, GM_SMEM>>>(
        ctxh, wvh, wvl, pv, nullptr, nullptr, nullptr, nullptr, 0, nullptr, nullptr, HD, HD, HD, HD);
    hmma_gemm_kernel<<<dim3(HD / 64, RL / 128), blk, GM_SMEM>>>(
        posh, wrh, wrl, nullptr, nullptr, rh, rl, nullptr, 0, nullptr, nullptr, HD, HD, HD, HD);

    convT_kernel<<<dim3(HD / 32, CL / 32), blk>>>(pv, vth, vtl, CL, HD);
    eseg_kernel<<<(2 * NH * QL) / 256, blk>>>(cb, sbb, seg);

    score_hmma_kernel<<<dim3(CL / 128, QL / 128, NH), blk, S_SMEM>>>(mask, segm);
    pv_fused_kernel<<<dim3(QL / 128, NH), blk, PV_SMEM>>>();

    hmma_gemm_kernel<<<dim3(HD / 64, QL / 128), blk, GM_SMEM>>>(
        ath, woh, wol, pao, nullptr, nullptr, nullptr, nullptr, 0, nullptr, nullptr, HD, HD, HD, HD);

    ln_kernel<<<QL, blk>>>(pao, cs, g1, be1, pfi, fih);

    hmma_gemm_kernel<<<dim3(FF / 64, QL / 128), blk, GM_SMEM>>>(
        fih, w1h, w1l, nullptr, nullptr, fhh, nullptr, bf1, 1, nullptr, nullptr, HD, HD, HD, FF);
    hmma_gemm_kernel<<<dim3(HD / 64, QL / 128), blk, GM_SMEM>>>(
        fhh, w2h, w2l, pfo, bf2, nullptr, nullptr, nullptr, 0, nullptr, nullptr, FF, FF, FF, HD);

    ln_kernel<<<QL, blk>>>(pfo, pfi, g2, be2, out, nullptr);
}

// round 10
// speedup vs baseline: 1.9551x; 1.3622x over previous
#include <cuda_runtime.h>
#include <cuda_fp16.h>
#include <math.h>
#include <stdint.h>

#define QL 2048
#define CL 2048
#define HD 1024
#define NH 16
#define DH 64
#define FF 4096
#define RL 4096
typedef __half half_t;
typedef __half2 half2_t;

// ---------------- scratch ----------------
__device__ float g_v[CL * HD];
__device__ float g_scores[(size_t)NH * QL * CL];
__device__ float g_eseg[2 * NH * QL];
__device__ float g_attnout[QL * HD];
__device__ float g_ffnin[QL * HD];
__device__ float g_ffnout[QL * HD];
// fp16 buffers (single precision level, no hi/lo)
__device__ half_t g_csh[QL * HD];
__device__ half_t g_ctxh[CL * HD];
__device__ half_t g_posh[RL * HD];
__device__ half_t g_qch[QL * HD];
__device__ half_t g_qph[QL * HD];
__device__ half_t g_ath[QL * HD];
__device__ half_t g_fih[QL * HD];
__device__ half_t g_fhh[(size_t)QL * FF];
__device__ half_t g_kh[CL * HD];
__device__ half_t g_rh[RL * HD];
__device__ half_t g_vth[HD * CL];
__device__ half_t g_wqh[HD * HD];
__device__ half_t g_wkh[HD * HD];
__device__ half_t g_wvh[HD * HD];
__device__ half_t g_wrh[HD * HD];
__device__ half_t g_woh[HD * HD];
__device__ half_t g_w1h[(size_t)FF * HD];
__device__ half_t g_w2h[(size_t)FF * HD];

#define SWZ(o) ((o) ^ (((o) >> 3) & 0x70))

__device__ __forceinline__ uint32_t smem_u32(const void* p) {
    uint32_t a;
    asm("{ .reg .u64 t; cvta.to.shared.u64 t, %1; cvt.u32.u64 %0, t; }" : "=r"(a) : "l"(p));
    return a;
}
__device__ __forceinline__ void cpasync16(uint32_t s, const void* g) {
    asm volatile("cp.async.cg.shared.global [%0], [%1], 16;" :: "r"(s), "l"(g));
}
#define CP_COMMIT() asm volatile("cp.async.commit_group;")
#define CP_WAIT(n) asm volatile("cp.async.wait_group %0;" :: "n"(n))

__device__ __forceinline__ void wone2(half_t* o, long long off, float x, float y) {
    *(half2_t*)(o + off) = __floats2half2_rn(x, y);
}
__device__ __forceinline__ float warpSum(float v) {
#pragma unroll
    for (int o = 16; o; o >>= 1) v += __shfl_xor_sync(0xffffffffu, v, o);
    return v;
}
__device__ __forceinline__ void mma_f16(float* d, const uint32_t* a, const uint32_t* b) {
    asm volatile(
        "mma.sync.aligned.m16n8k16.row.col.f32.f16.f16.f32 "
        "{%0,%1,%2,%3}, {%4,%5,%6,%7}, {%8,%9}, {%0,%1,%2,%3};"
        : "+f"(d[0]), "+f"(d[1]), "+f"(d[2]), "+f"(d[3])
        : "r"(a[0]), "r"(a[1]), "r"(a[2]), "r"(a[3]), "r"(b[0]), "r"(b[1]));
}
__device__ __forceinline__ void ldm4(uint32_t* r, uint32_t base, int row0, int k0, int lane) {
    int row = row0 + (lane & 15);
    int kc = k0 + ((lane >> 4) << 3);
    uint32_t addr = base + SWZ((uint32_t)row * 128 + (uint32_t)kc * 2);
    asm volatile("ldmatrix.sync.aligned.m8n8.x4.shared.b16 {%0,%1,%2,%3}, [%4];"
                 : "=r"(r[0]), "=r"(r[1]), "=r"(r[2]), "=r"(r[3]) : "r"(addr));
}

// ---------------- converters ----------------
__global__ void __launch_bounds__(256) cvt4_kernel(
    const float* __restrict__ in, half_t* __restrict__ o, int n4)
{
    int i = blockIdx.x * 256 + threadIdx.x;
    if (i >= n4) return;
    float4 v = *(const float4*)(in + i * 4);
    wone2(o, (long long)i * 4, v.x, v.y);
    wone2(o, (long long)i * 4 + 2, v.z, v.w);
}
__global__ void __launch_bounds__(256) convT_kernel(
    const float* __restrict__ in, half_t* __restrict__ o, int R, int Cc)
{
    __shared__ float t[32][33];
    const int tx = threadIdx.x & 31, ty8 = threadIdx.x >> 5;
    const int r0 = blockIdx.y * 32, c0 = blockIdx.x * 32;
    for (int j = ty8; j < 32; j += 8) t[j][tx] = in[(long long)(r0 + j) * Cc + c0 + tx];
    __syncthreads();
    for (int j = ty8; j < 32; j += 8)
        o[(long long)(c0 + j) * R + r0 + tx] = __float2half_rn(t[tx][j]);
}
__global__ void __launch_bounds__(256) conv_kernel(
    const float* __restrict__ in, half_t* __restrict__ o, int n)
{
    int i = blockIdx.x * 256 + threadIdx.x;
    if (i < n) o[i] = __float2half_rn(in[i]);
}

// ---------------- HMMA GEMM: C[M,N]=A[M,K]@B[N,K]^T, fp16 single ------------
// BM=128, BN=64, BK=64, 256 threads (8 warps 4m x 2n, warp tile 32x32), 2-stage
#define ST_A 0
#define ST_B 16384
#define ST_SZ 24576
#define GM_SMEM (2 * ST_SZ)

__global__ void __launch_bounds__(256) hmma_gemm_kernel(
    const half_t* __restrict__ A, const half_t* __restrict__ B,
    float* __restrict__ C, const float* __restrict__ biasC,
    half_t* __restrict__ O1h, const float* __restrict__ bias1, int relu1,
    half_t* __restrict__ O2h, const float* __restrict__ bias2,
    int K, int lda, int ldb, int ldc)
{
    extern __shared__ char smem[];
    const uint32_t sbase = smem_u32(smem);
    const int tid = threadIdx.x, lane = tid & 31, w = tid >> 5;
    const int g = lane >> 2, tig = lane & 3;
    const int m0 = blockIdx.y * 128, n0 = blockIdx.x * 64;
    const int wm = (w >> 1) * 32, wn = (w & 1) * 32;

    auto load_stage = [&](int s, int k0) {
        uint32_t sb = sbase + s * ST_SZ;
#pragma unroll
        for (int i = 0; i < 4; i++) {
            int u = tid + (i << 8);
            int row = u >> 3, c16 = u & 7;
            uint32_t sw = SWZ((uint32_t)row * 128 + (uint32_t)(c16 << 4));
            cpasync16(sb + ST_A + sw, A + (long long)(m0 + row) * lda + k0 + (c16 << 3));
        }
#pragma unroll
        for (int i = 0; i < 2; i++) {
            int u = tid + (i << 8);
            int row = u >> 3, c16 = u & 7;
            uint32_t sw = SWZ((uint32_t)row * 128 + (uint32_t)(c16 << 4));
            cpasync16(sb + ST_B + sw, B + (long long)(n0 + row) * ldb + k0 + (c16 << 3));
        }
    };

    float acc[2][4][4] = {};
    const int NC = K >> 6;
    load_stage(0, 0);
    CP_COMMIT();
    for (int c = 0; c < NC; c++) {
        if (c + 1 < NC) { load_stage((c + 1) & 1, (c + 1) << 6); CP_COMMIT(); CP_WAIT(1); }
        else CP_WAIT(0);
        __syncthreads();
        const uint32_t sb = sbase + (c & 1) * ST_SZ;
#pragma unroll
        for (int ks = 0; ks < 4; ks++) {
            uint32_t ah[2][4], bh[2][4];
            ldm4(ah[0], sb + ST_A, wm, ks * 16, lane);
            ldm4(ah[1], sb + ST_A, wm + 16, ks * 16, lane);
            ldm4(bh[0], sb + ST_B, wn, ks * 16, lane);
            ldm4(bh[1], sb + ST_B, wn + 16, ks * 16, lane);
#pragma unroll
            for (int mt = 0; mt < 2; mt++)
#pragma unroll
                for (int nt = 0; nt < 4; nt++) {
                    const int p = nt >> 1, o = nt & 1;
                    uint32_t fb[2] = { bh[p][o], bh[p][2 + o] };
                    mma_f16(acc[mt][nt], ah[mt], fb);
                }
        }
        __syncthreads();
    }

#pragma unroll
    for (int mt = 0; mt < 2; mt++)
#pragma unroll
        for (int nt = 0; nt < 4; nt++) {
#pragma unroll
            for (int h = 0; h < 2; h++) {
                const int row = m0 + wm + mt * 16 + g + h * 8;
                const int col = n0 + wn + nt * 8 + 2 * tig;
                float x = acc[mt][nt][h * 2], y = acc[mt][nt][h * 2 + 1];
                const long long off = (long long)row * ldc + col;
                if (C) {
                    float b0 = biasC ? biasC[col] : 0.f, b1 = biasC ? biasC[col + 1] : 0.f;
                    float2 o = { x + b0, y + b1 };
                    *(float2*)(C + off) = o;
                }
                if (O1h) {
                    float b0 = bias1 ? bias1[col] : 0.f, b1 = bias1 ? bias1[col + 1] : 0.f;
                    float vx = x + b0, vy = y + b1;
                    if (relu1) { vx = fmaxf(vx, 0.f); vy = fmaxf(vy, 0.f); }
                    wone2(O1h, off, vx, vy);
                }
                if (O2h) {
                    float b0 = bias2 ? bias2[col] : 0.f, b1 = bias2 ? bias2[col + 1] : 0.f;
                    wone2(O2h, off, x + b0, y + b1);
                }
            }
        }
}

// ---------------- HMMA score kernel (fp16 single) ----------------
#define S_QC 0
#define S_QP 16384
#define S_K  32768
#define S_R  49152
#define S_ST 81920
#define S_SMEM (81920 + 8 * 3200)

__global__ void __launch_bounds__(256) score_hmma_kernel(
    const float* __restrict__ mask, const unsigned char* __restrict__ segmat)
{
    extern __shared__ char smem[];
    const uint32_t sbase = smem_u32(smem);
    const int tid = threadIdx.x, lane = tid & 31, w = tid >> 5;
    const int g = lane >> 2, tig = lane & 3;
    const int n = blockIdx.z, q0 = blockIdx.y * 128, c0 = blockIdx.x * 128;
    const int nDH = n * DH;

#pragma unroll
    for (int i = 0; i < 4; i++) {
        int u = tid + (i << 8);
        int row = u >> 3, c16 = u & 7;
        uint32_t sw = SWZ((uint32_t)row * 128 + (uint32_t)(c16 << 4));
        long long gq = (long long)(q0 + row) * HD + nDH + (c16 << 3);
        long long gk = (long long)(c0 + row) * HD + nDH + (c16 << 3);
        *(uint4*)(smem + S_QC + sw) = *(const uint4*)(g_qch + gq);
        *(uint4*)(smem + S_QP + sw) = *(const uint4*)(g_qph + gq);
        *(uint4*)(smem + S_K + sw) = *(const uint4*)(g_kh + gk);
    }
    const int rstart = QL + c0 - q0 - 127;
#pragma unroll
    for (int i = 0; i < 8; i++) {
        int u = tid + (i << 8);
        int row = u >> 3, c16 = u & 7;
        int rg = rstart + row; if (rg > RL - 1) rg = RL - 1;
        uint32_t sw = SWZ((uint32_t)row * 128 + (uint32_t)(c16 << 4));
        *(uint4*)(smem + S_R + sw) = *(const uint4*)(g_rh + (long long)rg * HD + nDH + (c16 << 3));
    }
    __syncthreads();

    const int w0 = w * 16;
    const float e0a = g_eseg[(0 * NH + n) * QL + q0 + w0 + g];
    const float e1a = g_eseg[(1 * NH + n) * QL + q0 + w0 + g];
    const float e0b = g_eseg[(0 * NH + n) * QL + q0 + w0 + g + 8];
    const float e1b = g_eseg[(1 * NH + n) * QL + q0 + w0 + g + 8];
    float* stg = (float*)(smem + S_ST + w * 3200);

    for (int ch = 0; ch < 4; ch++) {
        float accA[4][4] = {};
        float accB[6][4] = {};
        const int s0 = ch * 32 - w0 + 112;
#pragma unroll
        for (int ks = 0; ks < 4; ks++) {
            uint32_t aqc[4], aqp[4];
            ldm4(aqc, sbase + S_QC, w0, ks * 16, lane);
            ldm4(aqp, sbase + S_QP, w0, ks * 16, lane);
            uint32_t kh[2][4];
            ldm4(kh[0], sbase + S_K, ch * 32, ks * 16, lane);
            ldm4(kh[1], sbase + S_K, ch * 32 + 16, ks * 16, lane);
#pragma unroll
            for (int nt = 0; nt < 4; nt++) {
                const int p = nt >> 1, o = nt & 1;
                uint32_t fb[2] = { kh[p][o], kh[p][2 + o] };
                mma_f16(accA[nt], aqc, fb);
            }
            uint32_t rh[3][4];
#pragma unroll
            for (int p = 0; p < 3; p++)
                ldm4(rh[p], sbase + S_R, s0 + p * 16, ks * 16, lane);
#pragma unroll
            for (int nt = 0; nt < 6; nt++) {
                const int p = nt >> 1, o = nt & 1;
                uint32_t fb[2] = { rh[p][o], rh[p][2 + o] };
                mma_f16(accB[nt], aqp, fb);
            }
        }
#pragma unroll
        for (int nt = 0; nt < 6; nt++) {
            int cc = nt * 8 + 2 * tig;
            stg[g * 50 + cc] = accB[nt][0];
            stg[g * 50 + cc + 1] = accB[nt][1];
            stg[(g + 8) * 50 + cc] = accB[nt][2];
            stg[(g + 8) * 50 + cc + 1] = accB[nt][3];
        }
        __syncwarp();
#pragma unroll
        for (int nt = 0; nt < 4; nt++) {
            const int jl = nt * 8 + 2 * tig;
            const float bd0 = stg[g * 50 + jl - g + 15], bd1 = stg[g * 50 + jl - g + 16];
            const float bd2 = stg[(g + 8) * 50 + jl - g + 7], bd3 = stg[(g + 8) * 50 + jl - g + 8];
            const int qa = q0 + w0 + g, cc = c0 + ch * 32 + jl;
            const size_t ma = (size_t)qa * CL + cc;
            const size_t mb = (size_t)(qa + 8) * CL + cc;
            float2 mka = *(const float2*)(mask + ma);
            float2 mkb = *(const float2*)(mask + mb);
            uchar2 sga = *(const uchar2*)(segmat + ma);
            uchar2 sgb = *(const uchar2*)(segmat + mb);
            float2 oa, ob;
            oa.x = (accA[nt][0] + bd0 + (sga.x ? e1a : e0a)) * 0.125f - 1e30f * mka.x;
            oa.y = (accA[nt][1] + bd1 + (sga.y ? e1a : e0a)) * 0.125f - 1e30f * mka.y;
            ob.x = (accA[nt][2] + bd2 + (sgb.x ? e1b : e0b)) * 0.125f - 1e30f * mkb.x;
            ob.y = (accA[nt][3] + bd3 + (sgb.y ? e1b : e0b)) * 0.125f - 1e30f * mkb.y;
            *(float2*)(g_scores + ((size_t)n * QL + qa) * CL + cc) = oa;
            *(float2*)(g_scores + ((size_t)n * QL + qa + 8) * CL + cc) = ob;
        }
        __syncwarp();
    }
}

// ---------------- fused online-softmax + probs@V (fp16 single) --------------
#define PV_V0 0
#define PV_V1 8192
#define PV_P  16384
#define PV_SC 32768
#define PV_SCW 68
#define PV_SMEM (32768 + 128 * PV_SCW * 4)

__global__ void __launch_bounds__(256) pv_fused_kernel()
{
    extern __shared__ char smem[];
    const uint32_t sbase = smem_u32(smem);
    const int tid = threadIdx.x, lane = tid & 31, w = tid >> 5;
    const int g = lane >> 2, tig = lane & 3;
    const int n = blockIdx.y, q0 = blockIdx.x * 128;
    const int w0 = w * 16;
    const int ri = lane >> 1, half = lane & 1;

    const half_t* vt = g_vth + (long long)(n * 64) * CL;
    float* sc = (float*)(smem + PV_SC);
    const float* sgbase = g_scores + ((size_t)n * QL + q0) * CL;

    auto loadV = [&](int s, int c0) {
        uint32_t sb = sbase + (s ? PV_V1 : PV_V0);
        // 64 rows x 64 cols fp16 = 512 16B units, 2 per thread
#pragma unroll
        for (int i = 0; i < 2; i++) {
            int u = tid + (i << 8);
            int row = u >> 3, c16 = u & 7;
            uint32_t sw = SWZ((uint32_t)row * 128 + (uint32_t)(c16 << 4));
            cpasync16(sb + sw, vt + (long long)row * CL + c0 + (c16 << 3));
        }
    };
    auto loadSC = [&](int cb) {
#pragma unroll
        for (int i = 0; i < 8; i++) {
            int u = tid + (i << 8);
            int row = u >> 4, c16 = u & 15;
            cpasync16(sbase + PV_SC + (uint32_t)row * (PV_SCW * 4) + (uint32_t)(c16 << 4),
                      sgbase + (size_t)row * CL + cb * 64 + c16 * 4);
        }
    };

    float m_run = -3.0e38f, l_run = 0.f;
    float accO[8][4] = {};

    loadSC(0); loadV(0, 0); CP_COMMIT();
    for (int cb = 0; cb < CL / 64; cb++) {
        CP_WAIT(0);
        __syncthreads();

        const float* srow = sc + (w0 + ri) * PV_SCW + half * 32;
        float4 sv[8];
#pragma unroll
        for (int j = 0; j < 8; j++) sv[j] = *(const float4*)(srow + j * 4);
        float cmax = -3.0e38f;
#pragma unroll
        for (int j = 0; j < 8; j++)
            cmax = fmaxf(cmax, fmaxf(fmaxf(sv[j].x, sv[j].y), fmaxf(sv[j].z, sv[j].w)));
        cmax = fmaxf(cmax, __shfl_xor_sync(0xffffffffu, cmax, 1));
        const float m_new = fmaxf(m_run, cmax);
        const float scale = __expf(m_run - m_new);
        m_run = m_new;
        float csum = 0.f;
#pragma unroll
        for (int j = 0; j < 8; j++) {
            float p0 = __expf(sv[j].x - m_new), p1 = __expf(sv[j].y - m_new);
            float p2 = __expf(sv[j].z - m_new), p3 = __expf(sv[j].w - m_new);
            csum += (p0 + p1) + (p2 + p3);
            const int c = half * 32 + j * 4;
            const uint32_t sw = SWZ((uint32_t)(w0 + ri) * 128 + (uint32_t)c * 2);
            *(half2_t*)(smem + PV_P + sw) = __floats2half2_rn(p0, p1);
            *(half2_t*)(smem + PV_P + sw + 4) = __floats2half2_rn(p2, p3);
        }
        csum += __shfl_xor_sync(0xffffffffu, csum, 1);
        l_run = l_run * scale + csum;
        const float sA = __shfl_sync(0xffffffffu, scale, 2 * g);
        const float sB = __shfl_sync(0xffffffffu, scale, 2 * g + 16);
#pragma unroll
        for (int t = 0; t < 8; t++) {
            accO[t][0] *= sA; accO[t][1] *= sA;
            accO[t][2] *= sB; accO[t][3] *= sB;
        }
        __syncthreads();

        if (cb + 1 < CL / 64) {
            loadSC(cb + 1);
            loadV((cb + 1) & 1, (cb + 1) * 64);
            CP_COMMIT();
        }

        const uint32_t vb = sbase + ((cb & 1) ? PV_V1 : PV_V0);
#pragma unroll
        for (int ks = 0; ks < 4; ks++) {
            uint32_t aP[4];
            ldm4(aP, sbase + PV_P, w0, ks * 16, lane);
            uint32_t bH[4][4];
#pragma unroll
            for (int p = 0; p < 4; p++)
                ldm4(bH[p], vb, p * 16, ks * 16, lane);
#pragma unroll
            for (int t = 0; t < 8; t++) {
                const int p = t >> 1, o = t & 1;
                uint32_t fb[2] = { bH[p][o], bH[p][2 + o] };
                mma_f16(accO[t], aP, fb);
            }
        }
    }
    const float li = 1.0f / l_run;
    const float lA = __shfl_sync(0xffffffffu, li, 2 * g);
    const float lB = __shfl_sync(0xffffffffu, li, 2 * g + 16);
#pragma unroll
    for (int t = 0; t < 8; t++) {
        const int dloc = (t >> 1) * 16 + (t & 1) * 8 + 2 * tig;
        const long long col = (long long)n * 64 + dloc;
        const long long offA = (long long)(q0 + w0 + g) * HD + col;
        const long long offB = (long long)(q0 + w0 + g + 8) * HD + col;
        wone2(g_ath, offA, accO[t][0] * lA, accO[t][1] * lA);
        wone2(g_ath, offB, accO[t][2] * lB, accO[t][3] * lB);
    }
}

// ---------------- eseg ----------------
__global__ void __launch_bounds__(256) eseg_kernel(
    const float* __restrict__ cb, const float* __restrict__ sb, const float* __restrict__ seg)
{
    int idx = blockIdx.x * 256 + threadIdx.x;
    if (idx >= 2 * NH * QL) return;
    int s = idx / (NH * QL), n = (idx / QL) % NH, qi = idx % QL;
    const half_t* qh = g_qch + (long long)qi * HD + n * DH;
    const float* cbr = cb + n * DH;
    const float* sbr = sb + n * DH;
    const float* sg = seg + s * (NH * DH) + n * DH;
    float acc = 0.f;
#pragma unroll
    for (int d = 0; d < DH; d++) {
        float q = __half2float(qh[d]) - cbr[d] + sbr[d];
        acc += q * sg[d];
    }
    g_eseg[idx] = acc;
}

// ---------------- residual + LN ----------------
__global__ void __launch_bounds__(256) ln_kernel(
    const float* __restrict__ x, const float* __restrict__ res,
    const float* __restrict__ g, const float* __restrict__ b,
    float* __restrict__ out, half_t* __restrict__ oh)
{
    const int row = blockIdx.x;
    __shared__ float buf[HD];
    __shared__ float red[8];
    __shared__ float s_mean, s_rstd;
    const int tid = threadIdx.x;
    float lsum = 0.f;
    for (int i = tid; i < HD; i += 256) {
        float v = x[(long long)row * HD + i] + res[(long long)row * HD + i];
        buf[i] = v; lsum += v;
    }
    lsum = warpSum(lsum);
    if ((tid & 31) == 0) red[tid >> 5] = lsum;
    __syncthreads();
    if (tid == 0) {
        float s = 0.f;
#pragma unroll
        for (int i = 0; i < 8; i++) s += red[i];
        s_mean = s * (1.0f / HD);
    }
    __syncthreads();
    const float m = s_mean;
    float lv = 0.f;
    for (int i = tid; i < HD; i += 256) { float d = buf[i] - m; lv += d * d; }
    lv = warpSum(lv);
    __syncthreads();
    if ((tid & 31) == 0) red[tid >> 5] = lv;
    __syncthreads();
    if (tid == 0) {
        float s = 0.f;
#pragma unroll
        for (int i = 0; i < 8; i++) s += red[i];
        s_rstd = rsqrtf(s * (1.0f / HD) + 1e-12f);
    }
    __syncthreads();
    const float rs = s_rstd;
    for (int i = tid; i < HD; i += 256) {
        float o = (buf[i] - m) * rs * g[i] + b[i];
        if (out) out[(long long)row * HD + i] = o;
        if (oh) oh[(long long)row * HD + i] = __float2half_rn(o);
    }
}

// ---------------- launch ----------------
extern "C" void kernel_launch(void* const* d_in, const int* in_sizes, int n_in,
                              void* d_out, int out_size)
{
    const float* cs = (const float*)d_in[0];
    const float* mask = (const float*)d_in[1];
    const float* ctx = (const float*)d_in[2];
    const float* pos = (const float*)d_in[3];
    const float* cb = (const float*)d_in[4];
    const float* pb = (const float*)d_in[5];
    const float* seg = (const float*)d_in[6];
    const unsigned char* segm = (const unsigned char*)d_in[7];
    const float* sbb = (const float*)d_in[8];
    const float* Wq = (const float*)d_in[9];
    const float* Wk = (const float*)d_in[10];
    const float* Wv = (const float*)d_in[11];
    const float* Wr = (const float*)d_in[12];
    const float* Wo = (const float*)d_in[13];
    const float* g1 = (const float*)d_in[14];
    const float* be1 = (const float*)d_in[15];
    const float* W1 = (const float*)d_in[16];
    const float* bf1 = (const float*)d_in[17];
    const float* W2 = (const float*)d_in[18];
    const float* bf2 = (const float*)d_in[19];
    const float* g2 = (const float*)d_in[20];
    const float* be2 = (const float*)d_in[21];
    float* out = (float*)d_out;

#define SYM(T, name, sym) T* name; cudaGetSymbolAddress((void**)&name, sym)
    SYM(float, pv, g_v); SYM(float, pao, g_attnout);
    SYM(float, pfi, g_ffnin); SYM(float, pfo, g_ffnout);
    SYM(half_t, csh, g_csh); SYM(half_t, ctxh, g_ctxh); SYM(half_t, posh, g_posh);
    SYM(half_t, qch, g_qch); SYM(half_t, qph, g_qph);
    SYM(half_t, kh, g_kh); SYM(half_t, rh, g_rh);
    SYM(half_t, ath, g_ath); SYM(half_t, fih, g_fih); SYM(half_t, fhh, g_fhh);
    SYM(half_t, wqh, g_wqh); SYM(half_t, wkh, g_wkh); SYM(half_t, wvh, g_wvh);
    SYM(half_t, wrh, g_wrh); SYM(half_t, woh, g_woh);
    SYM(half_t, w1h, g_w1h); SYM(half_t, w2h, g_w2h);
    SYM(half_t, vth, g_vth);
#undef SYM

    cudaFuncSetAttribute(hmma_gemm_kernel, cudaFuncAttributeMaxDynamicSharedMemorySize, GM_SMEM);
    cudaFuncSetAttribute(score_hmma_kernel, cudaFuncAttributeMaxDynamicSharedMemorySize, S_SMEM);
    cudaFuncSetAttribute(pv_fused_kernel, cudaFuncAttributeMaxDynamicSharedMemorySize, PV_SMEM);

    dim3 blk(256);
    cvt4_kernel<<<(QL * HD / 4) / 256, blk>>>(cs, csh, QL * HD / 4);
    cvt4_kernel<<<(CL * HD / 4) / 256, blk>>>(ctx, ctxh, CL * HD / 4);
    cvt4_kernel<<<(RL * HD / 4) / 256, blk>>>(pos, posh, RL * HD / 4);
    convT_kernel<<<dim3(HD / 32, HD / 32), blk>>>(Wq, wqh, HD, HD);
    convT_kernel<<<dim3(HD / 32, HD / 32), blk>>>(Wk, wkh, HD, HD);
    convT_kernel<<<dim3(HD / 32, HD / 32), blk>>>(Wv, wvh, HD, HD);
    convT_kernel<<<dim3(HD / 32, HD / 32), blk>>>(Wr, wrh, HD, HD);
    conv_kernel<<<(HD * HD) / 256, blk>>>(Wo, woh, HD * HD);
    convT_kernel<<<dim3(FF / 32, HD / 32), blk>>>(W1, w1h, HD, FF);
    convT_kernel<<<dim3(HD / 32, FF / 32), blk>>>(W2, w2h, FF, HD);

    // projections
    hmma_gemm_kernel<<<dim3(HD / 64, QL / 128), blk, GM_SMEM>>>(
        csh, wqh, nullptr, nullptr, qch, cb, 0, qph, pb, HD, HD, HD, HD);
    hmma_gemm_kernel<<<dim3(HD / 64, CL / 128), blk, GM_SMEM>>>(
        ctxh, wkh, nullptr, nullptr, kh, nullptr, 0, nullptr, nullptr, HD, HD, HD, HD);
    hmma_gemm_kernel<<<dim3(HD / 64, CL / 128), blk, GM_SMEM>>>(
        ctxh, wvh, pv, nullptr, nullptr, nullptr, 0, nullptr, nullptr, HD, HD, HD, HD);
    hmma_gemm_kernel<<<dim3(HD / 64, RL / 128), blk, GM_SMEM>>>(
        posh, wrh, nullptr, nullptr, rh, nullptr, 0, nullptr, nullptr, HD, HD, HD, HD);

    convT_kernel<<<dim3(HD / 32, CL / 32), blk>>>(pv, vth, CL, HD);
    eseg_kernel<<<(2 * NH * QL) / 256, blk>>>(cb, sbb, seg);

    score_hmma_kernel<<<dim3(CL / 128, QL / 128, NH), blk, S_SMEM>>>(mask, segm);
    pv_fused_kernel<<<dim3(QL / 128, NH), blk, PV_SMEM>>>();

    hmma_gemm_kernel<<<dim3(HD / 64, QL / 128), blk, GM_SMEM>>>(
        ath, woh, pao, nullptr, nullptr, nullptr, 0, nullptr, nullptr, HD, HD, HD, HD);

    ln_kernel<<<QL, blk>>>(pao, cs, g1, be1, pfi, fih);

    hmma_gemm_kernel<<<dim3(FF / 64, QL / 128), blk, GM_SMEM>>>(
        fih, w1h, nullptr, nullptr, fhh, bf1, 1, nullptr, nullptr, HD, HD, HD, FF);
    hmma_gemm_kernel<<<dim3(HD / 64, QL / 128), blk, GM_SMEM>>>(
        fhh, w2h, pfo, bf2, nullptr, nullptr, 0, nullptr, nullptr, FF, FF, FF, HD);

    ln_kernel<<<QL, blk>>>(pfo, pfi, g2, be2, out, nullptr);
}

// round 11
// speedup vs baseline: 2.1180x; 1.0833x over previous
#include <cuda_runtime.h>
#include <cuda_fp16.h>
#include <math.h>
#include <stdint.h>

#define QL 2048
#define CL 2048
#define HD 1024
#define NH 16
#define DH 64
#define FF 4096
#define RL 4096
typedef __half half_t;
typedef __half2 half2_t;

// ---------------- scratch ----------------
__device__ float g_v[CL * HD];
__device__ float g_eseg[2 * NH * QL];
__device__ float g_attnout[QL * HD];
__device__ float g_ffnin[QL * HD];
__device__ float g_ffnout[QL * HD];
__device__ half_t g_csh[QL * HD];
__device__ half_t g_ctxh[CL * HD];
__device__ half_t g_posh[RL * HD];
__device__ half_t g_qch[QL * HD];
__device__ half_t g_qph[QL * HD];
__device__ half_t g_ath[QL * HD];
__device__ half_t g_fih[QL * HD];
__device__ half_t g_fhh[(size_t)QL * FF];
__device__ half_t g_kh[CL * HD];
__device__ half_t g_rh[RL * HD];
__device__ half_t g_vth[HD * CL];
__device__ half_t g_wqh[HD * HD];
__device__ half_t g_wkh[HD * HD];
__device__ half_t g_wvh[HD * HD];
__device__ half_t g_wrh[HD * HD];
__device__ half_t g_woh[HD * HD];
__device__ half_t g_w1h[(size_t)FF * HD];
__device__ half_t g_w2h[(size_t)FF * HD];

#define SWZ(o) ((o) ^ (((o) >> 3) & 0x70))

__device__ __forceinline__ uint32_t smem_u32(const void* p) {
    uint32_t a;
    asm("{ .reg .u64 t; cvta.to.shared.u64 t, %1; cvt.u32.u64 %0, t; }" : "=r"(a) : "l"(p));
    return a;
}
__device__ __forceinline__ void cpasync16(uint32_t s, const void* g) {
    asm volatile("cp.async.cg.shared.global [%0], [%1], 16;" :: "r"(s), "l"(g));
}
#define CP_COMMIT() asm volatile("cp.async.commit_group;")
#define CP_WAIT(n) asm volatile("cp.async.wait_group %0;" :: "n"(n))

__device__ __forceinline__ void wone2(half_t* o, long long off, float x, float y) {
    *(half2_t*)(o + off) = __floats2half2_rn(x, y);
}
__device__ __forceinline__ float warpSum(float v) {
#pragma unroll
    for (int o = 16; o; o >>= 1) v += __shfl_xor_sync(0xffffffffu, v, o);
    return v;
}
__device__ __forceinline__ void mma_f16(float* d, const uint32_t* a, const uint32_t* b) {
    asm volatile(
        "mma.sync.aligned.m16n8k16.row.col.f32.f16.f16.f32 "
        "{%0,%1,%2,%3}, {%4,%5,%6,%7}, {%8,%9}, {%0,%1,%2,%3};"
        : "+f"(d[0]), "+f"(d[1]), "+f"(d[2]), "+f"(d[3])
        : "r"(a[0]), "r"(a[1]), "r"(a[2]), "r"(a[3]), "r"(b[0]), "r"(b[1]));
}
__device__ __forceinline__ void ldm4(uint32_t* r, uint32_t base, int row0, int k0, int lane) {
    int row = row0 + (lane & 15);
    int kc = k0 + ((lane >> 4) << 3);
    uint32_t addr = base + SWZ((uint32_t)row * 128 + (uint32_t)kc * 2);
    asm volatile("ldmatrix.sync.aligned.m8n8.x4.shared.b16 {%0,%1,%2,%3}, [%4];"
                 : "=r"(r[0]), "=r"(r[1]), "=r"(r[2]), "=r"(r[3]) : "r"(addr));
}

// ---------------- converters ----------------
__global__ void __launch_bounds__(256) cvt4_kernel(
    const float* __restrict__ in, half_t* __restrict__ o, int n4)
{
    int i = blockIdx.x * 256 + threadIdx.x;
    if (i >= n4) return;
    float4 v = *(const float4*)(in + i * 4);
    wone2(o, (long long)i * 4, v.x, v.y);
    wone2(o, (long long)i * 4 + 2, v.z, v.w);
}
__global__ void __launch_bounds__(256) convT_kernel(
    const float* __restrict__ in, half_t* __restrict__ o, int R, int Cc)
{
    __shared__ float t[32][33];
    const int tx = threadIdx.x & 31, ty8 = threadIdx.x >> 5;
    const int r0 = blockIdx.y * 32, c0 = blockIdx.x * 32;
    for (int j = ty8; j < 32; j += 8) t[j][tx] = in[(long long)(r0 + j) * Cc + c0 + tx];
    __syncthreads();
    for (int j = ty8; j < 32; j += 8)
        o[(long long)(c0 + j) * R + r0 + tx] = __float2half_rn(t[tx][j]);
}
__global__ void __launch_bounds__(256) conv_kernel(
    const float* __restrict__ in, half_t* __restrict__ o, int n)
{
    int i = blockIdx.x * 256 + threadIdx.x;
    if (i < n) o[i] = __float2half_rn(in[i]);
}

// ---------------- HMMA GEMM (unchanged from R10) ----------------
#define ST_A 0
#define ST_B 16384
#define ST_SZ 24576
#define GM_SMEM (2 * ST_SZ)

__global__ void __launch_bounds__(256) hmma_gemm_kernel(
    const half_t* __restrict__ A, const half_t* __restrict__ B,
    float* __restrict__ C, const float* __restrict__ biasC,
    half_t* __restrict__ O1h, const float* __restrict__ bias1, int relu1,
    half_t* __restrict__ O2h, const float* __restrict__ bias2,
    int K, int lda, int ldb, int ldc)
{
    extern __shared__ char smem[];
    const uint32_t sbase = smem_u32(smem);
    const int tid = threadIdx.x, lane = tid & 31, w = tid >> 5;
    const int g = lane >> 2, tig = lane & 3;
    const int m0 = blockIdx.y * 128, n0 = blockIdx.x * 64;
    const int wm = (w >> 1) * 32, wn = (w & 1) * 32;

    auto load_stage = [&](int s, int k0) {
        uint32_t sb = sbase + s * ST_SZ;
#pragma unroll
        for (int i = 0; i < 4; i++) {
            int u = tid + (i << 8);
            int row = u >> 3, c16 = u & 7;
            uint32_t sw = SWZ((uint32_t)row * 128 + (uint32_t)(c16 << 4));
            cpasync16(sb + ST_A + sw, A + (long long)(m0 + row) * lda + k0 + (c16 << 3));
        }
#pragma unroll
        for (int i = 0; i < 2; i++) {
            int u = tid + (i << 8);
            int row = u >> 3, c16 = u & 7;
            uint32_t sw = SWZ((uint32_t)row * 128 + (uint32_t)(c16 << 4));
            cpasync16(sb + ST_B + sw, B + (long long)(n0 + row) * ldb + k0 + (c16 << 3));
        }
    };

    float acc[2][4][4] = {};
    const int NC = K >> 6;
    load_stage(0, 0);
    CP_COMMIT();
    for (int c = 0; c < NC; c++) {
        if (c + 1 < NC) { load_stage((c + 1) & 1, (c + 1) << 6); CP_COMMIT(); CP_WAIT(1); }
        else CP_WAIT(0);
        __syncthreads();
        const uint32_t sb = sbase + (c & 1) * ST_SZ;
#pragma unroll
        for (int ks = 0; ks < 4; ks++) {
            uint32_t ah[2][4], bh[2][4];
            ldm4(ah[0], sb + ST_A, wm, ks * 16, lane);
            ldm4(ah[1], sb + ST_A, wm + 16, ks * 16, lane);
            ldm4(bh[0], sb + ST_B, wn, ks * 16, lane);
            ldm4(bh[1], sb + ST_B, wn + 16, ks * 16, lane);
#pragma unroll
            for (int mt = 0; mt < 2; mt++)
#pragma unroll
                for (int nt = 0; nt < 4; nt++) {
                    const int p = nt >> 1, o = nt & 1;
                    uint32_t fb[2] = { bh[p][o], bh[p][2 + o] };
                    mma_f16(acc[mt][nt], ah[mt], fb);
                }
        }
        __syncthreads();
    }

#pragma unroll
    for (int mt = 0; mt < 2; mt++)
#pragma unroll
        for (int nt = 0; nt < 4; nt++) {
#pragma unroll
            for (int h = 0; h < 2; h++) {
                const int row = m0 + wm + mt * 16 + g + h * 8;
                const int col = n0 + wn + nt * 8 + 2 * tig;
                float x = acc[mt][nt][h * 2], y = acc[mt][nt][h * 2 + 1];
                const long long off = (long long)row * ldc + col;
                if (C) {
                    float b0 = biasC ? biasC[col] : 0.f, b1 = biasC ? biasC[col + 1] : 0.f;
                    float2 o = { x + b0, y + b1 };
                    *(float2*)(C + off) = o;
                }
                if (O1h) {
                    float b0 = bias1 ? bias1[col] : 0.f, b1 = bias1 ? bias1[col + 1] : 0.f;
                    float vx = x + b0, vy = y + b1;
                    if (relu1) { vx = fmaxf(vx, 0.f); vy = fmaxf(vy, 0.f); }
                    wone2(O1h, off, vx, vy);
                }
                if (O2h) {
                    float b0 = bias2 ? bias2[col] : 0.f, b1 = bias2 ? bias2[col + 1] : 0.f;
                    wone2(O2h, off, x + b0, y + b1);
                }
            }
        }
}

// ---------------- fused flash attention: scores + online softmax + PV -------
// grid (QL/128, NH), 256 threads (8 warps x 16 q rows)
#define F_QC 0
#define F_QP 16384
#define F_K  32768
#define F_R  49152
#define F_V0 81920
#define F_V1 90112
#define F_P0 98304
#define F_P1 114688
#define F_ST 131072
#define F_SMEM (131072 + 8 * 3200)

__global__ void __launch_bounds__(256) flash_kernel(
    const float* __restrict__ mask, const unsigned char* __restrict__ segmat)
{
    extern __shared__ char smem[];
    const uint32_t sbase = smem_u32(smem);
    const int tid = threadIdx.x, lane = tid & 31, w = tid >> 5;
    const int g = lane >> 2, tig = lane & 3;
    const int n = blockIdx.y, q0 = blockIdx.x * 128;
    const int nDH = n * DH;
    const int w0 = w * 16;

    // load q tiles once
#pragma unroll
    for (int i = 0; i < 4; i++) {
        int u = tid + (i << 8);
        int row = u >> 3, c16 = u & 7;
        uint32_t sw = SWZ((uint32_t)row * 128 + (uint32_t)(c16 << 4));
        long long gq = (long long)(q0 + row) * HD + nDH + (c16 << 3);
        *(uint4*)(smem + F_QC + sw) = *(const uint4*)(g_qch + gq);
        *(uint4*)(smem + F_QP + sw) = *(const uint4*)(g_qph + gq);
    }

    auto loadKR = [&](int c0) {
#pragma unroll
        for (int i = 0; i < 4; i++) {
            int u = tid + (i << 8);
            int row = u >> 3, c16 = u & 7;
            cpasync16(sbase + F_K + SWZ((uint32_t)row * 128 + (uint32_t)(c16 << 4)),
                      g_kh + (long long)(c0 + row) * HD + nDH + (c16 << 3));
        }
        const int rstart = QL + c0 - q0 - 127;
#pragma unroll
        for (int i = 0; i < 8; i++) {
            int u = tid + (i << 8);
            int row = u >> 3, c16 = u & 7;
            int rg = rstart + row; if (rg > RL - 1) rg = RL - 1;
            cpasync16(sbase + F_R + SWZ((uint32_t)row * 128 + (uint32_t)(c16 << 4)),
                      g_rh + (long long)rg * HD + nDH + (c16 << 3));
        }
    };
    const half_t* vt = g_vth + (long long)(n * 64) * CL;
    auto loadV = [&](int c0) {
#pragma unroll
        for (int i = 0; i < 2; i++) {
            int u = tid + (i << 8);
            int row = u >> 3, c16 = u & 7;
            uint32_t sw = SWZ((uint32_t)row * 128 + (uint32_t)(c16 << 4));
            cpasync16(sbase + F_V0 + sw, vt + (long long)row * CL + c0 + (c16 << 3));
            cpasync16(sbase + F_V1 + sw, vt + (long long)row * CL + c0 + 64 + (c16 << 3));
        }
    };

    loadKR(0); CP_COMMIT();
    loadV(0); CP_COMMIT();

    const float e0a = g_eseg[(0 * NH + n) * QL + q0 + w0 + g];
    const float e1a = g_eseg[(1 * NH + n) * QL + q0 + w0 + g];
    const float e0b = g_eseg[(0 * NH + n) * QL + q0 + w0 + g + 8];
    const float e1b = g_eseg[(1 * NH + n) * QL + q0 + w0 + g + 8];
    float* stg = (float*)(smem + F_ST + w * 3200);

    float m0r = -3.0e38f, m1r = -3.0e38f, l0r = 0.f, l1r = 0.f;
    float accO[8][4] = {};

    for (int cb = 0; cb < CL / 128; cb++) {
        const int c0 = cb * 128;
        CP_WAIT(1);               // K,r ready (V group still pending)
        __syncthreads();

        // ---- phase 1: scores into registers ----
        float sc[4][16];
#pragma unroll
        for (int ch = 0; ch < 4; ch++) {
            float accA[4][4] = {};
            float accB[6][4] = {};
            const int s0 = ch * 32 - w0 + 112;
#pragma unroll
            for (int ks = 0; ks < 4; ks++) {
                uint32_t aqc[4], aqp[4];
                ldm4(aqc, sbase + F_QC, w0, ks * 16, lane);
                ldm4(aqp, sbase + F_QP, w0, ks * 16, lane);
                uint32_t kh[2][4];
                ldm4(kh[0], sbase + F_K, ch * 32, ks * 16, lane);
                ldm4(kh[1], sbase + F_K, ch * 32 + 16, ks * 16, lane);
#pragma unroll
                for (int nt = 0; nt < 4; nt++) {
                    const int p = nt >> 1, o = nt & 1;
                    uint32_t fb[2] = { kh[p][o], kh[p][2 + o] };
                    mma_f16(accA[nt], aqc, fb);
                }
                uint32_t rh[3][4];
#pragma unroll
                for (int p = 0; p < 3; p++)
                    ldm4(rh[p], sbase + F_R, s0 + p * 16, ks * 16, lane);
#pragma unroll
                for (int nt = 0; nt < 6; nt++) {
                    const int p = nt >> 1, o = nt & 1;
                    uint32_t fb[2] = { rh[p][o], rh[p][2 + o] };
                    mma_f16(accB[nt], aqp, fb);
                }
            }
#pragma unroll
            for (int nt = 0; nt < 6; nt++) {
                int cc = nt * 8 + 2 * tig;
                stg[g * 50 + cc] = accB[nt][0];
                stg[g * 50 + cc + 1] = accB[nt][1];
                stg[(g + 8) * 50 + cc] = accB[nt][2];
                stg[(g + 8) * 50 + cc + 1] = accB[nt][3];
            }
            __syncwarp();
#pragma unroll
            for (int nt = 0; nt < 4; nt++) {
                const int jl = nt * 8 + 2 * tig;
                const float bd0 = stg[g * 50 + jl - g + 15], bd1 = stg[g * 50 + jl - g + 16];
                const float bd2 = stg[(g + 8) * 50 + jl - g + 7], bd3 = stg[(g + 8) * 50 + jl - g + 8];
                const int qa = q0 + w0 + g, cc = c0 + ch * 32 + jl;
                const size_t ma = (size_t)qa * CL + cc;
                const size_t mb = (size_t)(qa + 8) * CL + cc;
                float2 mka = *(const float2*)(mask + ma);
                float2 mkb = *(const float2*)(mask + mb);
                uchar2 sga = *(const uchar2*)(segmat + ma);
                uchar2 sgb = *(const uchar2*)(segmat + mb);
                sc[ch][nt * 4 + 0] = (accA[nt][0] + bd0 + (sga.x ? e1a : e0a)) * 0.125f - 1e30f * mka.x;
                sc[ch][nt * 4 + 1] = (accA[nt][1] + bd1 + (sga.y ? e1a : e0a)) * 0.125f - 1e30f * mka.y;
                sc[ch][nt * 4 + 2] = (accA[nt][2] + bd2 + (sgb.x ? e1b : e0b)) * 0.125f - 1e30f * mkb.x;
                sc[ch][nt * 4 + 3] = (accA[nt][3] + bd3 + (sgb.y ? e1b : e0b)) * 0.125f - 1e30f * mkb.y;
            }
            __syncwarp();
        }
        __syncthreads();           // all warps done with K,r
        if (cb + 1 < CL / 128) { loadKR(c0 + 128); CP_COMMIT(); }

        // ---- phase 2: online softmax (registers -> P smem) ----
        float rmax0 = -3.0e38f, rmax1 = -3.0e38f;
#pragma unroll
        for (int ch = 0; ch < 4; ch++)
#pragma unroll
            for (int nt = 0; nt < 4; nt++) {
                rmax0 = fmaxf(rmax0, fmaxf(sc[ch][nt * 4], sc[ch][nt * 4 + 1]));
                rmax1 = fmaxf(rmax1, fmaxf(sc[ch][nt * 4 + 2], sc[ch][nt * 4 + 3]));
            }
        rmax0 = fmaxf(rmax0, __shfl_xor_sync(0xffffffffu, rmax0, 1));
        rmax0 = fmaxf(rmax0, __shfl_xor_sync(0xffffffffu, rmax0, 2));
        rmax1 = fmaxf(rmax1, __shfl_xor_sync(0xffffffffu, rmax1, 1));
        rmax1 = fmaxf(rmax1, __shfl_xor_sync(0xffffffffu, rmax1, 2));
        const float mn0 = fmaxf(m0r, rmax0), mn1 = fmaxf(m1r, rmax1);
        const float s0s = __expf(m0r - mn0), s1s = __expf(m1r - mn1);
        m0r = mn0; m1r = mn1;
        float cs0 = 0.f, cs1 = 0.f;
#pragma unroll
        for (int ch = 0; ch < 4; ch++) {
            const uint32_t pb = sbase + (ch < 2 ? F_P0 : F_P1);
            const int cofs = (ch & 1) * 32;
#pragma unroll
            for (int nt = 0; nt < 4; nt++) {
                float p0 = __expf(sc[ch][nt * 4 + 0] - mn0);
                float p1 = __expf(sc[ch][nt * 4 + 1] - mn0);
                float p2 = __expf(sc[ch][nt * 4 + 2] - mn1);
                float p3 = __expf(sc[ch][nt * 4 + 3] - mn1);
                cs0 += p0 + p1; cs1 += p2 + p3;
                const uint32_t col2 = (uint32_t)(cofs + nt * 8 + 2 * tig) * 2;
                *(half2_t*)(smem + (pb - sbase) + SWZ((uint32_t)(w0 + g) * 128 + col2)) =
                    __floats2half2_rn(p0, p1);
                *(half2_t*)(smem + (pb - sbase) + SWZ((uint32_t)(w0 + g + 8) * 128 + col2)) =
                    __floats2half2_rn(p2, p3);
            }
        }
        cs0 += __shfl_xor_sync(0xffffffffu, cs0, 1);
        cs0 += __shfl_xor_sync(0xffffffffu, cs0, 2);
        cs1 += __shfl_xor_sync(0xffffffffu, cs1, 1);
        cs1 += __shfl_xor_sync(0xffffffffu, cs1, 2);
        l0r = l0r * s0s + cs0;
        l1r = l1r * s1s + cs1;
#pragma unroll
        for (int t = 0; t < 8; t++) {
            accO[t][0] *= s0s; accO[t][1] *= s0s;
            accO[t][2] *= s1s; accO[t][3] *= s1s;
        }
        __syncwarp();
        CP_WAIT(1);                // V ready (only next-KR group may remain)
        if (cb + 1 >= CL / 128) CP_WAIT(0);

        // ---- phase 3: PV MMA ----
#pragma unroll
        for (int ks = 0; ks < 8; ks++) {
            const uint32_t pb = sbase + (ks < 4 ? F_P0 : F_P1);
            const uint32_t vb = sbase + (ks < 4 ? F_V0 : F_V1);
            const int kk = (ks & 3) * 16;
            uint32_t aP[4];
            ldm4(aP, pb, w0, kk, lane);
            uint32_t bH[4][4];
#pragma unroll
            for (int p = 0; p < 4; p++)
                ldm4(bH[p], vb, p * 16, kk, lane);
#pragma unroll
            for (int t = 0; t < 8; t++) {
                const int p = t >> 1, o = t & 1;
                uint32_t fb[2] = { bH[p][o], bH[p][2 + o] };
                mma_f16(accO[t], aP, fb);
            }
        }
        __syncthreads();           // all warps done with V
        if (cb + 1 < CL / 128) { loadV(c0 + 128); CP_COMMIT(); }
    }

    const float li0 = 1.0f / l0r, li1 = 1.0f / l1r;
#pragma unroll
    for (int t = 0; t < 8; t++) {
        const int dloc = (t >> 1) * 16 + (t & 1) * 8 + 2 * tig;
        const long long col = (long long)n * 64 + dloc;
        wone2(g_ath, (long long)(q0 + w0 + g) * HD + col, accO[t][0] * li0, accO[t][1] * li0);
        wone2(g_ath, (long long)(q0 + w0 + g + 8) * HD + col, accO[t][2] * li1, accO[t][3] * li1);
    }
}

// ---------------- eseg ----------------
__global__ void __launch_bounds__(256) eseg_kernel(
    const float* __restrict__ cb, const float* __restrict__ sb, const float* __restrict__ seg)
{
    int idx = blockIdx.x * 256 + threadIdx.x;
    if (idx >= 2 * NH * QL) return;
    int s = idx / (NH * QL), n = (idx / QL) % NH, qi = idx % QL;
    const half_t* qh = g_qch + (long long)qi * HD + n * DH;
    const float* cbr = cb + n * DH;
    const float* sbr = sb + n * DH;
    const float* sg = seg + s * (NH * DH) + n * DH;
    float acc = 0.f;
#pragma unroll
    for (int d = 0; d < DH; d++) {
        float q = __half2float(qh[d]) - cbr[d] + sbr[d];
        acc += q * sg[d];
    }
    g_eseg[idx] = acc;
}

// ---------------- residual + LN ----------------
__global__ void __launch_bounds__(256) ln_kernel(
    const float* __restrict__ x, const float* __restrict__ res,
    const float* __restrict__ g, const float* __restrict__ b,
    float* __restrict__ out, half_t* __restrict__ oh)
{
    const int row = blockIdx.x;
    __shared__ float buf[HD];
    __shared__ float red[8];
    __shared__ float s_mean, s_rstd;
    const int tid = threadIdx.x;
    float lsum = 0.f;
    for (int i = tid; i < HD; i += 256) {
        float v = x[(long long)row * HD + i] + res[(long long)row * HD + i];
        buf[i] = v; lsum += v;
    }
    lsum = warpSum(lsum);
    if ((tid & 31) == 0) red[tid >> 5] = lsum;
    __syncthreads();
    if (tid == 0) {
        float s = 0.f;
#pragma unroll
        for (int i = 0; i < 8; i++) s += red[i];
        s_mean = s * (1.0f / HD);
    }
    __syncthreads();
    const float m = s_mean;
    float lv = 0.f;
    for (int i = tid; i < HD; i += 256) { float d = buf[i] - m; lv += d * d; }
    lv = warpSum(lv);
    __syncthreads();
    if ((tid & 31) == 0) red[tid >> 5] = lv;
    __syncthreads();
    if (tid == 0) {
        float s = 0.f;
#pragma unroll
        for (int i = 0; i < 8; i++) s += red[i];
        s_rstd = rsqrtf(s * (1.0f / HD) + 1e-12f);
    }
    __syncthreads();
    const float rs = s_rstd;
    for (int i = tid; i < HD; i += 256) {
        float o = (buf[i] - m) * rs * g[i] + b[i];
        if (out) out[(long long)row * HD + i] = o;
        if (oh) oh[(long long)row * HD + i] = __float2half_rn(o);
    }
}

// ---------------- launch ----------------
extern "C" void kernel_launch(void* const* d_in, const int* in_sizes, int n_in,
                              void* d_out, int out_size)
{
    const float* cs = (const float*)d_in[0];
    const float* mask = (const float*)d_in[1];
    const float* ctx = (const float*)d_in[2];
    const float* pos = (const float*)d_in[3];
    const float* cb = (const float*)d_in[4];
    const float* pb = (const float*)d_in[5];
    const float* seg = (const float*)d_in[6];
    const unsigned char* segm = (const unsigned char*)d_in[7];
    const float* sbb = (const float*)d_in[8];
    const float* Wq = (const float*)d_in[9];
    const float* Wk = (const float*)d_in[10];
    const float* Wv = (const float*)d_in[11];
    const float* Wr = (const float*)d_in[12];
    const float* Wo = (const float*)d_in[13];
    const float* g1 = (const float*)d_in[14];
    const float* be1 = (const float*)d_in[15];
    const float* W1 = (const float*)d_in[16];
    const float* bf1 = (const float*)d_in[17];
    const float* W2 = (const float*)d_in[18];
    const float* bf2 = (const float*)d_in[19];
    const float* g2 = (const float*)d_in[20];
    const float* be2 = (const float*)d_in[21];
    float* out = (float*)d_out;

#define SYM(T, name, sym) T* name; cudaGetSymbolAddress((void**)&name, sym)
    SYM(float, pv, g_v); SYM(float, pao, g_attnout);
    SYM(float, pfi, g_ffnin); SYM(float, pfo, g_ffnout);
    SYM(half_t, csh, g_csh); SYM(half_t, ctxh, g_ctxh); SYM(half_t, posh, g_posh);
    SYM(half_t, qch, g_qch); SYM(half_t, qph, g_qph);
    SYM(half_t, kh, g_kh); SYM(half_t, rh, g_rh);
    SYM(half_t, ath, g_ath); SYM(half_t, fih, g_fih); SYM(half_t, fhh, g_fhh);
    SYM(half_t, wqh, g_wqh); SYM(half_t, wkh, g_wkh); SYM(half_t, wvh, g_wvh);
    SYM(half_t, wrh, g_wrh); SYM(half_t, woh, g_woh);
    SYM(half_t, w1h, g_w1h); SYM(half_t, w2h, g_w2h);
    SYM(half_t, vth, g_vth);
#undef SYM

    cudaFuncSetAttribute(hmma_gemm_kernel, cudaFuncAttributeMaxDynamicSharedMemorySize, GM_SMEM);
    cudaFuncSetAttribute(flash_kernel, cudaFuncAttributeMaxDynamicSharedMemorySize, F_SMEM);

    dim3 blk(256);
    cvt4_kernel<<<(QL * HD / 4) / 256, blk>>>(cs, csh, QL * HD / 4);
    cvt4_kernel<<<(CL * HD / 4) / 256, blk>>>(ctx, ctxh, CL * HD / 4);
    cvt4_kernel<<<(RL * HD / 4) / 256, blk>>>(pos, posh, RL * HD / 4);
    convT_kernel<<<dim3(HD / 32, HD / 32), blk>>>(Wq, wqh, HD, HD);
    convT_kernel<<<dim3(HD / 32, HD / 32), blk>>>(Wk, wkh, HD, HD);
    convT_kernel<<<dim3(HD / 32, HD / 32), blk>>>(Wv, wvh, HD, HD);
    convT_kernel<<<dim3(HD / 32, HD / 32), blk>>>(Wr, wrh, HD, HD);
    conv_kernel<<<(HD * HD) / 256, blk>>>(Wo, woh, HD * HD);
    convT_kernel<<<dim3(FF / 32, HD / 32), blk>>>(W1, w1h, HD, FF);
    convT_kernel<<<dim3(HD / 32, FF / 32), blk>>>(W2, w2h, FF, HD);

    // projections
    hmma_gemm_kernel<<<dim3(HD / 64, QL / 128), blk, GM_SMEM>>>(
        csh, wqh, nullptr, nullptr, qch, cb, 0, qph, pb, HD, HD, HD, HD);
    hmma_gemm_kernel<<<dim3(HD / 64, CL / 128), blk, GM_SMEM>>>(
        ctxh, wkh, nullptr, nullptr, kh, nullptr, 0, nullptr, nullptr, HD, HD, HD, HD);
    hmma_gemm_kernel<<<dim3(HD / 64, CL / 128), blk, GM_SMEM>>>(
        ctxh, wvh, pv, nullptr, nullptr, nullptr, 0, nullptr, nullptr, HD, HD, HD, HD);
    hmma_gemm_kernel<<<dim3(HD / 64, RL / 128), blk, GM_SMEM>>>(
        posh, wrh, nullptr, nullptr, rh, nullptr, 0, nullptr, nullptr, HD, HD, HD, HD);

    convT_kernel<<<dim3(HD / 32, CL / 32), blk>>>(pv, vth, CL, HD);
    eseg_kernel<<<(2 * NH * QL) / 256, blk>>>(cb, sbb, seg);

    // fused flash attention (scores never hit gmem)
    flash_kernel<<<dim3(QL / 128, NH), blk, F_SMEM>>>(mask, segm);

    hmma_gemm_kernel<<<dim3(HD / 64, QL / 128), blk, GM_SMEM>>>(
        ath, woh, pao, nullptr, nullptr, nullptr, 0, nullptr, nullptr, HD, HD, HD, HD);

    ln_kernel<<<QL, blk>>>(pao, cs, g1, be1, pfi, fih);

    hmma_gemm_kernel<<<dim3(FF / 64, QL / 128), blk, GM_SMEM>>>(
        fih, w1h, nullptr, nullptr, fhh, bf1, 1, nullptr, nullptr, HD, HD, HD, FF);
    hmma_gemm_kernel<<<dim3(HD / 64, QL / 128), blk, GM_SMEM>>>(
        fhh, w2h, pfo, bf2, nullptr, nullptr, 0, nullptr, nullptr, FF, FF, FF, HD);

    ln_kernel<<<QL, blk>>>(pfo, pfi, g2, be2, out, nullptr);
}

// round 12
// speedup vs baseline: 2.2155x; 1.0460x over previous
#include <cuda_runtime.h>
#include <cuda_fp16.h>
#include <math.h>
#include <stdint.h>

#define QL 2048
#define CL 2048
#define HD 1024
#define NH 16
#define DH 64
#define FF 4096
#define RL 4096
typedef __half half_t;
typedef __half2 half2_t;

// ---------------- scratch ----------------
__device__ float g_v[CL * HD];
__device__ float g_eseg[2 * NH * QL];
__device__ float g_attnout[QL * HD];
__device__ float g_ffnin[QL * HD];
__device__ float g_ffnout[QL * HD];
__device__ unsigned char g_msk[(size_t)QL * CL];   // bit0=segment, bit1=masked
__device__ half_t g_csh[QL * HD];
__device__ half_t g_ctxh[CL * HD];
__device__ half_t g_posh[RL * HD];
__device__ half_t g_qch[QL * HD];
__device__ half_t g_qph[QL * HD];
__device__ half_t g_ath[QL * HD];
__device__ half_t g_fih[QL * HD];
__device__ half_t g_fhh[(size_t)QL * FF];
__device__ half_t g_kh[CL * HD];
__device__ half_t g_rh[RL * HD];
__device__ half_t g_vth[HD * CL];
__device__ half_t g_wqh[HD * HD];
__device__ half_t g_wkh[HD * HD];
__device__ half_t g_wvh[HD * HD];
__device__ half_t g_wrh[HD * HD];
__device__ half_t g_woh[HD * HD];
__device__ half_t g_w1h[(size_t)FF * HD];
__device__ half_t g_w2h[(size_t)FF * HD];

#define SWZ(o) ((o) ^ (((o) >> 3) & 0x70))

__device__ __forceinline__ uint32_t smem_u32(const void* p) {
    uint32_t a;
    asm("{ .reg .u64 t; cvta.to.shared.u64 t, %1; cvt.u32.u64 %0, t; }" : "=r"(a) : "l"(p));
    return a;
}
__device__ __forceinline__ void cpasync16(uint32_t s, const void* g) {
    asm volatile("cp.async.cg.shared.global [%0], [%1], 16;" :: "r"(s), "l"(g));
}
#define CP_COMMIT() asm volatile("cp.async.commit_group;")
#define CP_WAIT(n) asm volatile("cp.async.wait_group %0;" :: "n"(n))

__device__ __forceinline__ void wone2(half_t* o, long long off, float x, float y) {
    *(half2_t*)(o + off) = __floats2half2_rn(x, y);
}
__device__ __forceinline__ float warpSum(float v) {
#pragma unroll
    for (int o = 16; o; o >>= 1) v += __shfl_xor_sync(0xffffffffu, v, o);
    return v;
}
__device__ __forceinline__ void mma_f16(float* d, const uint32_t* a, const uint32_t* b) {
    asm volatile(
        "mma.sync.aligned.m16n8k16.row.col.f32.f16.f16.f32 "
        "{%0,%1,%2,%3}, {%4,%5,%6,%7}, {%8,%9}, {%0,%1,%2,%3};"
        : "+f"(d[0]), "+f"(d[1]), "+f"(d[2]), "+f"(d[3])
        : "r"(a[0]), "r"(a[1]), "r"(a[2]), "r"(a[3]), "r"(b[0]), "r"(b[1]));
}
__device__ __forceinline__ void ldm4(uint32_t* r, uint32_t base, int row0, int k0, int lane) {
    int row = row0 + (lane & 15);
    int kc = k0 + ((lane >> 4) << 3);
    uint32_t addr = base + SWZ((uint32_t)row * 128 + (uint32_t)kc * 2);
    asm volatile("ldmatrix.sync.aligned.m8n8.x4.shared.b16 {%0,%1,%2,%3}, [%4];"
                 : "=r"(r[0]), "=r"(r[1]), "=r"(r[2]), "=r"(r[3]) : "r"(addr));
}

// ---------------- converters ----------------
__global__ void __launch_bounds__(256) cvt4_kernel(
    const float* __restrict__ in, half_t* __restrict__ o, int n4)
{
    int i = blockIdx.x * 256 + threadIdx.x;
    if (i >= n4) return;
    float4 v = *(const float4*)(in + i * 4);
    wone2(o, (long long)i * 4, v.x, v.y);
    wone2(o, (long long)i * 4 + 2, v.z, v.w);
}
__global__ void __launch_bounds__(256) convT_kernel(
    const float* __restrict__ in, half_t* __restrict__ o, int R, int Cc)
{
    __shared__ float t[32][33];
    const int tx = threadIdx.x & 31, ty8 = threadIdx.x >> 5;
    const int r0 = blockIdx.y * 32, c0 = blockIdx.x * 32;
    for (int j = ty8; j < 32; j += 8) t[j][tx] = in[(long long)(r0 + j) * Cc + c0 + tx];
    __syncthreads();
    for (int j = ty8; j < 32; j += 8)
        o[(long long)(c0 + j) * R + r0 + tx] = __float2half_rn(t[tx][j]);
}
// batched square-transpose converter for the 4 HD x HD weights
struct CT4 { const float* in[4]; half_t* out[4]; };
__global__ void __launch_bounds__(256) convT4_kernel(CT4 a)
{
    __shared__ float t[32][33];
    const float* in = a.in[blockIdx.z];
    half_t* o = a.out[blockIdx.z];
    const int tx = threadIdx.x & 31, ty8 = threadIdx.x >> 5;
    const int r0 = blockIdx.y * 32, c0 = blockIdx.x * 32;
    for (int j = ty8; j < 32; j += 8) t[j][tx] = in[(long long)(r0 + j) * HD + c0 + tx];
    __syncthreads();
    for (int j = ty8; j < 32; j += 8)
        o[(long long)(c0 + j) * HD + r0 + tx] = __float2half_rn(t[tx][j]);
}
__global__ void __launch_bounds__(256) conv_kernel(
    const float* __restrict__ in, half_t* __restrict__ o, int n)
{
    int i = blockIdx.x * 256 + threadIdx.x;
    if (i < n) o[i] = __float2half_rn(in[i]);
}
// combined mask byte map: bit0=segment, bit1=masked
__global__ void __launch_bounds__(256) msk_kernel(
    const float* __restrict__ mask, const unsigned char* __restrict__ segmat,
    unsigned char* __restrict__ o)
{
    int i = blockIdx.x * 256 + threadIdx.x;          // QL*CL/4 units
    float4 m = *(const float4*)(mask + (size_t)i * 4);
    uchar4 s = *(const uchar4*)(segmat + (size_t)i * 4);
    uchar4 r;
    r.x = (s.x ? 1 : 0) | (m.x != 0.f ? 2 : 0);
    r.y = (s.y ? 1 : 0) | (m.y != 0.f ? 2 : 0);
    r.z = (s.z ? 1 : 0) | (m.z != 0.f ? 2 : 0);
    r.w = (s.w ? 1 : 0) | (m.w != 0.f ? 2 : 0);
    *(uchar4*)(o + (size_t)i * 4) = r;
}

// ---------------- HMMA GEMM (unchanged) ----------------
#define ST_A 0
#define ST_B 16384
#define ST_SZ 24576
#define GM_SMEM (2 * ST_SZ)

__global__ void __launch_bounds__(256) hmma_gemm_kernel(
    const half_t* __restrict__ A, const half_t* __restrict__ B,
    float* __restrict__ C, const float* __restrict__ biasC,
    half_t* __restrict__ O1h, const float* __restrict__ bias1, int relu1,
    half_t* __restrict__ O2h, const float* __restrict__ bias2,
    int K, int lda, int ldb, int ldc)
{
    extern __shared__ char smem[];
    const uint32_t sbase = smem_u32(smem);
    const int tid = threadIdx.x, lane = tid & 31, w = tid >> 5;
    const int g = lane >> 2, tig = lane & 3;
    const int m0 = blockIdx.y * 128, n0 = blockIdx.x * 64;
    const int wm = (w >> 1) * 32, wn = (w & 1) * 32;

    auto load_stage = [&](int s, int k0) {
        uint32_t sb = sbase + s * ST_SZ;
#pragma unroll
        for (int i = 0; i < 4; i++) {
            int u = tid + (i << 8);
            int row = u >> 3, c16 = u & 7;
            uint32_t sw = SWZ((uint32_t)row * 128 + (uint32_t)(c16 << 4));
            cpasync16(sb + ST_A + sw, A + (long long)(m0 + row) * lda + k0 + (c16 << 3));
        }
#pragma unroll
        for (int i = 0; i < 2; i++) {
            int u = tid + (i << 8);
            int row = u >> 3, c16 = u & 7;
            uint32_t sw = SWZ((uint32_t)row * 128 + (uint32_t)(c16 << 4));
            cpasync16(sb + ST_B + sw, B + (long long)(n0 + row) * ldb + k0 + (c16 << 3));
        }
    };

    float acc[2][4][4] = {};
    const int NC = K >> 6;
    load_stage(0, 0);
    CP_COMMIT();
    for (int c = 0; c < NC; c++) {
        if (c + 1 < NC) { load_stage((c + 1) & 1, (c + 1) << 6); CP_COMMIT(); CP_WAIT(1); }
        else CP_WAIT(0);
        __syncthreads();
        const uint32_t sb = sbase + (c & 1) * ST_SZ;
#pragma unroll
        for (int ks = 0; ks < 4; ks++) {
            uint32_t ah[2][4], bh[2][4];
            ldm4(ah[0], sb + ST_A, wm, ks * 16, lane);
            ldm4(ah[1], sb + ST_A, wm + 16, ks * 16, lane);
            ldm4(bh[0], sb + ST_B, wn, ks * 16, lane);
            ldm4(bh[1], sb + ST_B, wn + 16, ks * 16, lane);
#pragma unroll
            for (int mt = 0; mt < 2; mt++)
#pragma unroll
                for (int nt = 0; nt < 4; nt++) {
                    const int p = nt >> 1, o = nt & 1;
                    uint32_t fb[2] = { bh[p][o], bh[p][2 + o] };
                    mma_f16(acc[mt][nt], ah[mt], fb);
                }
        }
        __syncthreads();
    }

#pragma unroll
    for (int mt = 0; mt < 2; mt++)
#pragma unroll
        for (int nt = 0; nt < 4; nt++) {
#pragma unroll
            for (int h = 0; h < 2; h++) {
                const int row = m0 + wm + mt * 16 + g + h * 8;
                const int col = n0 + wn + nt * 8 + 2 * tig;
                float x = acc[mt][nt][h * 2], y = acc[mt][nt][h * 2 + 1];
                const long long off = (long long)row * ldc + col;
                if (C) {
                    float b0 = biasC ? biasC[col] : 0.f, b1 = biasC ? biasC[col + 1] : 0.f;
                    float2 o = { x + b0, y + b1 };
                    *(float2*)(C + off) = o;
                }
                if (O1h) {
                    float b0 = bias1 ? bias1[col] : 0.f, b1 = bias1 ? bias1[col + 1] : 0.f;
                    float vx = x + b0, vy = y + b1;
                    if (relu1) { vx = fmaxf(vx, 0.f); vy = fmaxf(vy, 0.f); }
                    wone2(O1h, off, vx, vy);
                }
                if (O2h) {
                    float b0 = bias2 ? bias2[col] : 0.f, b1 = bias2 ? bias2[col + 1] : 0.f;
                    wone2(O2h, off, x + b0, y + b1);
                }
            }
        }
}

// ---------------- fused flash attention ----------------
#define F_QC 0
#define F_QP 16384
#define F_K  32768
#define F_R  49152
#define F_V0 81920
#define F_V1 90112
#define F_P0 98304
#define F_P1 114688
#define F_ST 131072
#define F_SMEM (131072 + 8 * 3200)

__global__ void __launch_bounds__(256) flash_kernel()
{
    extern __shared__ char smem[];
    const uint32_t sbase = smem_u32(smem);
    const int tid = threadIdx.x, lane = tid & 31, w = tid >> 5;
    const int g = lane >> 2, tig = lane & 3;
    const int n = blockIdx.y, q0 = blockIdx.x * 128;
    const int nDH = n * DH;
    const int w0 = w * 16;

#pragma unroll
    for (int i = 0; i < 4; i++) {
        int u = tid + (i << 8);
        int row = u >> 3, c16 = u & 7;
        uint32_t sw = SWZ((uint32_t)row * 128 + (uint32_t)(c16 << 4));
        long long gq = (long long)(q0 + row) * HD + nDH + (c16 << 3);
        *(uint4*)(smem + F_QC + sw) = *(const uint4*)(g_qch + gq);
        *(uint4*)(smem + F_QP + sw) = *(const uint4*)(g_qph + gq);
    }

    auto loadKR = [&](int c0) {
#pragma unroll
        for (int i = 0; i < 4; i++) {
            int u = tid + (i << 8);
            int row = u >> 3, c16 = u & 7;
            cpasync16(sbase + F_K + SWZ((uint32_t)row * 128 + (uint32_t)(c16 << 4)),
                      g_kh + (long long)(c0 + row) * HD + nDH + (c16 << 3));
        }
        const int rstart = QL + c0 - q0 - 127;
#pragma unroll
        for (int i = 0; i < 8; i++) {
            int u = tid + (i << 8);
            int row = u >> 3, c16 = u & 7;
            int rg = rstart + row; if (rg > RL - 1) rg = RL - 1;
            cpasync16(sbase + F_R + SWZ((uint32_t)row * 128 + (uint32_t)(c16 << 4)),
                      g_rh + (long long)rg * HD + nDH + (c16 << 3));
        }
    };
    const half_t* vt = g_vth + (long long)(n * 64) * CL;
    auto loadV = [&](int c0) {
#pragma unroll
        for (int i = 0; i < 2; i++) {
            int u = tid + (i << 8);
            int row = u >> 3, c16 = u & 7;
            uint32_t sw = SWZ((uint32_t)row * 128 + (uint32_t)(c16 << 4));
            cpasync16(sbase + F_V0 + sw, vt + (long long)row * CL + c0 + (c16 << 3));
            cpasync16(sbase + F_V1 + sw, vt + (long long)row * CL + c0 + 64 + (c16 << 3));
        }
    };

    loadKR(0); CP_COMMIT();
    loadV(0); CP_COMMIT();

    const float e0a = g_eseg[(0 * NH + n) * QL + q0 + w0 + g];
    const float e1a = g_eseg[(1 * NH + n) * QL + q0 + w0 + g];
    const float e0b = g_eseg[(0 * NH + n) * QL + q0 + w0 + g + 8];
    const float e1b = g_eseg[(1 * NH + n) * QL + q0 + w0 + g + 8];
    float* stg = (float*)(smem + F_ST + w * 3200);

    float m0r = -3.0e38f, m1r = -3.0e38f, l0r = 0.f, l1r = 0.f;
    float accO[8][4] = {};

    for (int cb = 0; cb < CL / 128; cb++) {
        const int c0 = cb * 128;
        CP_WAIT(1);
        __syncthreads();

        // ---- phase 1: scores into registers ----
        float sc[4][16];
#pragma unroll
        for (int ch = 0; ch < 4; ch++) {
            float accA[4][4] = {};
            float accB[6][4] = {};
            const int s0 = ch * 32 - w0 + 112;
#pragma unroll
            for (int ks = 0; ks < 4; ks++) {
                uint32_t aqc[4], aqp[4];
                ldm4(aqc, sbase + F_QC, w0, ks * 16, lane);
                ldm4(aqp, sbase + F_QP, w0, ks * 16, lane);
                uint32_t kh[2][4];
                ldm4(kh[0], sbase + F_K, ch * 32, ks * 16, lane);
                ldm4(kh[1], sbase + F_K, ch * 32 + 16, ks * 16, lane);
#pragma unroll
                for (int nt = 0; nt < 4; nt++) {
                    const int p = nt >> 1, o = nt & 1;
                    uint32_t fb[2] = { kh[p][o], kh[p][2 + o] };
                    mma_f16(accA[nt], aqc, fb);
                }
                uint32_t rh[3][4];
#pragma unroll
                for (int p = 0; p < 3; p++)
                    ldm4(rh[p], sbase + F_R, s0 + p * 16, ks * 16, lane);
#pragma unroll
                for (int nt = 0; nt < 6; nt++) {
                    const int p = nt >> 1, o = nt & 1;
                    uint32_t fb[2] = { rh[p][o], rh[p][2 + o] };
                    mma_f16(accB[nt], aqp, fb);
                }
            }
#pragma unroll
            for (int nt = 0; nt < 6; nt++) {
                int cc = nt * 8 + 2 * tig;
                stg[g * 50 + cc] = accB[nt][0];
                stg[g * 50 + cc + 1] = accB[nt][1];
                stg[(g + 8) * 50 + cc] = accB[nt][2];
                stg[(g + 8) * 50 + cc + 1] = accB[nt][3];
            }
            __syncwarp();
#pragma unroll
            for (int nt = 0; nt < 4; nt++) {
                const int jl = nt * 8 + 2 * tig;
                const float bd0 = stg[g * 50 + jl - g + 15], bd1 = stg[g * 50 + jl - g + 16];
                const float bd2 = stg[(g + 8) * 50 + jl - g + 7], bd3 = stg[(g + 8) * 50 + jl - g + 8];
                const int qa = q0 + w0 + g, cc = c0 + ch * 32 + jl;
                uchar2 ba = *(const uchar2*)(g_msk + (size_t)qa * CL + cc);
                uchar2 bb = *(const uchar2*)(g_msk + (size_t)(qa + 8) * CL + cc);
                sc[ch][nt * 4 + 0] = (accA[nt][0] + bd0 + ((ba.x & 1) ? e1a : e0a)) * 0.125f - ((ba.x & 2) ? 1e30f : 0.f);
                sc[ch][nt * 4 + 1] = (accA[nt][1] + bd1 + ((ba.y & 1) ? e1a : e0a)) * 0.125f - ((ba.y & 2) ? 1e30f : 0.f);
                sc[ch][nt * 4 + 2] = (accA[nt][2] + bd2 + ((bb.x & 1) ? e1b : e0b)) * 0.125f - ((bb.x & 2) ? 1e30f : 0.f);
                sc[ch][nt * 4 + 3] = (accA[nt][3] + bd3 + ((bb.y & 1) ? e1b : e0b)) * 0.125f - ((bb.y & 2) ? 1e30f : 0.f);
            }
            __syncwarp();
        }
        __syncthreads();
        if (cb + 1 < CL / 128) { loadKR(c0 + 128); CP_COMMIT(); }

        // ---- phase 2: online softmax ----
        float rmax0 = -3.0e38f, rmax1 = -3.0e38f;
#pragma unroll
        for (int ch = 0; ch < 4; ch++)
#pragma unroll
            for (int nt = 0; nt < 4; nt++) {
                rmax0 = fmaxf(rmax0, fmaxf(sc[ch][nt * 4], sc[ch][nt * 4 + 1]));
                rmax1 = fmaxf(rmax1, fmaxf(sc[ch][nt * 4 + 2], sc[ch][nt * 4 + 3]));
            }
        rmax0 = fmaxf(rmax0, __shfl_xor_sync(0xffffffffu, rmax0, 1));
        rmax0 = fmaxf(rmax0, __shfl_xor_sync(0xffffffffu, rmax0, 2));
        rmax1 = fmaxf(rmax1, __shfl_xor_sync(0xffffffffu, rmax1, 1));
        rmax1 = fmaxf(rmax1, __shfl_xor_sync(0xffffffffu, rmax1, 2));
        const float mn0 = fmaxf(m0r, rmax0), mn1 = fmaxf(m1r, rmax1);
        const float s0s = __expf(m0r - mn0), s1s = __expf(m1r - mn1);
        m0r = mn0; m1r = mn1;
        float cs0 = 0.f, cs1 = 0.f;
#pragma unroll
        for (int ch = 0; ch < 4; ch++) {
            const uint32_t pofs = (ch < 2 ? F_P0 : F_P1);
            const int cofs = (ch & 1) * 32;
#pragma unroll
            for (int nt = 0; nt < 4; nt++) {
                float p0 = __expf(sc[ch][nt * 4 + 0] - mn0);
                float p1 = __expf(sc[ch][nt * 4 + 1] - mn0);
                float p2 = __expf(sc[ch][nt * 4 + 2] - mn1);
                float p3 = __expf(sc[ch][nt * 4 + 3] - mn1);
                cs0 += p0 + p1; cs1 += p2 + p3;
                const uint32_t col2 = (uint32_t)(cofs + nt * 8 + 2 * tig) * 2;
                *(half2_t*)(smem + pofs + SWZ((uint32_t)(w0 + g) * 128 + col2)) =
                    __floats2half2_rn(p0, p1);
                *(half2_t*)(smem + pofs + SWZ((uint32_t)(w0 + g + 8) * 128 + col2)) =
                    __floats2half2_rn(p2, p3);
            }
        }
        cs0 += __shfl_xor_sync(0xffffffffu, cs0, 1);
        cs0 += __shfl_xor_sync(0xffffffffu, cs0, 2);
        cs1 += __shfl_xor_sync(0xffffffffu, cs1, 1);
        cs1 += __shfl_xor_sync(0xffffffffu, cs1, 2);
        l0r = l0r * s0s + cs0;
        l1r = l1r * s1s + cs1;
#pragma unroll
        for (int t = 0; t < 8; t++) {
            accO[t][0] *= s0s; accO[t][1] *= s0s;
            accO[t][2] *= s1s; accO[t][3] *= s1s;
        }
        __syncwarp();
        CP_WAIT(1);
        if (cb + 1 >= CL / 128) CP_WAIT(0);

        // ---- phase 3: PV MMA ----
#pragma unroll
        for (int ks = 0; ks < 8; ks++) {
            const uint32_t pb = sbase + (ks < 4 ? F_P0 : F_P1);
            const uint32_t vb = sbase + (ks < 4 ? F_V0 : F_V1);
            const int kk = (ks & 3) * 16;
            uint32_t aP[4];
            ldm4(aP, pb, w0, kk, lane);
            uint32_t bH[4][4];
#pragma unroll
            for (int p = 0; p < 4; p++)
                ldm4(bH[p], vb, p * 16, kk, lane);
#pragma unroll
            for (int t = 0; t < 8; t++) {
                const int p = t >> 1, o = t & 1;
                uint32_t fb[2] = { bH[p][o], bH[p][2 + o] };
                mma_f16(accO[t], aP, fb);
            }
        }
        __syncthreads();
        if (cb + 1 < CL / 128) { loadV(c0 + 128); CP_COMMIT(); }
    }

    const float li0 = 1.0f / l0r, li1 = 1.0f / l1r;
#pragma unroll
    for (int t = 0; t < 8; t++) {
        const int dloc = (t >> 1) * 16 + (t & 1) * 8 + 2 * tig;
        const long long col = (long long)n * 64 + dloc;
        wone2(g_ath, (long long)(q0 + w0 + g) * HD + col, accO[t][0] * li0, accO[t][1] * li0);
        wone2(g_ath, (long long)(q0 + w0 + g + 8) * HD + col, accO[t][2] * li1, accO[t][3] * li1);
    }
}

// ---------------- eseg ----------------
__global__ void __launch_bounds__(256) eseg_kernel(
    const float* __restrict__ cb, const float* __restrict__ sb, const float* __restrict__ seg)
{
    int idx = blockIdx.x * 256 + threadIdx.x;
    if (idx >= 2 * NH * QL) return;
    int s = idx / (NH * QL), n = (idx / QL) % NH, qi = idx % QL;
    const half_t* qh = g_qch + (long long)qi * HD + n * DH;
    const float* cbr = cb + n * DH;
    const float* sbr = sb + n * DH;
    const float* sg = seg + s * (NH * DH) + n * DH;
    float acc = 0.f;
#pragma unroll
    for (int d = 0; d < DH; d++) {
        float q = __half2float(qh[d]) - cbr[d] + sbr[d];
        acc += q * sg[d];
    }
    g_eseg[idx] = acc;
}

// ---------------- residual + LN ----------------
__global__ void __launch_bounds__(256) ln_kernel(
    const float* __restrict__ x, const float* __restrict__ res,
    const float* __restrict__ g, const float* __restrict__ b,
    float* __restrict__ out, half_t* __restrict__ oh)
{
    const int row = blockIdx.x;
    __shared__ float buf[HD];
    __shared__ float red[8];
    __shared__ float s_mean, s_rstd;
    const int tid = threadIdx.x;
    float lsum = 0.f;
    for (int i = tid; i < HD; i += 256) {
        float v = x[(long long)row * HD + i] + res[(long long)row * HD + i];
        buf[i] = v; lsum += v;
    }
    lsum = warpSum(lsum);
    if ((tid & 31) == 0) red[tid >> 5] = lsum;
    __syncthreads();
    if (tid == 0) {
        float s = 0.f;
#pragma unroll
        for (int i = 0; i < 8; i++) s += red[i];
        s_mean = s * (1.0f / HD);
    }
    __syncthreads();
    const float m = s_mean;
    float lv = 0.f;
    for (int i = tid; i < HD; i += 256) { float d = buf[i] - m; lv += d * d; }
    lv = warpSum(lv);
    __syncthreads();
    if ((tid & 31) == 0) red[tid >> 5] = lv;
    __syncthreads();
    if (tid == 0) {
        float s = 0.f;
#pragma unroll
        for (int i = 0; i < 8; i++) s += red[i];
        s_rstd = rsqrtf(s * (1.0f / HD) + 1e-12f);
    }
    __syncthreads();
    const float rs = s_rstd;
    for (int i = tid; i < HD; i += 256) {
        float o = (buf[i] - m) * rs * g[i] + b[i];
        if (out) out[(long long)row * HD + i] = o;
        if (oh) oh[(long long)row * HD + i] = __float2half_rn(o);
    }
}

// ---------------- launch ----------------
extern "C" void kernel_launch(void* const* d_in, const int* in_sizes, int n_in,
                              void* d_out, int out_size)
{
    const float* cs = (const float*)d_in[0];
    const float* mask = (const float*)d_in[1];
    const float* ctx = (const float*)d_in[2];
    const float* pos = (const float*)d_in[3];
    const float* cb = (const float*)d_in[4];
    const float* pb = (const float*)d_in[5];
    const float* seg = (const float*)d_in[6];
    const unsigned char* segm = (const unsigned char*)d_in[7];
    const float* sbb = (const float*)d_in[8];
    const float* Wq = (const float*)d_in[9];
    const float* Wk = (const float*)d_in[10];
    const float* Wv = (const float*)d_in[11];
    const float* Wr = (const float*)d_in[12];
    const float* Wo = (const float*)d_in[13];
    const float* g1 = (const float*)d_in[14];
    const float* be1 = (const float*)d_in[15];
    const float* W1 = (const float*)d_in[16];
    const float* bf1 = (const float*)d_in[17];
    const float* W2 = (const float*)d_in[18];
    const float* bf2 = (const float*)d_in[19];
    const float* g2 = (const float*)d_in[20];
    const float* be2 = (const float*)d_in[21];
    float* out = (float*)d_out;

#define SYM(T, name, sym) T* name; cudaGetSymbolAddress((void**)&name, sym)
    SYM(float, pv, g_v); SYM(float, pao, g_attnout);
    SYM(float, pfi, g_ffnin); SYM(float, pfo, g_ffnout);
    SYM(unsigned char, msk, g_msk);
    SYM(half_t, csh, g_csh); SYM(half_t, ctxh, g_ctxh); SYM(half_t, posh, g_posh);
    SYM(half_t, qch, g_qch); SYM(half_t, qph, g_qph);
    SYM(half_t, kh, g_kh); SYM(half_t, rh, g_rh);
    SYM(half_t, ath, g_ath); SYM(half_t, fih, g_fih); SYM(half_t, fhh, g_fhh);
    SYM(half_t, wqh, g_wqh); SYM(half_t, wkh, g_wkh); SYM(half_t, wvh, g_wvh);
    SYM(half_t, wrh, g_wrh); SYM(half_t, woh, g_woh);
    SYM(half_t, w1h, g_w1h); SYM(half_t, w2h, g_w2h);
    SYM(half_t, vth, g_vth);
#undef SYM

    cudaFuncSetAttribute(hmma_gemm_kernel, cudaFuncAttributeMaxDynamicSharedMemorySize, GM_SMEM);
    cudaFuncSetAttribute(flash_kernel, cudaFuncAttributeMaxDynamicSharedMemorySize, F_SMEM);

    dim3 blk(256);
    cvt4_kernel<<<(QL * HD / 4) / 256, blk>>>(cs, csh, QL * HD / 4);
    cvt4_kernel<<<(CL * HD / 4) / 256, blk>>>(ctx, ctxh, CL * HD / 4);
    cvt4_kernel<<<(RL * HD / 4) / 256, blk>>>(pos, posh, RL * HD / 4);
    CT4 ct4;
    ct4.in[0] = Wq; ct4.out[0] = wqh;
    ct4.in[1] = Wk; ct4.out[1] = wkh;
    ct4.in[2] = Wv; ct4.out[2] = wvh;
    ct4.in[3] = Wr; ct4.out[3] = wrh;
    convT4_kernel<<<dim3(HD / 32, HD / 32, 4), blk>>>(ct4);
    conv_kernel<<<(HD * HD) / 256, blk>>>(Wo, woh, HD * HD);
    convT_kernel<<<dim3(FF / 32, HD / 32), blk>>>(W1, w1h, HD, FF);
    convT_kernel<<<dim3(HD / 32, FF / 32), blk>>>(W2, w2h, FF, HD);
    msk_kernel<<<(QL * CL / 4) / 256, blk>>>(mask, segm, msk);

    // projections
    hmma_gemm_kernel<<<dim3(HD / 64, QL / 128), blk, GM_SMEM>>>(
        csh, wqh, nullptr, nullptr, qch, cb, 0, qph, pb, HD, HD, HD, HD);
    hmma_gemm_kernel<<<dim3(HD / 64, CL / 128), blk, GM_SMEM>>>(
        ctxh, wkh, nullptr, nullptr, kh, nullptr, 0, nullptr, nullptr, HD, HD, HD, HD);
    hmma_gemm_kernel<<<dim3(HD / 64, CL / 128), blk, GM_SMEM>>>(
        ctxh, wvh, pv, nullptr, nullptr, nullptr, 0, nullptr, nullptr, HD, HD, HD, HD);
    hmma_gemm_kernel<<<dim3(HD / 64, RL / 128), blk, GM_SMEM>>>(
        posh, wrh, nullptr, nullptr, rh, nullptr, 0, nullptr, nullptr, HD, HD, HD, HD);

    convT_kernel<<<dim3(HD / 32, CL / 32), blk>>>(pv, vth, CL, HD);
    eseg_kernel<<<(2 * NH * QL) / 256, blk>>>(cb, sbb, seg);

    flash_kernel<<<dim3(QL / 128, NH), blk, F_SMEM>>>();

    hmma_gemm_kernel<<<dim3(HD / 64, QL / 128), blk, GM_SMEM>>>(
        ath, woh, pao, nullptr, nullptr, nullptr, 0, nullptr, nullptr, HD, HD, HD, HD);

    ln_kernel<<<QL, blk>>>(pao, cs, g1, be1, pfi, fih);

    hmma_gemm_kernel<<<dim3(FF / 64, QL / 128), blk, GM_SMEM>>>(
        fih, w1h, nullptr, nullptr, fhh, bf1, 1, nullptr, nullptr, HD, HD, HD, FF);
    hmma_gemm_kernel<<<dim3(HD / 64, QL / 128), blk, GM_SMEM>>>(
        fhh, w2h, pfo, bf2, nullptr, nullptr, 0, nullptr, nullptr, FF, FF, FF, HD);

    ln_kernel<<<QL, blk>>>(pfo, pfi, g2, be2, out, nullptr);
}

// round 13
// speedup vs baseline: 2.4028x; 1.0846x over previous
#include <cuda_runtime.h>
#include <cuda_fp16.h>
#include <math.h>
#include <stdint.h>

#define QL 2048
#define CL 2048
#define HD 1024
#define NH 16
#define DH 64
#define FF 4096
#define RL 4096
typedef __half half_t;
typedef __half2 half2_t;

// ---------------- scratch ----------------
__device__ float g_eseg[2 * NH * QL];
__device__ float g_attnout[QL * HD];
__device__ float g_ffnin[QL * HD];
__device__ float g_ffnout[QL * HD];
__device__ unsigned char g_msk[(size_t)QL * CL];   // bit0=segment, bit1=masked
__device__ half_t g_csh[QL * HD];
__device__ half_t g_ctxh[CL * HD];
__device__ half_t g_posh[RL * HD];
__device__ half_t g_qch[QL * HD];
__device__ half_t g_qph[QL * HD];
__device__ half_t g_vh[CL * HD];            // v, [c][n*d] fp16 (written by proj epilogue)
__device__ half_t g_ath[QL * HD];
__device__ half_t g_fih[QL * HD];
__device__ half_t g_fhh[(size_t)QL * FF];
__device__ half_t g_kh[CL * HD];
__device__ half_t g_rh[RL * HD];
__device__ half_t g_wqh[HD * HD];           // K-major [H, N*D] (native)
__device__ half_t g_wkh[HD * HD];
__device__ half_t g_wvh[HD * HD];
__device__ half_t g_wrh[HD * HD];
__device__ half_t g_woh[HD * HD];           // N-major (native for attn-out)
__device__ half_t g_w1h[(size_t)FF * HD];   // K-major [H, FF]
__device__ half_t g_w2h[(size_t)FF * HD];   // K-major [FF, H]

#define SWZ(o) ((o) ^ (((o) >> 3) & 0x70))

__device__ __forceinline__ uint32_t smem_u32(const void* p) {
    uint32_t a;
    asm("{ .reg .u64 t; cvta.to.shared.u64 t, %1; cvt.u32.u64 %0, t; }" : "=r"(a) : "l"(p));
    return a;
}
__device__ __forceinline__ void cpasync16(uint32_t s, const void* g) {
    asm volatile("cp.async.cg.shared.global [%0], [%1], 16;" :: "r"(s), "l"(g));
}
#define CP_COMMIT() asm volatile("cp.async.commit_group;")
#define CP_WAIT(n) asm volatile("cp.async.wait_group %0;" :: "n"(n))

__device__ __forceinline__ void wone2(half_t* o, long long off, float x, float y) {
    *(half2_t*)(o + off) = __floats2half2_rn(x, y);
}
__device__ __forceinline__ float warpSum(float v) {
#pragma unroll
    for (int o = 16; o; o >>= 1) v += __shfl_xor_sync(0xffffffffu, v, o);
    return v;
}
__device__ __forceinline__ void mma_f16(float* d, const uint32_t* a, const uint32_t* b) {
    asm volatile(
        "mma.sync.aligned.m16n8k16.row.col.f32.f16.f16.f32 "
        "{%0,%1,%2,%3}, {%4,%5,%6,%7}, {%8,%9}, {%0,%1,%2,%3};"
        : "+f"(d[0]), "+f"(d[1]), "+f"(d[2]), "+f"(d[3])
        : "r"(a[0]), "r"(a[1]), "r"(a[2]), "r"(a[3]), "r"(b[0]), "r"(b[1]));
}
// non-trans: tile stored [n][k], rows = n
__device__ __forceinline__ void ldm4(uint32_t* r, uint32_t base, int row0, int k0, int lane) {
    int row = row0 + (lane & 15);
    int kc = k0 + ((lane >> 4) << 3);
    uint32_t addr = base + SWZ((uint32_t)row * 128 + (uint32_t)kc * 2);
    asm volatile("ldmatrix.sync.aligned.m8n8.x4.shared.b16 {%0,%1,%2,%3}, [%4];"
                 : "=r"(r[0]), "=r"(r[1]), "=r"(r[2]), "=r"(r[3]) : "r"(addr));
}
// trans: tile stored [k][n], rows = k; r0/r1 = k0-7/k8-15 of n-group n0..n0+7,
// r2/r3 = same for n0+8..n0+15
__device__ __forceinline__ void ldm4t(uint32_t* r, uint32_t base, int k0, int n0, int lane) {
    int row = k0 + (lane & 15);
    int nc = n0 + ((lane >> 4) << 3);
    uint32_t addr = base + SWZ((uint32_t)row * 128 + (uint32_t)nc * 2);
    asm volatile("ldmatrix.sync.aligned.m8n8.x4.trans.shared.b16 {%0,%1,%2,%3}, [%4];"
                 : "=r"(r[0]), "=r"(r[1]), "=r"(r[2]), "=r"(r[3]) : "r"(addr));
}

// ---------------- converters ----------------
__global__ void __launch_bounds__(256) cvt4_kernel(
    const float* __restrict__ in, half_t* __restrict__ o, int n4)
{
    int i = blockIdx.x * 256 + threadIdx.x;
    if (i >= n4) return;
    float4 v = *(const float4*)(in + (size_t)i * 4);
    wone2(o, (long long)i * 4, v.x, v.y);
    wone2(o, (long long)i * 4 + 2, v.z, v.w);
}
__global__ void __launch_bounds__(256) msk_kernel(
    const float* __restrict__ mask, const unsigned char* __restrict__ segmat,
    unsigned char* __restrict__ o)
{
    int i = blockIdx.x * 256 + threadIdx.x;
    float4 m = *(const float4*)(mask + (size_t)i * 4);
    uchar4 s = *(const uchar4*)(segmat + (size_t)i * 4);
    uchar4 r;
    r.x = (s.x ? 1 : 0) | (m.x != 0.f ? 2 : 0);
    r.y = (s.y ? 1 : 0) | (m.y != 0.f ? 2 : 0);
    r.z = (s.z ? 1 : 0) | (m.z != 0.f ? 2 : 0);
    r.w = (s.w ? 1 : 0) | (m.w != 0.f ? 2 : 0);
    *(uchar4*)(o + (size_t)i * 4) = r;
}

// ---------------- HMMA GEMM: C[M,N] = A[M,K] @ B, fp16 ----------------
// BT=false: B is [N,K] row-major. BT=true: B is [K,N] row-major (ldmatrix.trans).
#define ST_A 0
#define ST_B 16384
#define ST_SZ 24576
#define GM_SMEM (2 * ST_SZ)

template <bool BT>
__global__ void __launch_bounds__(256) hmma_gemm_kernel(
    const half_t* __restrict__ A, const half_t* __restrict__ B,
    float* __restrict__ C, const float* __restrict__ biasC,
    half_t* __restrict__ O1h, const float* __restrict__ bias1, int relu1,
    half_t* __restrict__ O2h, const float* __restrict__ bias2,
    int K, int lda, int ldb, int ldc)
{
    extern __shared__ char smem[];
    const uint32_t sbase = smem_u32(smem);
    const int tid = threadIdx.x, lane = tid & 31, w = tid >> 5;
    const int g = lane >> 2, tig = lane & 3;
    const int m0 = blockIdx.y * 128, n0 = blockIdx.x * 64;
    const int wm = (w >> 1) * 32, wn = (w & 1) * 32;

    auto load_stage = [&](int s, int k0) {
        uint32_t sb = sbase + s * ST_SZ;
#pragma unroll
        for (int i = 0; i < 4; i++) {
            int u = tid + (i << 8);
            int row = u >> 3, c16 = u & 7;
            uint32_t sw = SWZ((uint32_t)row * 128 + (uint32_t)(c16 << 4));
            cpasync16(sb + ST_A + sw, A + (long long)(m0 + row) * lda + k0 + (c16 << 3));
        }
#pragma unroll
        for (int i = 0; i < 2; i++) {
            int u = tid + (i << 8);
            int row = u >> 3, c16 = u & 7;
            uint32_t sw = SWZ((uint32_t)row * 128 + (uint32_t)(c16 << 4));
            if (BT)
                cpasync16(sb + ST_B + sw, B + (long long)(k0 + row) * ldb + n0 + (c16 << 3));
            else
                cpasync16(sb + ST_B + sw, B + (long long)(n0 + row) * ldb + k0 + (c16 << 3));
        }
    };

    float acc[2][4][4] = {};
    const int NC = K >> 6;
    load_stage(0, 0);
    CP_COMMIT();
    for (int c = 0; c < NC; c++) {
        if (c + 1 < NC) { load_stage((c + 1) & 1, (c + 1) << 6); CP_COMMIT(); CP_WAIT(1); }
        else CP_WAIT(0);
        __syncthreads();
        const uint32_t sb = sbase + (c & 1) * ST_SZ;
#pragma unroll
        for (int ks = 0; ks < 4; ks++) {
            uint32_t ah[2][4], bh[2][4];
            ldm4(ah[0], sb + ST_A, wm, ks * 16, lane);
            ldm4(ah[1], sb + ST_A, wm + 16, ks * 16, lane);
            if (BT) {
                ldm4t(bh[0], sb + ST_B, ks * 16, wn, lane);
                ldm4t(bh[1], sb + ST_B, ks * 16, wn + 16, lane);
            } else {
                ldm4(bh[0], sb + ST_B, wn, ks * 16, lane);
                ldm4(bh[1], sb + ST_B, wn + 16, ks * 16, lane);
            }
#pragma unroll
            for (int mt = 0; mt < 2; mt++)
#pragma unroll
                for (int nt = 0; nt < 4; nt++) {
                    const int p = nt >> 1, o = nt & 1;
                    uint32_t fb[2];
                    if (BT) { fb[0] = bh[p][2 * o]; fb[1] = bh[p][2 * o + 1]; }
                    else { fb[0] = bh[p][o]; fb[1] = bh[p][2 + o]; }
                    mma_f16(acc[mt][nt], ah[mt], fb);
                }
        }
        __syncthreads();
    }

#pragma unroll
    for (int mt = 0; mt < 2; mt++)
#pragma unroll
        for (int nt = 0; nt < 4; nt++) {
#pragma unroll
            for (int h = 0; h < 2; h++) {
                const int row = m0 + wm + mt * 16 + g + h * 8;
                const int col = n0 + wn + nt * 8 + 2 * tig;
                float x = acc[mt][nt][h * 2], y = acc[mt][nt][h * 2 + 1];
                const long long off = (long long)row * ldc + col;
                if (C) {
                    float b0 = biasC ? biasC[col] : 0.f, b1 = biasC ? biasC[col + 1] : 0.f;
                    float2 o = { x + b0, y + b1 };
                    *(float2*)(C + off) = o;
                }
                if (O1h) {
                    float b0 = bias1 ? bias1[col] : 0.f, b1 = bias1 ? bias1[col + 1] : 0.f;
                    float vx = x + b0, vy = y + b1;
                    if (relu1) { vx = fmaxf(vx, 0.f); vy = fmaxf(vy, 0.f); }
                    wone2(O1h, off, vx, vy);
                }
                if (O2h) {
                    float b0 = bias2 ? bias2[col] : 0.f, b1 = bias2 ? bias2[col + 1] : 0.f;
                    wone2(O2h, off, x + b0, y + b1);
                }
            }
        }
}

// ---------------- fused flash attention ----------------
#define F_QC 0
#define F_QP 16384
#define F_K  32768
#define F_R  49152
#define F_V  81920
#define F_P0 98304
#define F_P1 114688
#define F_ST 131072
#define F_SMEM (131072 + 8 * 3200)

__global__ void __launch_bounds__(256) flash_kernel()
{
    extern __shared__ char smem[];
    const uint32_t sbase = smem_u32(smem);
    const int tid = threadIdx.x, lane = tid & 31, w = tid >> 5;
    const int g = lane >> 2, tig = lane & 3;
    const int n = blockIdx.y, q0 = blockIdx.x * 128;
    const int nDH = n * DH;
    const int w0 = w * 16;

#pragma unroll
    for (int i = 0; i < 4; i++) {
        int u = tid + (i << 8);
        int row = u >> 3, c16 = u & 7;
        uint32_t sw = SWZ((uint32_t)row * 128 + (uint32_t)(c16 << 4));
        long long gq = (long long)(q0 + row) * HD + nDH + (c16 << 3);
        *(uint4*)(smem + F_QC + sw) = *(const uint4*)(g_qch + gq);
        *(uint4*)(smem + F_QP + sw) = *(const uint4*)(g_qph + gq);
    }

    auto loadKR = [&](int c0) {
#pragma unroll
        for (int i = 0; i < 4; i++) {
            int u = tid + (i << 8);
            int row = u >> 3, c16 = u & 7;
            cpasync16(sbase + F_K + SWZ((uint32_t)row * 128 + (uint32_t)(c16 << 4)),
                      g_kh + (long long)(c0 + row) * HD + nDH + (c16 << 3));
        }
        const int rstart = QL + c0 - q0 - 127;
#pragma unroll
        for (int i = 0; i < 8; i++) {
            int u = tid + (i << 8);
            int row = u >> 3, c16 = u & 7;
            int rg = rstart + row; if (rg > RL - 1) rg = RL - 1;
            cpasync16(sbase + F_R + SWZ((uint32_t)row * 128 + (uint32_t)(c16 << 4)),
                      g_rh + (long long)rg * HD + nDH + (c16 << 3));
        }
    };
    auto loadV = [&](int c0) {
        // V tile [128 c][64 d] fp16, rows 128B
#pragma unroll
        for (int i = 0; i < 4; i++) {
            int u = tid + (i << 8);
            int row = u >> 3, c16 = u & 7;
            cpasync16(sbase + F_V + SWZ((uint32_t)row * 128 + (uint32_t)(c16 << 4)),
                      g_vh + (long long)(c0 + row) * HD + nDH + (c16 << 3));
        }
    };

    loadKR(0); CP_COMMIT();
    loadV(0); CP_COMMIT();

    const float e0a = g_eseg[(0 * NH + n) * QL + q0 + w0 + g];
    const float e1a = g_eseg[(1 * NH + n) * QL + q0 + w0 + g];
    const float e0b = g_eseg[(0 * NH + n) * QL + q0 + w0 + g + 8];
    const float e1b = g_eseg[(1 * NH + n) * QL + q0 + w0 + g + 8];
    float* stg = (float*)(smem + F_ST + w * 3200);

    float m0r = -3.0e38f, m1r = -3.0e38f, l0r = 0.f, l1r = 0.f;
    float accO[8][4] = {};

    for (int cb = 0; cb < CL / 128; cb++) {
        const int c0 = cb * 128;
        CP_WAIT(1);
        __syncthreads();

        // ---- phase 1: scores ----
        float sc[4][16];
#pragma unroll
        for (int ch = 0; ch < 4; ch++) {
            float accA[4][4] = {};
            float accB[6][4] = {};
            const int s0 = ch * 32 - w0 + 112;
#pragma unroll
            for (int ks = 0; ks < 4; ks++) {
                uint32_t aqc[4], aqp[4];
                ldm4(aqc, sbase + F_QC, w0, ks * 16, lane);
                ldm4(aqp, sbase + F_QP, w0, ks * 16, lane);
                uint32_t kh[2][4];
                ldm4(kh[0], sbase + F_K, ch * 32, ks * 16, lane);
                ldm4(kh[1], sbase + F_K, ch * 32 + 16, ks * 16, lane);
#pragma unroll
                for (int nt = 0; nt < 4; nt++) {
                    const int p = nt >> 1, o = nt & 1;
                    uint32_t fb[2] = { kh[p][o], kh[p][2 + o] };
                    mma_f16(accA[nt], aqc, fb);
                }
                uint32_t rh[3][4];
#pragma unroll
                for (int p = 0; p < 3; p++)
                    ldm4(rh[p], sbase + F_R, s0 + p * 16, ks * 16, lane);
#pragma unroll
                for (int nt = 0; nt < 6; nt++) {
                    const int p = nt >> 1, o = nt & 1;
                    uint32_t fb[2] = { rh[p][o], rh[p][2 + o] };
                    mma_f16(accB[nt], aqp, fb);
                }
            }
#pragma unroll
            for (int nt = 0; nt < 6; nt++) {
                int cc = nt * 8 + 2 * tig;
                stg[g * 50 + cc] = accB[nt][0];
                stg[g * 50 + cc + 1] = accB[nt][1];
                stg[(g + 8) * 50 + cc] = accB[nt][2];
                stg[(g + 8) * 50 + cc + 1] = accB[nt][3];
            }
            __syncwarp();
#pragma unroll
            for (int nt = 0; nt < 4; nt++) {
                const int jl = nt * 8 + 2 * tig;
                const float bd0 = stg[g * 50 + jl - g + 15], bd1 = stg[g * 50 + jl - g + 16];
                const float bd2 = stg[(g + 8) * 50 + jl - g + 7], bd3 = stg[(g + 8) * 50 + jl - g + 8];
                const int qa = q0 + w0 + g, cc = c0 + ch * 32 + jl;
                uchar2 ba = *(const uchar2*)(g_msk + (size_t)qa * CL + cc);
                uchar2 bb = *(const uchar2*)(g_msk + (size_t)(qa + 8) * CL + cc);
                sc[ch][nt * 4 + 0] = (accA[nt][0] + bd0 + ((ba.x & 1) ? e1a : e0a)) * 0.125f - ((ba.x & 2) ? 1e30f : 0.f);
                sc[ch][nt * 4 + 1] = (accA[nt][1] + bd1 + ((ba.y & 1) ? e1a : e0a)) * 0.125f - ((ba.y & 2) ? 1e30f : 0.f);
                sc[ch][nt * 4 + 2] = (accA[nt][2] + bd2 + ((bb.x & 1) ? e1b : e0b)) * 0.125f - ((bb.x & 2) ? 1e30f : 0.f);
                sc[ch][nt * 4 + 3] = (accA[nt][3] + bd3 + ((bb.y & 1) ? e1b : e0b)) * 0.125f - ((bb.y & 2) ? 1e30f : 0.f);
            }
            __syncwarp();
        }
        __syncthreads();
        if (cb + 1 < CL / 128) { loadKR(c0 + 128); CP_COMMIT(); }

        // ---- phase 2: online softmax ----
        float rmax0 = -3.0e38f, rmax1 = -3.0e38f;
#pragma unroll
        for (int ch = 0; ch < 4; ch++)
#pragma unroll
            for (int nt = 0; nt < 4; nt++) {
                rmax0 = fmaxf(rmax0, fmaxf(sc[ch][nt * 4], sc[ch][nt * 4 + 1]));
                rmax1 = fmaxf(rmax1, fmaxf(sc[ch][nt * 4 + 2], sc[ch][nt * 4 + 3]));
            }
        rmax0 = fmaxf(rmax0, __shfl_xor_sync(0xffffffffu, rmax0, 1));
        rmax0 = fmaxf(rmax0, __shfl_xor_sync(0xffffffffu, rmax0, 2));
        rmax1 = fmaxf(rmax1, __shfl_xor_sync(0xffffffffu, rmax1, 1));
        rmax1 = fmaxf(rmax1, __shfl_xor_sync(0xffffffffu, rmax1, 2));
        const float mn0 = fmaxf(m0r, rmax0), mn1 = fmaxf(m1r, rmax1);
        const float s0s = __expf(m0r - mn0), s1s = __expf(m1r - mn1);
        m0r = mn0; m1r = mn1;
        float cs0 = 0.f, cs1 = 0.f;
#pragma unroll
        for (int ch = 0; ch < 4; ch++) {
            const uint32_t pofs = (ch < 2 ? F_P0 : F_P1);
            const int cofs = (ch & 1) * 32;
#pragma unroll
            for (int nt = 0; nt < 4; nt++) {
                float p0 = __expf(sc[ch][nt * 4 + 0] - mn0);
                float p1 = __expf(sc[ch][nt * 4 + 1] - mn0);
                float p2 = __expf(sc[ch][nt * 4 + 2] - mn1);
                float p3 = __expf(sc[ch][nt * 4 + 3] - mn1);
                cs0 += p0 + p1; cs1 += p2 + p3;
                const uint32_t col2 = (uint32_t)(cofs + nt * 8 + 2 * tig) * 2;
                *(half2_t*)(smem + pofs + SWZ((uint32_t)(w0 + g) * 128 + col2)) =
                    __floats2half2_rn(p0, p1);
                *(half2_t*)(smem + pofs + SWZ((uint32_t)(w0 + g + 8) * 128 + col2)) =
                    __floats2half2_rn(p2, p3);
            }
        }
        cs0 += __shfl_xor_sync(0xffffffffu, cs0, 1);
        cs0 += __shfl_xor_sync(0xffffffffu, cs0, 2);
        cs1 += __shfl_xor_sync(0xffffffffu, cs1, 1);
        cs1 += __shfl_xor_sync(0xffffffffu, cs1, 2);
        l0r = l0r * s0s + cs0;
        l1r = l1r * s1s + cs1;
#pragma unroll
        for (int t = 0; t < 8; t++) {
            accO[t][0] *= s0s; accO[t][1] *= s0s;
            accO[t][2] *= s1s; accO[t][3] *= s1s;
        }
        __syncwarp();
        CP_WAIT(1);
        if (cb + 1 >= CL / 128) CP_WAIT(0);

        // ---- phase 3: PV MMA (V [c][d] via trans-ldmatrix) ----
#pragma unroll
        for (int ks = 0; ks < 8; ks++) {
            const uint32_t pb = sbase + (ks < 4 ? F_P0 : F_P1);
            const int kk = (ks & 3) * 16;
            uint32_t aP[4];
            ldm4(aP, pb, w0, kk, lane);
            uint32_t bt[4][4];
#pragma unroll
            for (int p = 0; p < 4; p++)
                ldm4t(bt[p], sbase + F_V, ks * 16, p * 16, lane);
#pragma unroll
            for (int t = 0; t < 8; t++) {
                const int p = t >> 1, o = t & 1;
                uint32_t fb[2] = { bt[p][2 * o], bt[p][2 * o + 1] };
                mma_f16(accO[t], aP, fb);
            }
        }
        __syncthreads();
        if (cb + 1 < CL / 128) { loadV(c0 + 128); CP_COMMIT(); }
    }

    const float li0 = 1.0f / l0r, li1 = 1.0f / l1r;
#pragma unroll
    for (int t = 0; t < 8; t++) {
        const int dloc = (t >> 1) * 16 + (t & 1) * 8 + 2 * tig;
        const long long col = (long long)n * 64 + dloc;
        wone2(g_ath, (long long)(q0 + w0 + g) * HD + col, accO[t][0] * li0, accO[t][1] * li0);
        wone2(g_ath, (long long)(q0 + w0 + g + 8) * HD + col, accO[t][2] * li1, accO[t][3] * li1);
    }
}

// ---------------- eseg ----------------
__global__ void __launch_bounds__(256) eseg_kernel(
    const float* __restrict__ cb, const float* __restrict__ sb, const float* __restrict__ seg)
{
    int idx = blockIdx.x * 256 + threadIdx.x;
    if (idx >= 2 * NH * QL) return;
    int s = idx / (NH * QL), n = (idx / QL) % NH, qi = idx % QL;
    const half_t* qh = g_qch + (long long)qi * HD + n * DH;
    const float* cbr = cb + n * DH;
    const float* sbr = sb + n * DH;
    const float* sg = seg + s * (NH * DH) + n * DH;
    float acc = 0.f;
#pragma unroll
    for (int d = 0; d < DH; d++) {
        float q = __half2float(qh[d]) - cbr[d] + sbr[d];
        acc += q * sg[d];
    }
    g_eseg[idx] = acc;
}

// ---------------- residual + LN ----------------
__global__ void __launch_bounds__(256) ln_kernel(
    const float* __restrict__ x, const float* __restrict__ res,
    const float* __restrict__ g, const float* __restrict__ b,
    float* __restrict__ out, half_t* __restrict__ oh)
{
    const int row = blockIdx.x;
    __shared__ float buf[HD];
    __shared__ float red[8];
    __shared__ float s_mean, s_rstd;
    const int tid = threadIdx.x;
    float lsum = 0.f;
    for (int i = tid; i < HD; i += 256) {
        float v = x[(long long)row * HD + i] + res[(long long)row * HD + i];
        buf[i] = v; lsum += v;
    }
    lsum = warpSum(lsum);
    if ((tid & 31) == 0) red[tid >> 5] = lsum;
    __syncthreads();
    if (tid == 0) {
        float s = 0.f;
#pragma unroll
        for (int i = 0; i < 8; i++) s += red[i];
        s_mean = s * (1.0f / HD);
    }
    __syncthreads();
    const float m = s_mean;
    float lv = 0.f;
    for (int i = tid; i < HD; i += 256) { float d = buf[i] - m; lv += d * d; }
    lv = warpSum(lv);
    __syncthreads();
    if ((tid & 31) == 0) red[tid >> 5] = lv;
    __syncthreads();
    if (tid == 0) {
        float s = 0.f;
#pragma unroll
        for (int i = 0; i < 8; i++) s += red[i];
        s_rstd = rsqrtf(s * (1.0f / HD) + 1e-12f);
    }
    __syncthreads();
    const float rs = s_rstd;
    for (int i = tid; i < HD; i += 256) {
        float o = (buf[i] - m) * rs * g[i] + b[i];
        if (out) out[(long long)row * HD + i] = o;
        if (oh) oh[(long long)row * HD + i] = __float2half_rn(o);
    }
}

// ---------------- launch ----------------
extern "C" void kernel_launch(void* const* d_in, const int* in_sizes, int n_in,
                              void* d_out, int out_size)
{
    const float* cs = (const float*)d_in[0];
    const float* mask = (const float*)d_in[1];
    const float* ctx = (const float*)d_in[2];
    const float* pos = (const float*)d_in[3];
    const float* cb = (const float*)d_in[4];
    const float* pb = (const float*)d_in[5];
    const float* seg = (const float*)d_in[6];
    const unsigned char* segm = (const unsigned char*)d_in[7];
    const float* sbb = (const float*)d_in[8];
    const float* Wq = (const float*)d_in[9];
    const float* Wk = (const float*)d_in[10];
    const float* Wv = (const float*)d_in[11];
    const float* Wr = (const float*)d_in[12];
    const float* Wo = (const float*)d_in[13];
    const float* g1 = (const float*)d_in[14];
    const float* be1 = (const float*)d_in[15];
    const float* W1 = (const float*)d_in[16];
    const float* bf1 = (const float*)d_in[17];
    const float* W2 = (const float*)d_in[18];
    const float* bf2 = (const float*)d_in[19];
    const float* g2 = (const float*)d_in[20];
    const float* be2 = (const float*)d_in[21];
    float* out = (float*)d_out;

#define SYM(T, name, sym) T* name; cudaGetSymbolAddress((void**)&name, sym)
    SYM(float, pao, g_attnout);
    SYM(float, pfi, g_ffnin); SYM(float, pfo, g_ffnout);
    SYM(unsigned char, msk, g_msk);
    SYM(half_t, csh, g_csh); SYM(half_t, ctxh, g_ctxh); SYM(half_t, posh, g_posh);
    SYM(half_t, qch, g_qch); SYM(half_t, qph, g_qph);
    SYM(half_t, kh, g_kh); SYM(half_t, rh, g_rh); SYM(half_t, vh, g_vh);
    SYM(half_t, ath, g_ath); SYM(half_t, fih, g_fih); SYM(half_t, fhh, g_fhh);
    SYM(half_t, wqh, g_wqh); SYM(half_t, wkh, g_wkh); SYM(half_t, wvh, g_wvh);
    SYM(half_t, wrh, g_wrh); SYM(half_t, woh, g_woh);
    SYM(half_t, w1h, g_w1h); SYM(half_t, w2h, g_w2h);
#undef SYM

    cudaFuncSetAttribute(hmma_gemm_kernel<false>, cudaFuncAttributeMaxDynamicSharedMemorySize, GM_SMEM);
    cudaFuncSetAttribute(hmma_gemm_kernel<true>, cudaFuncAttributeMaxDynamicSharedMemorySize, GM_SMEM);
    cudaFuncSetAttribute(flash_kernel, cudaFuncAttributeMaxDynamicSharedMemorySize, F_SMEM);

    dim3 blk(256);
    // straight fp32 -> fp16 conversions (no transposes anywhere)
    cvt4_kernel<<<(QL * HD / 4) / 256, blk>>>(cs, csh, QL * HD / 4);
    cvt4_kernel<<<(CL * HD / 4) / 256, blk>>>(ctx, ctxh, CL * HD / 4);
    cvt4_kernel<<<(RL * HD / 4) / 256, blk>>>(pos, posh, RL * HD / 4);
    cvt4_kernel<<<(HD * HD / 4) / 256, blk>>>(Wq, wqh, HD * HD / 4);
    cvt4_kernel<<<(HD * HD / 4) / 256, blk>>>(Wk, wkh, HD * HD / 4);
    cvt4_kernel<<<(HD * HD / 4) / 256, blk>>>(Wv, wvh, HD * HD / 4);
    cvt4_kernel<<<(HD * HD / 4) / 256, blk>>>(Wr, wrh, HD * HD / 4);
    cvt4_kernel<<<(HD * HD / 4) / 256, blk>>>(Wo, woh, HD * HD / 4);
    cvt4_kernel<<<(HD * FF / 4) / 256, blk>>>(W1, w1h, HD * FF / 4);
    cvt4_kernel<<<(FF * HD / 4) / 256, blk>>>(W2, w2h, FF * HD / 4);
    msk_kernel<<<(QL * CL / 4) / 256, blk>>>(mask, segm, msk);

    // projections (B = weight, K-major, trans path)
    hmma_gemm_kernel<true><<<dim3(HD / 64, QL / 128), blk, GM_SMEM>>>(
        csh, wqh, nullptr, nullptr, qch, cb, 0, qph, pb, HD, HD, HD, HD);
    hmma_gemm_kernel<true><<<dim3(HD / 64, CL / 128), blk, GM_SMEM>>>(
        ctxh, wkh, nullptr, nullptr, kh, nullptr, 0, nullptr, nullptr, HD, HD, HD, HD);
    hmma_gemm_kernel<true><<<dim3(HD / 64, CL / 128), blk, GM_SMEM>>>(
        ctxh, wvh, nullptr, nullptr, vh, nullptr, 0, nullptr, nullptr, HD, HD, HD, HD);
    hmma_gemm_kernel<true><<<dim3(HD / 64, RL / 128), blk, GM_SMEM>>>(
        posh, wrh, nullptr, nullptr, rh, nullptr, 0, nullptr, nullptr, HD, HD, HD, HD);

    eseg_kernel<<<(2 * NH * QL) / 256, blk>>>(cb, sbb, seg);

    flash_kernel<<<dim3(QL / 128, NH), blk, F_SMEM>>>();

    // attn_out = attn @ Wo^T (Wo native [N,K], non-trans path)
    hmma_gemm_kernel<false><<<dim3(HD / 64, QL / 128), blk, GM_SMEM>>>(
        ath, woh, pao, nullptr, nullptr, nullptr, 0, nullptr, nullptr, HD, HD, HD, HD);

    ln_kernel<<<QL, blk>>>(pao, cs, g1, be1, pfi, fih);

    hmma_gemm_kernel<true><<<dim3(FF / 64, QL / 128), blk, GM_SMEM>>>(
        fih, w1h, nullptr, nullptr, fhh, bf1, 1, nullptr, nullptr, HD, HD, FF, FF);
    hmma_gemm_kernel<true><<<dim3(HD / 64, QL / 128), blk, GM_SMEM>>>(
        fhh, w2h, pfo, bf2, nullptr, nullptr, 0, nullptr, nullptr, FF, FF, HD, HD);

    ln_kernel<<<QL, blk>>>(pfo, pfi, g2, be2, out, nullptr);
}

// round 16
// speedup vs baseline: 2.5081x; 1.0438x over previous
#include <cuda_runtime.h>
#include <cuda_fp16.h>
#include <math.h>
#include <stdint.h>

#define QL 2048
#define CL 2048
#define HD 1024
#define NH 16
#define DH 64
#define FF 4096
#define RL 4096
typedef __half half_t;
typedef __half2 half2_t;

// ---------------- scratch ----------------
__device__ float g_eseg[2 * NH * QL];
__device__ float g_attnout[QL * HD];
__device__ float g_ffnin[QL * HD];
__device__ float g_ffnout[QL * HD];
__device__ unsigned char g_msk[(size_t)QL * CL];   // bit0=segment, bit1=masked
__device__ half_t g_csh[QL * HD];
__device__ half_t g_ctxh[CL * HD];
__device__ half_t g_posh[RL * HD];
__device__ half_t g_qch[QL * HD];
__device__ half_t g_qph[QL * HD];
__device__ half_t g_vh[CL * HD];
__device__ half_t g_ath[QL * HD];
__device__ half_t g_fih[QL * HD];
__device__ half_t g_fhh[(size_t)QL * FF];
__device__ half_t g_kh[CL * HD];
__device__ half_t g_rh[RL * HD];
__device__ half_t g_wqh[HD * HD];
__device__ half_t g_wkh[HD * HD];
__device__ half_t g_wvh[HD * HD];
__device__ half_t g_wrh[HD * HD];
__device__ half_t g_woh[HD * HD];
__device__ half_t g_w1h[(size_t)FF * HD];
__device__ half_t g_w2h[(size_t)FF * HD];

#define SWZ(o) ((o) ^ (((o) >> 3) & 0x70))

__device__ __forceinline__ uint32_t smem_u32(const void* p) {
    uint32_t a;
    asm("{ .reg .u64 t; cvta.to.shared.u64 t, %1; cvt.u32.u64 %0, t; }" : "=r"(a) : "l"(p));
    return a;
}
__device__ __forceinline__ void cpasync16(uint32_t s, const void* g) {
    asm volatile("cp.async.cg.shared.global [%0], [%1], 16;" :: "r"(s), "l"(g));
}
#define CP_COMMIT() asm volatile("cp.async.commit_group;")
#define CP_WAIT(n) asm volatile("cp.async.wait_group %0;" :: "n"(n))

__device__ __forceinline__ void wone2(half_t* o, long long off, float x, float y) {
    *(half2_t*)(o + off) = __floats2half2_rn(x, y);
}
__device__ __forceinline__ float warpSum(float v) {
#pragma unroll
    for (int o = 16; o; o >>= 1) v += __shfl_xor_sync(0xffffffffu, v, o);
    return v;
}
__device__ __forceinline__ void mma_f16(float* d, const uint32_t* a, const uint32_t* b) {
    asm volatile(
        "mma.sync.aligned.m16n8k16.row.col.f32.f16.f16.f32 "
        "{%0,%1,%2,%3}, {%4,%5,%6,%7}, {%8,%9}, {%0,%1,%2,%3};"
        : "+f"(d[0]), "+f"(d[1]), "+f"(d[2]), "+f"(d[3])
        : "r"(a[0]), "r"(a[1]), "r"(a[2]), "r"(a[3]), "r"(b[0]), "r"(b[1]));
}
__device__ __forceinline__ void ldm4(uint32_t* r, uint32_t base, int row0, int k0, int lane) {
    int row = row0 + (lane & 15);
    int kc = k0 + ((lane >> 4) << 3);
    uint32_t addr = base + SWZ((uint32_t)row * 128 + (uint32_t)kc * 2);
    asm volatile("ldmatrix.sync.aligned.m8n8.x4.shared.b16 {%0,%1,%2,%3}, [%4];"
                 : "=r"(r[0]), "=r"(r[1]), "=r"(r[2]), "=r"(r[3]) : "r"(addr));
}
__device__ __forceinline__ void ldm4t(uint32_t* r, uint32_t base, int k0, int n0, int lane) {
    int row = k0 + (lane & 15);
    int nc = n0 + ((lane >> 4) << 3);
    uint32_t addr = base + SWZ((uint32_t)row * 128 + (uint32_t)nc * 2);
    asm volatile("ldmatrix.sync.aligned.m8n8.x4.trans.shared.b16 {%0,%1,%2,%3}, [%4];"
                 : "=r"(r[0]), "=r"(r[1]), "=r"(r[2]), "=r"(r[3]) : "r"(addr));
}

// ---------------- merged converter (4096 elems / block, 4 float4 / thread) --
#define NSEG 10
struct CvtTab {
    const float* src[NSEG];
    half_t* dst[NSEG];
    int blk_start[NSEG + 1];
};
__global__ void __launch_bounds__(256) cvtall_kernel(CvtTab t)
{
    int b = blockIdx.x;
    int s = 0;
#pragma unroll
    for (int i = 0; i < NSEG; i++)
        if (b >= t.blk_start[i + 1]) s = i + 1;
    const float* src = t.src[s];
    half_t* dst = t.dst[s];
    // block covers [blk*4096, blk*4096+4096); thread t handles 4 float4s at
    // t*4 + i*1024 within that range  (coverage: i*1024 + t*4, t<256 -> exact)
    const long long base = (long long)(b - t.blk_start[s]) * 4096 + (long long)threadIdx.x * 4;
    float4 v[4];
#pragma unroll
    for (int i = 0; i < 4; i++)
        v[i] = *(const float4*)(src + base + i * 1024);
#pragma unroll
    for (int i = 0; i < 4; i++) {
        long long o = base + i * 1024;
        wone2(dst, o, v[i].x, v[i].y);
        wone2(dst, o + 2, v[i].z, v[i].w);
    }
}
// combined mask byte map (16 bytes / thread)
__global__ void __launch_bounds__(256) msk_kernel(
    const float* __restrict__ mask, const unsigned char* __restrict__ segmat,
    unsigned char* __restrict__ o)
{
    const long long base = ((long long)blockIdx.x * 256 + threadIdx.x) * 16;
    float4 m[4];
#pragma unroll
    for (int i = 0; i < 4; i++) m[i] = *(const float4*)(mask + base + i * 4);
    uint4 sv = *(const uint4*)(segmat + base);
    const unsigned char* s = (const unsigned char*)&sv;
    unsigned char r[16];
#pragma unroll
    for (int i = 0; i < 4; i++) {
        const float* mf = (const float*)&m[i];
#pragma unroll
        for (int j = 0; j < 4; j++)
            r[i * 4 + j] = (s[i * 4 + j] ? 1 : 0) | (mf[j] != 0.f ? 2 : 0);
    }
    *(uint4*)(o + base) = *(uint4*)r;
}

// ---------------- HMMA GEMM ----------------
#define ST_A 0
#define ST_B 16384
#define ST_SZ 24576
#define GM_SMEM (2 * ST_SZ)

template <bool BT>
__global__ void __launch_bounds__(256) hmma_gemm_kernel(
    const half_t* __restrict__ A, const half_t* __restrict__ B,
    float* __restrict__ C, const float* __restrict__ biasC,
    half_t* __restrict__ O1h, const float* __restrict__ bias1, int relu1,
    half_t* __restrict__ O2h, const float* __restrict__ bias2,
    int K, int lda, int ldb, int ldc)
{
    extern __shared__ char smem[];
    const uint32_t sbase = smem_u32(smem);
    const int tid = threadIdx.x, lane = tid & 31, w = tid >> 5;
    const int g = lane >> 2, tig = lane & 3;
    const int m0 = blockIdx.y * 128, n0 = blockIdx.x * 64;
    const int wm = (w >> 1) * 32, wn = (w & 1) * 32;

    auto load_stage = [&](int s, int k0) {
        uint32_t sb = sbase + s * ST_SZ;
#pragma unroll
        for (int i = 0; i < 4; i++) {
            int u = tid + (i << 8);
            int row = u >> 3, c16 = u & 7;
            uint32_t sw = SWZ((uint32_t)row * 128 + (uint32_t)(c16 << 4));
            cpasync16(sb + ST_A + sw, A + (long long)(m0 + row) * lda + k0 + (c16 << 3));
        }
#pragma unroll
        for (int i = 0; i < 2; i++) {
            int u = tid + (i << 8);
            int row = u >> 3, c16 = u & 7;
            uint32_t sw = SWZ((uint32_t)row * 128 + (uint32_t)(c16 << 4));
            if (BT)
                cpasync16(sb + ST_B + sw, B + (long long)(k0 + row) * ldb + n0 + (c16 << 3));
            else
                cpasync16(sb + ST_B + sw, B + (long long)(n0 + row) * ldb + k0 + (c16 << 3));
        }
    };

    float acc[2][4][4] = {};
    const int NC = K >> 6;
    load_stage(0, 0);
    CP_COMMIT();
    for (int c = 0; c < NC; c++) {
        if (c + 1 < NC) { load_stage((c + 1) & 1, (c + 1) << 6); CP_COMMIT(); CP_WAIT(1); }
        else CP_WAIT(0);
        __syncthreads();
        const uint32_t sb = sbase + (c & 1) * ST_SZ;
#pragma unroll
        for (int ks = 0; ks < 4; ks++) {
            uint32_t ah[2][4], bh[2][4];
            ldm4(ah[0], sb + ST_A, wm, ks * 16, lane);
            ldm4(ah[1], sb + ST_A, wm + 16, ks * 16, lane);
            if (BT) {
                ldm4t(bh[0], sb + ST_B, ks * 16, wn, lane);
                ldm4t(bh[1], sb + ST_B, ks * 16, wn + 16, lane);
            } else {
                ldm4(bh[0], sb + ST_B, wn, ks * 16, lane);
                ldm4(bh[1], sb + ST_B, wn + 16, ks * 16, lane);
            }
#pragma unroll
            for (int mt = 0; mt < 2; mt++)
#pragma unroll
                for (int nt = 0; nt < 4; nt++) {
                    const int p = nt >> 1, o = nt & 1;
                    uint32_t fb[2];
                    if (BT) { fb[0] = bh[p][2 * o]; fb[1] = bh[p][2 * o + 1]; }
                    else { fb[0] = bh[p][o]; fb[1] = bh[p][2 + o]; }
                    mma_f16(acc[mt][nt], ah[mt], fb);
                }
        }
        __syncthreads();
    }

#pragma unroll
    for (int mt = 0; mt < 2; mt++)
#pragma unroll
        for (int nt = 0; nt < 4; nt++) {
#pragma unroll
            for (int h = 0; h < 2; h++) {
                const int row = m0 + wm + mt * 16 + g + h * 8;
                const int col = n0 + wn + nt * 8 + 2 * tig;
                float x = acc[mt][nt][h * 2], y = acc[mt][nt][h * 2 + 1];
                const long long off = (long long)row * ldc + col;
                if (C) {
                    float b0 = biasC ? biasC[col] : 0.f, b1 = biasC ? biasC[col + 1] : 0.f;
                    float2 o = { x + b0, y + b1 };
                    *(float2*)(C + off) = o;
                }
                if (O1h) {
                    float b0 = bias1 ? bias1[col] : 0.f, b1 = bias1 ? bias1[col + 1] : 0.f;
                    float vx = x + b0, vy = y + b1;
                    if (relu1) { vx = fmaxf(vx, 0.f); vy = fmaxf(vy, 0.f); }
                    wone2(O1h, off, vx, vy);
                }
                if (O2h) {
                    float b0 = bias2 ? bias2[col] : 0.f, b1 = bias2 ? bias2[col + 1] : 0.f;
                    wone2(O2h, off, x + b0, y + b1);
                }
            }
        }
}

// ---------------- fused flash attention ----------------
#define F_QC 0
#define F_QP 16384
#define F_K  32768
#define F_R  49152
#define F_V  81920
#define F_P0 98304
#define F_P1 114688
#define F_ST 131072
#define F_SMEM (131072 + 8 * 3200)

__global__ void __launch_bounds__(256) flash_kernel()
{
    extern __shared__ char smem[];
    const uint32_t sbase = smem_u32(smem);
    const int tid = threadIdx.x, lane = tid & 31, w = tid >> 5;
    const int g = lane >> 2, tig = lane & 3;
    const int n = blockIdx.y, q0 = blockIdx.x * 128;
    const int nDH = n * DH;
    const int w0 = w * 16;

#pragma unroll
    for (int i = 0; i < 4; i++) {
        int u = tid + (i << 8);
        int row = u >> 3, c16 = u & 7;
        uint32_t sw = SWZ((uint32_t)row * 128 + (uint32_t)(c16 << 4));
        long long gq = (long long)(q0 + row) * HD + nDH + (c16 << 3);
        *(uint4*)(smem + F_QC + sw) = *(const uint4*)(g_qch + gq);
        *(uint4*)(smem + F_QP + sw) = *(const uint4*)(g_qph + gq);
    }

    auto loadKR = [&](int c0) {
#pragma unroll
        for (int i = 0; i < 4; i++) {
            int u = tid + (i << 8);
            int row = u >> 3, c16 = u & 7;
            cpasync16(sbase + F_K + SWZ((uint32_t)row * 128 + (uint32_t)(c16 << 4)),
                      g_kh + (long long)(c0 + row) * HD + nDH + (c16 << 3));
        }
        const int rstart = QL + c0 - q0 - 127;
#pragma unroll
        for (int i = 0; i < 8; i++) {
            int u = tid + (i << 8);
            int row = u >> 3, c16 = u & 7;
            int rg = rstart + row; if (rg > RL - 1) rg = RL - 1;
            cpasync16(sbase + F_R + SWZ((uint32_t)row * 128 + (uint32_t)(c16 << 4)),
                      g_rh + (long long)rg * HD + nDH + (c16 << 3));
        }
    };
    auto loadV = [&](int c0) {
#pragma unroll
        for (int i = 0; i < 4; i++) {
            int u = tid + (i << 8);
            int row = u >> 3, c16 = u & 7;
            cpasync16(sbase + F_V + SWZ((uint32_t)row * 128 + (uint32_t)(c16 << 4)),
                      g_vh + (long long)(c0 + row) * HD + nDH + (c16 << 3));
        }
    };

    loadKR(0); CP_COMMIT();
    loadV(0); CP_COMMIT();

    const float e0a = g_eseg[(0 * NH + n) * QL + q0 + w0 + g];
    const float e1a = g_eseg[(1 * NH + n) * QL + q0 + w0 + g];
    const float e0b = g_eseg[(0 * NH + n) * QL + q0 + w0 + g + 8];
    const float e1b = g_eseg[(1 * NH + n) * QL + q0 + w0 + g + 8];
    float* stg = (float*)(smem + F_ST + w * 3200);

    float m0r = -3.0e38f, m1r = -3.0e38f, l0r = 0.f, l1r = 0.f;
    float accO[8][4] = {};

    for (int cb = 0; cb < CL / 128; cb++) {
        const int c0 = cb * 128;
        CP_WAIT(1);
        __syncthreads();

        float sc[4][16];
#pragma unroll
        for (int ch = 0; ch < 4; ch++) {
            float accA[4][4] = {};
            float accB[6][4] = {};
            const int s0 = ch * 32 - w0 + 112;
#pragma unroll
            for (int ks = 0; ks < 4; ks++) {
                uint32_t aqc[4], aqp[4];
                ldm4(aqc, sbase + F_QC, w0, ks * 16, lane);
                ldm4(aqp, sbase + F_QP, w0, ks * 16, lane);
                uint32_t kh[2][4];
                ldm4(kh[0], sbase + F_K, ch * 32, ks * 16, lane);
                ldm4(kh[1], sbase + F_K, ch * 32 + 16, ks * 16, lane);
#pragma unroll
                for (int nt = 0; nt < 4; nt++) {
                    const int p = nt >> 1, o = nt & 1;
                    uint32_t fb[2] = { kh[p][o], kh[p][2 + o] };
                    mma_f16(accA[nt], aqc, fb);
                }
                uint32_t rh[3][4];
#pragma unroll
                for (int p = 0; p < 3; p++)
                    ldm4(rh[p], sbase + F_R, s0 + p * 16, ks * 16, lane);
#pragma unroll
                for (int nt = 0; nt < 6; nt++) {
                    const int p = nt >> 1, o = nt & 1;
                    uint32_t fb[2] = { rh[p][o], rh[p][2 + o] };
                    mma_f16(accB[nt], aqp, fb);
                }
            }
#pragma unroll
            for (int nt = 0; nt < 6; nt++) {
                int cc = nt * 8 + 2 * tig;
                stg[g * 50 + cc] = accB[nt][0];
                stg[g * 50 + cc + 1] = accB[nt][1];
                stg[(g + 8) * 50 + cc] = accB[nt][2];
                stg[(g + 8) * 50 + cc + 1] = accB[nt][3];
            }
            __syncwarp();
#pragma unroll
            for (int nt = 0; nt < 4; nt++) {
                const int jl = nt * 8 + 2 * tig;
                const float bd0 = stg[g * 50 + jl - g + 15], bd1 = stg[g * 50 + jl - g + 16];
                const float bd2 = stg[(g + 8) * 50 + jl - g + 7], bd3 = stg[(g + 8) * 50 + jl - g + 8];
                const int qa = q0 + w0 + g, cc = c0 + ch * 32 + jl;
                uchar2 ba = *(const uchar2*)(g_msk + (size_t)qa * CL + cc);
                uchar2 bb = *(const uchar2*)(g_msk + (size_t)(qa + 8) * CL + cc);
                sc[ch][nt * 4 + 0] = (accA[nt][0] + bd0 + ((ba.x & 1) ? e1a : e0a)) * 0.125f - ((ba.x & 2) ? 1e30f : 0.f);
                sc[ch][nt * 4 + 1] = (accA[nt][1] + bd1 + ((ba.y & 1) ? e1a : e0a)) * 0.125f - ((ba.y & 2) ? 1e30f : 0.f);
                sc[ch][nt * 4 + 2] = (accA[nt][2] + bd2 + ((bb.x & 1) ? e1b : e0b)) * 0.125f - ((bb.x & 2) ? 1e30f : 0.f);
                sc[ch][nt * 4 + 3] = (accA[nt][3] + bd3 + ((bb.y & 1) ? e1b : e0b)) * 0.125f - ((bb.y & 2) ? 1e30f : 0.f);
            }
            __syncwarp();
        }
        __syncthreads();
        if (cb + 1 < CL / 128) { loadKR(c0 + 128); CP_COMMIT(); }

        float rmax0 = -3.0e38f, rmax1 = -3.0e38f;
#pragma unroll
        for (int ch = 0; ch < 4; ch++)
#pragma unroll
            for (int nt = 0; nt < 4; nt++) {
                rmax0 = fmaxf(rmax0, fmaxf(sc[ch][nt * 4], sc[ch][nt * 4 + 1]));
                rmax1 = fmaxf(rmax1, fmaxf(sc[ch][nt * 4 + 2], sc[ch][nt * 4 + 3]));
            }
        rmax0 = fmaxf(rmax0, __shfl_xor_sync(0xffffffffu, rmax0, 1));
        rmax0 = fmaxf(rmax0, __shfl_xor_sync(0xffffffffu, rmax0, 2));
        rmax1 = fmaxf(rmax1, __shfl_xor_sync(0xffffffffu, rmax1, 1));
        rmax1 = fmaxf(rmax1, __shfl_xor_sync(0xffffffffu, rmax1, 2));
        const float mn0 = fmaxf(m0r, rmax0), mn1 = fmaxf(m1r, rmax1);
        const float s0s = __expf(m0r - mn0), s1s = __expf(m1r - mn1);
        m0r = mn0; m1r = mn1;
        float cs0 = 0.f, cs1 = 0.f;
#pragma unroll
        for (int ch = 0; ch < 4; ch++) {
            const uint32_t pofs = (ch < 2 ? F_P0 : F_P1);
            const int cofs = (ch & 1) * 32;
#pragma unroll
            for (int nt = 0; nt < 4; nt++) {
                float p0 = __expf(sc[ch][nt * 4 + 0] - mn0);
                float p1 = __expf(sc[ch][nt * 4 + 1] - mn0);
                float p2 = __expf(sc[ch][nt * 4 + 2] - mn1);
                float p3 = __expf(sc[ch][nt * 4 + 3] - mn1);
                cs0 += p0 + p1; cs1 += p2 + p3;
                const uint32_t col2 = (uint32_t)(cofs + nt * 8 + 2 * tig) * 2;
                *(half2_t*)(smem + pofs + SWZ((uint32_t)(w0 + g) * 128 + col2)) =
                    __floats2half2_rn(p0, p1);
                *(half2_t*)(smem + pofs + SWZ((uint32_t)(w0 + g + 8) * 128 + col2)) =
                    __floats2half2_rn(p2, p3);
            }
        }
        cs0 += __shfl_xor_sync(0xffffffffu, cs0, 1);
        cs0 += __shfl_xor_sync(0xffffffffu, cs0, 2);
        cs1 += __shfl_xor_sync(0xffffffffu, cs1, 1);
        cs1 += __shfl_xor_sync(0xffffffffu, cs1, 2);
        l0r = l0r * s0s + cs0;
        l1r = l1r * s1s + cs1;
#pragma unroll
        for (int t = 0; t < 8; t++) {
            accO[t][0] *= s0s; accO[t][1] *= s0s;
            accO[t][2] *= s1s; accO[t][3] *= s1s;
        }
        __syncwarp();
        CP_WAIT(1);
        if (cb + 1 >= CL / 128) CP_WAIT(0);

#pragma unroll
        for (int ks = 0; ks < 8; ks++) {
            const uint32_t pb = sbase + (ks < 4 ? F_P0 : F_P1);
            const int kk = (ks & 3) * 16;
            uint32_t aP[4];
            ldm4(aP, pb, w0, kk, lane);
            uint32_t bt[4][4];
#pragma unroll
            for (int p = 0; p < 4; p++)
                ldm4t(bt[p], sbase + F_V, ks * 16, p * 16, lane);
#pragma unroll
            for (int t = 0; t < 8; t++) {
                const int p = t >> 1, o = t & 1;
                uint32_t fb[2] = { bt[p][2 * o], bt[p][2 * o + 1] };
                mma_f16(accO[t], aP, fb);
            }
        }
        __syncthreads();
        if (cb + 1 < CL / 128) { loadV(c0 + 128); CP_COMMIT(); }
    }

    const float li0 = 1.0f / l0r, li1 = 1.0f / l1r;
#pragma unroll
    for (int t = 0; t < 8; t++) {
        const int dloc = (t >> 1) * 16 + (t & 1) * 8 + 2 * tig;
        const long long col = (long long)n * 64 + dloc;
        wone2(g_ath, (long long)(q0 + w0 + g) * HD + col, accO[t][0] * li0, accO[t][1] * li0);
        wone2(g_ath, (long long)(q0 + w0 + g + 8) * HD + col, accO[t][2] * li1, accO[t][3] * li1);
    }
}

// ---------------- eseg ----------------
__global__ void __launch_bounds__(256) eseg_kernel(
    const float* __restrict__ cb, const float* __restrict__ sb, const float* __restrict__ seg)
{
    int idx = blockIdx.x * 256 + threadIdx.x;
    if (idx >= 2 * NH * QL) return;
    int s = idx / (NH * QL), n = (idx / QL) % NH, qi = idx % QL;
    const half_t* qh = g_qch + (long long)qi * HD + n * DH;
    const float* cbr = cb + n * DH;
    const float* sbr = sb + n * DH;
    const float* sg = seg + s * (NH * DH) + n * DH;
    float acc = 0.f;
#pragma unroll
    for (int d = 0; d < DH; d++) {
        float q = __half2float(qh[d]) - cbr[d] + sbr[d];
        acc += q * sg[d];
    }
    g_eseg[idx] = acc;
}

// ---------------- residual + LN ----------------
__global__ void __launch_bounds__(256) ln_kernel(
    const float* __restrict__ x, const float* __restrict__ res,
    const float* __restrict__ g, const float* __restrict__ b,
    float* __restrict__ out, half_t* __restrict__ oh)
{
    const int row = blockIdx.x;
    __shared__ float buf[HD];
    __shared__ float red[8];
    __shared__ float s_mean, s_rstd;
    const int tid = threadIdx.x;
    float lsum = 0.f;
    for (int i = tid; i < HD; i += 256) {
        float v = x[(long long)row * HD + i] + res[(long long)row * HD + i];
        buf[i] = v; lsum += v;
    }
    lsum = warpSum(lsum);
    if ((tid & 31) == 0) red[tid >> 5] = lsum;
    __syncthreads();
    if (tid == 0) {
        float s = 0.f;
#pragma unroll
        for (int i = 0; i < 8; i++) s += red[i];
        s_mean = s * (1.0f / HD);
    }
    __syncthreads();
    const float m = s_mean;
    float lv = 0.f;
    for (int i = tid; i < HD; i += 256) { float d = buf[i] - m; lv += d * d; }
    lv = warpSum(lv);
    __syncthreads();
    if ((tid & 31) == 0) red[tid >> 5] = lv;
    __syncthreads();
    if (tid == 0) {
        float s = 0.f;
#pragma unroll
        for (int i = 0; i < 8; i++) s += red[i];
        s_rstd = rsqrtf(s * (1.0f / HD) + 1e-12f);
    }
    __syncthreads();
    const float rs = s_rstd;
    for (int i = tid; i < HD; i += 256) {
        float o = (buf[i] - m) * rs * g[i] + b[i];
        if (out) out[(long long)row * HD + i] = o;
        if (oh) oh[(long long)row * HD + i] = __float2half_rn(o);
    }
}

// ---------------- launch ----------------
extern "C" void kernel_launch(void* const* d_in, const int* in_sizes, int n_in,
                              void* d_out, int out_size)
{
    const float* cs = (const float*)d_in[0];
    const float* mask = (const float*)d_in[1];
    const float* ctx = (const float*)d_in[2];
    const float* pos = (const float*)d_in[3];
    const float* cb = (const float*)d_in[4];
    const float* pb = (const float*)d_in[5];
    const float* seg = (const float*)d_in[6];
    const unsigned char* segm = (const unsigned char*)d_in[7];
    const float* sbb = (const float*)d_in[8];
    const float* Wq = (const float*)d_in[9];
    const float* Wk = (const float*)d_in[10];
    const float* Wv = (const float*)d_in[11];
    const float* Wr = (const float*)d_in[12];
    const float* Wo = (const float*)d_in[13];
    const float* g1 = (const float*)d_in[14];
    const float* be1 = (const float*)d_in[15];
    const float* W1 = (const float*)d_in[16];
    const float* bf1 = (const float*)d_in[17];
    const float* W2 = (const float*)d_in[18];
    const float* bf2 = (const float*)d_in[19];
    const float* g2 = (const float*)d_in[20];
    const float* be2 = (const float*)d_in[21];
    float* out = (float*)d_out;

#define SYM(T, name, sym) T* name; cudaGetSymbolAddress((void**)&name, sym)
    SYM(float, pao, g_attnout);
    SYM(float, pfi, g_ffnin); SYM(float, pfo, g_ffnout);
    SYM(unsigned char, msk, g_msk);
    SYM(half_t, csh, g_csh); SYM(half_t, ctxh, g_ctxh); SYM(half_t, posh, g_posh);
    SYM(half_t, qch, g_qch); SYM(half_t, qph, g_qph);
    SYM(half_t, kh, g_kh); SYM(half_t, rh, g_rh); SYM(half_t, vh, g_vh);
    SYM(half_t, ath, g_ath); SYM(half_t, fih, g_fih); SYM(half_t, fhh, g_fhh);
    SYM(half_t, wqh, g_wqh); SYM(half_t, wkh, g_wkh); SYM(half_t, wvh, g_wvh);
    SYM(half_t, wrh, g_wrh); SYM(half_t, woh, g_woh);
    SYM(half_t, w1h, g_w1h); SYM(half_t, w2h, g_w2h);
#undef SYM

    cudaFuncSetAttribute(hmma_gemm_kernel<false>, cudaFuncAttributeMaxDynamicSharedMemorySize, GM_SMEM);
    cudaFuncSetAttribute(hmma_gemm_kernel<true>, cudaFuncAttributeMaxDynamicSharedMemorySize, GM_SMEM);
    cudaFuncSetAttribute(flash_kernel, cudaFuncAttributeMaxDynamicSharedMemorySize, F_SMEM);

    dim3 blk(256);
    // merged fp32->fp16 conversion: 4096 elements per block (verified coverage)
    CvtTab t;
    const float* srcs[NSEG] = { cs, ctx, pos, Wq, Wk, Wv, Wr, Wo, W1, W2 };
    half_t* dsts[NSEG] = { csh, ctxh, posh, wqh, wkh, wvh, wrh, woh, w1h, w2h };
    const int elems[NSEG] = { QL * HD, CL * HD, RL * HD, HD * HD, HD * HD,
                              HD * HD, HD * HD, HD * HD, HD * FF, FF * HD };
    int acc = 0;
    for (int i = 0; i < NSEG; i++) {
        t.src[i] = srcs[i]; t.dst[i] = dsts[i];
        t.blk_start[i] = acc;
        acc += elems[i] / 4096;
    }
    t.blk_start[NSEG] = acc;
    cvtall_kernel<<<acc, blk>>>(t);
    msk_kernel<<<(QL * CL / 16) / 256, blk>>>(mask, segm, msk);

    // projections (B = weight, K-major, trans path)
    hmma_gemm_kernel<true><<<dim3(HD / 64, QL / 128), blk, GM_SMEM>>>(
        csh, wqh, nullptr, nullptr, qch, cb, 0, qph, pb, HD, HD, HD, HD);
    hmma_gemm_kernel<true><<<dim3(HD / 64, CL / 128), blk, GM_SMEM>>>(
        ctxh, wkh, nullptr, nullptr, kh, nullptr, 0, nullptr, nullptr, HD, HD, HD, HD);
    hmma_gemm_kernel<true><<<dim3(HD / 64, CL / 128), blk, GM_SMEM>>>(
        ctxh, wvh, nullptr, nullptr, vh, nullptr, 0, nullptr, nullptr, HD, HD, HD, HD);
    hmma_gemm_kernel<true><<<dim3(HD / 64, RL / 128), blk, GM_SMEM>>>(
        posh, wrh, nullptr, nullptr, rh, nullptr, 0, nullptr, nullptr, HD, HD, HD, HD);

    eseg_kernel<<<(2 * NH * QL) / 256, blk>>>(cb, sbb, seg);

    flash_kernel<<<dim3(QL / 128, NH), blk, F_SMEM>>>();

    hmma_gemm_kernel<false><<<dim3(HD / 64, QL / 128), blk, GM_SMEM>>>(
        ath, woh, pao, nullptr, nullptr, nullptr, 0, nullptr, nullptr, HD, HD, HD, HD);

    ln_kernel<<<QL, blk>>>(pao, cs, g1, be1, pfi, fih);

    hmma_gemm_kernel<true><<<dim3(FF / 64, QL / 128), blk, GM_SMEM>>>(
        fih, w1h, nullptr, nullptr, fhh, bf1, 1, nullptr, nullptr, HD, HD, FF, FF);
    hmma_gemm_kernel<true><<<dim3(HD / 64, QL / 128), blk, GM_SMEM>>>(
        fhh, w2h, pfo, bf2, nullptr, nullptr, 0, nullptr, nullptr, FF, FF, HD, HD);

    ln_kernel<<<QL, blk>>>(pfo, pfi, g2, be2, out, nullptr);
}

// round 17
// speedup vs baseline: 2.5287x; 1.0082x over previous
#include <cuda_runtime.h>
#include <cuda_fp16.h>
#include <math.h>
#include <stdint.h>

#define QL 2048
#define CL 2048
#define HD 1024
#define NH 16
#define DH 64
#define FF 4096
#define RL 4096
typedef __half half_t;
typedef __half2 half2_t;

// ---------------- scratch ----------------
__device__ float g_eseg[2 * NH * QL];
__device__ float g_attnout[QL * HD];
__device__ float g_ffnin[QL * HD];
__device__ float g_ffnout[QL * HD];
__device__ unsigned char g_msk[(size_t)QL * CL];
__device__ half_t g_csh[QL * HD];
__device__ half_t g_ctxh[CL * HD];
__device__ half_t g_posh[RL * HD];
__device__ half_t g_qch[QL * HD];
__device__ half_t g_qph[QL * HD];
__device__ half_t g_vh[CL * HD];
__device__ half_t g_ath[QL * HD];
__device__ half_t g_fih[QL * HD];
__device__ half_t g_fhh[(size_t)QL * FF];
__device__ half_t g_kh[CL * HD];
__device__ half_t g_rh[RL * HD];
__device__ half_t g_wqh[HD * HD];
__device__ half_t g_wkh[HD * HD];
__device__ half_t g_wvh[HD * HD];
__device__ half_t g_wrh[HD * HD];
__device__ half_t g_woh[HD * HD];
__device__ half_t g_w1h[(size_t)FF * HD];
__device__ half_t g_w2h[(size_t)FF * HD];

#define SWZ(o) ((o) ^ (((o) >> 3) & 0x70))

__device__ __forceinline__ uint32_t smem_u32(const void* p) {
    uint32_t a;
    asm("{ .reg .u64 t; cvta.to.shared.u64 t, %1; cvt.u32.u64 %0, t; }" : "=r"(a) : "l"(p));
    return a;
}
__device__ __forceinline__ void cpasync16(uint32_t s, const void* g) {
    asm volatile("cp.async.cg.shared.global [%0], [%1], 16;" :: "r"(s), "l"(g));
}
#define CP_COMMIT() asm volatile("cp.async.commit_group;")
#define CP_WAIT(n) asm volatile("cp.async.wait_group %0;" :: "n"(n))

__device__ __forceinline__ void wone2(half_t* o, long long off, float x, float y) {
    *(half2_t*)(o + off) = __floats2half2_rn(x, y);
}
__device__ __forceinline__ float warpSum(float v) {
#pragma unroll
    for (int o = 16; o; o >>= 1) v += __shfl_xor_sync(0xffffffffu, v, o);
    return v;
}
__device__ __forceinline__ void mma_f16(float* d, const uint32_t* a, const uint32_t* b) {
    asm volatile(
        "mma.sync.aligned.m16n8k16.row.col.f32.f16.f16.f32 "
        "{%0,%1,%2,%3}, {%4,%5,%6,%7}, {%8,%9}, {%0,%1,%2,%3};"
        : "+f"(d[0]), "+f"(d[1]), "+f"(d[2]), "+f"(d[3])
        : "r"(a[0]), "r"(a[1]), "r"(a[2]), "r"(a[3]), "r"(b[0]), "r"(b[1]));
}
__device__ __forceinline__ void ldm4(uint32_t* r, uint32_t base, int row0, int k0, int lane) {
    int row = row0 + (lane & 15);
    int kc = k0 + ((lane >> 4) << 3);
    uint32_t addr = base + SWZ((uint32_t)row * 128 + (uint32_t)kc * 2);
    asm volatile("ldmatrix.sync.aligned.m8n8.x4.shared.b16 {%0,%1,%2,%3}, [%4];"
                 : "=r"(r[0]), "=r"(r[1]), "=r"(r[2]), "=r"(r[3]) : "r"(addr));
}
__device__ __forceinline__ void ldm4t(uint32_t* r, uint32_t base, int k0, int n0, int lane) {
    int row = k0 + (lane & 15);
    int nc = n0 + ((lane >> 4) << 3);
    uint32_t addr = base + SWZ((uint32_t)row * 128 + (uint32_t)nc * 2);
    asm volatile("ldmatrix.sync.aligned.m8n8.x4.trans.shared.b16 {%0,%1,%2,%3}, [%4];"
                 : "=r"(r[0]), "=r"(r[1]), "=r"(r[2]), "=r"(r[3]) : "r"(addr));
}

// ---------------- merged converter (4096 elems / block) ----------------
#define NSEG 10
struct CvtTab {
    const float* src[NSEG];
    half_t* dst[NSEG];
    int blk_start[NSEG + 1];
};
__global__ void __launch_bounds__(256) cvtall_kernel(CvtTab t)
{
    int b = blockIdx.x;
    int s = 0;
#pragma unroll
    for (int i = 0; i < NSEG; i++)
        if (b >= t.blk_start[i + 1]) s = i + 1;
    const float* src = t.src[s];
    half_t* dst = t.dst[s];
    const long long base = (long long)(b - t.blk_start[s]) * 4096 + (long long)threadIdx.x * 4;
    float4 v[4];
#pragma unroll
    for (int i = 0; i < 4; i++)
        v[i] = *(const float4*)(src + base + i * 1024);
#pragma unroll
    for (int i = 0; i < 4; i++) {
        long long o = base + i * 1024;
        wone2(dst, o, v[i].x, v[i].y);
        wone2(dst, o + 2, v[i].z, v[i].w);
    }
}
__global__ void __launch_bounds__(256) msk_kernel(
    const float* __restrict__ mask, const unsigned char* __restrict__ segmat,
    unsigned char* __restrict__ o)
{
    const long long base = ((long long)blockIdx.x * 256 + threadIdx.x) * 16;
    float4 m[4];
#pragma unroll
    for (int i = 0; i < 4; i++) m[i] = *(const float4*)(mask + base + i * 4);
    uint4 sv = *(const uint4*)(segmat + base);
    const unsigned char* s = (const unsigned char*)&sv;
    unsigned char r[16];
#pragma unroll
    for (int i = 0; i < 4; i++) {
        const float* mf = (const float*)&m[i];
#pragma unroll
        for (int j = 0; j < 4; j++)
            r[i * 4 + j] = (s[i * 4 + j] ? 1 : 0) | (mf[j] != 0.f ? 2 : 0);
    }
    *(uint4*)(o + base) = *(uint4*)r;
}

// ---------------- HMMA GEMM body: 3-stage, single barrier per chunk ---------
#define ST_A 0
#define ST_B 16384
#define ST_SZ 24576
#define GM_SMEM (3 * ST_SZ)

template <bool BT>
__device__ __forceinline__ void gemm_body(
    const half_t* __restrict__ A, const half_t* __restrict__ B,
    float* __restrict__ C, const float* __restrict__ biasC,
    half_t* __restrict__ O1h, const float* __restrict__ bias1, int relu1,
    half_t* __restrict__ O2h, const float* __restrict__ bias2,
    int K, int lda, int ldb, int ldc, int m0, int n0, char* smem)
{
    const uint32_t sbase = smem_u32(smem);
    const int tid = threadIdx.x, lane = tid & 31, w = tid >> 5;
    const int g = lane >> 2, tig = lane & 3;
    const int wm = (w >> 1) * 32, wn = (w & 1) * 32;

    auto load_stage = [&](int s, int k0) {
        uint32_t sb = sbase + s * ST_SZ;
#pragma unroll
        for (int i = 0; i < 4; i++) {
            int u = tid + (i << 8);
            int row = u >> 3, c16 = u & 7;
            uint32_t sw = SWZ((uint32_t)row * 128 + (uint32_t)(c16 << 4));
            cpasync16(sb + ST_A + sw, A + (long long)(m0 + row) * lda + k0 + (c16 << 3));
        }
#pragma unroll
        for (int i = 0; i < 2; i++) {
            int u = tid + (i << 8);
            int row = u >> 3, c16 = u & 7;
            uint32_t sw = SWZ((uint32_t)row * 128 + (uint32_t)(c16 << 4));
            if (BT)
                cpasync16(sb + ST_B + sw, B + (long long)(k0 + row) * ldb + n0 + (c16 << 3));
            else
                cpasync16(sb + ST_B + sw, B + (long long)(n0 + row) * ldb + k0 + (c16 << 3));
        }
    };

    float acc[2][4][4] = {};
    const int NC = K >> 6;
    load_stage(0, 0); CP_COMMIT();
    if (NC > 1) { load_stage(1, 64); CP_COMMIT(); }
    int sidx = 0;
    for (int c = 0; c < NC; c++) {
        CP_WAIT(1);
        __syncthreads();
        if (c + 2 < NC) {
            int st = sidx + 2; if (st >= 3) st -= 3;
            load_stage(st, (c + 2) << 6);
            CP_COMMIT();
        }
        const uint32_t sb = sbase + sidx * ST_SZ;
#pragma unroll
        for (int ks = 0; ks < 4; ks++) {
            uint32_t ah[2][4], bh[2][4];
            ldm4(ah[0], sb + ST_A, wm, ks * 16, lane);
            ldm4(ah[1], sb + ST_A, wm + 16, ks * 16, lane);
            if (BT) {
                ldm4t(bh[0], sb + ST_B, ks * 16, wn, lane);
                ldm4t(bh[1], sb + ST_B, ks * 16, wn + 16, lane);
            } else {
                ldm4(bh[0], sb + ST_B, wn, ks * 16, lane);
                ldm4(bh[1], sb + ST_B, wn + 16, ks * 16, lane);
            }
#pragma unroll
            for (int mt = 0; mt < 2; mt++)
#pragma unroll
                for (int nt = 0; nt < 4; nt++) {
                    const int p = nt >> 1, o = nt & 1;
                    uint32_t fb[2];
                    if (BT) { fb[0] = bh[p][2 * o]; fb[1] = bh[p][2 * o + 1]; }
                    else { fb[0] = bh[p][o]; fb[1] = bh[p][2 + o]; }
                    mma_f16(acc[mt][nt], ah[mt], fb);
                }
        }
        if (++sidx == 3) sidx = 0;
    }

#pragma unroll
    for (int mt = 0; mt < 2; mt++)
#pragma unroll
        for (int nt = 0; nt < 4; nt++) {
#pragma unroll
            for (int h = 0; h < 2; h++) {
                const int row = m0 + wm + mt * 16 + g + h * 8;
                const int col = n0 + wn + nt * 8 + 2 * tig;
                float x = acc[mt][nt][h * 2], y = acc[mt][nt][h * 2 + 1];
                const long long off = (long long)row * ldc + col;
                if (C) {
                    float b0 = biasC ? biasC[col] : 0.f, b1 = biasC ? biasC[col + 1] : 0.f;
                    float2 o = { x + b0, y + b1 };
                    *(float2*)(C + off) = o;
                }
                if (O1h) {
                    float b0 = bias1 ? bias1[col] : 0.f, b1 = bias1 ? bias1[col + 1] : 0.f;
                    float vx = x + b0, vy = y + b1;
                    if (relu1) { vx = fmaxf(vx, 0.f); vy = fmaxf(vy, 0.f); }
                    wone2(O1h, off, vx, vy);
                }
                if (O2h) {
                    float b0 = bias2 ? bias2[col] : 0.f, b1 = bias2 ? bias2[col + 1] : 0.f;
                    wone2(O2h, off, x + b0, y + b1);
                }
            }
        }
}

template <bool BT>
__global__ void __launch_bounds__(256) hmma_gemm_kernel(
    const half_t* __restrict__ A, const half_t* __restrict__ B,
    float* __restrict__ C, const float* __restrict__ biasC,
    half_t* __restrict__ O1h, const float* __restrict__ bias1, int relu1,
    half_t* __restrict__ O2h, const float* __restrict__ bias2,
    int K, int lda, int ldb, int ldc)
{
    extern __shared__ char smem[];
    gemm_body<BT>(A, B, C, biasC, O1h, bias1, relu1, O2h, bias2,
                  K, lda, ldb, ldc, blockIdx.y * 128, blockIdx.x * 64, smem);
}

// batched projections: 4 segments, flattened m-block index on blockIdx.y
#define PSEG 4
struct ProjTab {
    const half_t* A[PSEG];
    const half_t* B[PSEG];
    half_t* O1[PSEG];
    const float* b1[PSEG];
    half_t* O2[PSEG];
    const float* b2[PSEG];
    int blk_start[PSEG + 1];
};
__global__ void __launch_bounds__(256) proj_gemm_kernel(ProjTab t)
{
    extern __shared__ char smem[];
    int b = blockIdx.y;
    int s = 0;
#pragma unroll
    for (int i = 0; i < PSEG; i++)
        if (b >= t.blk_start[i + 1]) s = i + 1;
    const int m0 = (b - t.blk_start[s]) * 128;
    gemm_body<true>(t.A[s], t.B[s], nullptr, nullptr, t.O1[s], t.b1[s], 0,
                    t.O2[s], t.b2[s], HD, HD, HD, HD, m0, blockIdx.x * 64, smem);
}

// ---------------- fused flash attention (unchanged) ----------------
#define F_QC 0
#define F_QP 16384
#define F_K  32768
#define F_R  49152
#define F_V  81920
#define F_P0 98304
#define F_P1 114688
#define F_ST 131072
#define F_SMEM (131072 + 8 * 3200)

__global__ void __launch_bounds__(256) flash_kernel()
{
    extern __shared__ char smem[];
    const uint32_t sbase = smem_u32(smem);
    const int tid = threadIdx.x, lane = tid & 31, w = tid >> 5;
    const int g = lane >> 2, tig = lane & 3;
    const int n = blockIdx.y, q0 = blockIdx.x * 128;
    const int nDH = n * DH;
    const int w0 = w * 16;

#pragma unroll
    for (int i = 0; i < 4; i++) {
        int u = tid + (i << 8);
        int row = u >> 3, c16 = u & 7;
        uint32_t sw = SWZ((uint32_t)row * 128 + (uint32_t)(c16 << 4));
        long long gq = (long long)(q0 + row) * HD + nDH + (c16 << 3);
        *(uint4*)(smem + F_QC + sw) = *(const uint4*)(g_qch + gq);
        *(uint4*)(smem + F_QP + sw) = *(const uint4*)(g_qph + gq);
    }

    auto loadKR = [&](int c0) {
#pragma unroll
        for (int i = 0; i < 4; i++) {
            int u = tid + (i << 8);
            int row = u >> 3, c16 = u & 7;
            cpasync16(sbase + F_K + SWZ((uint32_t)row * 128 + (uint32_t)(c16 << 4)),
                      g_kh + (long long)(c0 + row) * HD + nDH + (c16 << 3));
        }
        const int rstart = QL + c0 - q0 - 127;
#pragma unroll
        for (int i = 0; i < 8; i++) {
            int u = tid + (i << 8);
            int row = u >> 3, c16 = u & 7;
            int rg = rstart + row; if (rg > RL - 1) rg = RL - 1;
            cpasync16(sbase + F_R + SWZ((uint32_t)row * 128 + (uint32_t)(c16 << 4)),
                      g_rh + (long long)rg * HD + nDH + (c16 << 3));
        }
    };
    auto loadV = [&](int c0) {
#pragma unroll
        for (int i = 0; i < 4; i++) {
            int u = tid + (i << 8);
            int row = u >> 3, c16 = u & 7;
            cpasync16(sbase + F_V + SWZ((uint32_t)row * 128 + (uint32_t)(c16 << 4)),
                      g_vh + (long long)(c0 + row) * HD + nDH + (c16 << 3));
        }
    };

    loadKR(0); CP_COMMIT();
    loadV(0); CP_COMMIT();

    const float e0a = g_eseg[(0 * NH + n) * QL + q0 + w0 + g];
    const float e1a = g_eseg[(1 * NH + n) * QL + q0 + w0 + g];
    const float e0b = g_eseg[(0 * NH + n) * QL + q0 + w0 + g + 8];
    const float e1b = g_eseg[(1 * NH + n) * QL + q0 + w0 + g + 8];
    float* stg = (float*)(smem + F_ST + w * 3200);

    float m0r = -3.0e38f, m1r = -3.0e38f, l0r = 0.f, l1r = 0.f;
    float accO[8][4] = {};

    for (int cb = 0; cb < CL / 128; cb++) {
        const int c0 = cb * 128;
        CP_WAIT(1);
        __syncthreads();

        float sc[4][16];
#pragma unroll
        for (int ch = 0; ch < 4; ch++) {
            float accA[4][4] = {};
            float accB[6][4] = {};
            const int s0 = ch * 32 - w0 + 112;
#pragma unroll
            for (int ks = 0; ks < 4; ks++) {
                uint32_t aqc[4], aqp[4];
                ldm4(aqc, sbase + F_QC, w0, ks * 16, lane);
                ldm4(aqp, sbase + F_QP, w0, ks * 16, lane);
                uint32_t kh[2][4];
                ldm4(kh[0], sbase + F_K, ch * 32, ks * 16, lane);
                ldm4(kh[1], sbase + F_K, ch * 32 + 16, ks * 16, lane);
#pragma unroll
                for (int nt = 0; nt < 4; nt++) {
                    const int p = nt >> 1, o = nt & 1;
                    uint32_t fb[2] = { kh[p][o], kh[p][2 + o] };
                    mma_f16(accA[nt], aqc, fb);
                }
                uint32_t rh[3][4];
#pragma unroll
                for (int p = 0; p < 3; p++)
                    ldm4(rh[p], sbase + F_R, s0 + p * 16, ks * 16, lane);
#pragma unroll
                for (int nt = 0; nt < 6; nt++) {
                    const int p = nt >> 1, o = nt & 1;
                    uint32_t fb[2] = { rh[p][o], rh[p][2 + o] };
                    mma_f16(accB[nt], aqp, fb);
                }
            }
#pragma unroll
            for (int nt = 0; nt < 6; nt++) {
                int cc = nt * 8 + 2 * tig;
                stg[g * 50 + cc] = accB[nt][0];
                stg[g * 50 + cc + 1] = accB[nt][1];
                stg[(g + 8) * 50 + cc] = accB[nt][2];
                stg[(g + 8) * 50 + cc + 1] = accB[nt][3];
            }
            __syncwarp();
#pragma unroll
            for (int nt = 0; nt < 4; nt++) {
                const int jl = nt * 8 + 2 * tig;
                const float bd0 = stg[g * 50 + jl - g + 15], bd1 = stg[g * 50 + jl - g + 16];
                const float bd2 = stg[(g + 8) * 50 + jl - g + 7], bd3 = stg[(g + 8) * 50 + jl - g + 8];
                const int qa = q0 + w0 + g, cc = c0 + ch * 32 + jl;
                uchar2 ba = *(const uchar2*)(g_msk + (size_t)qa * CL + cc);
                uchar2 bb = *(const uchar2*)(g_msk + (size_t)(qa + 8) * CL + cc);
                sc[ch][nt * 4 + 0] = (accA[nt][0] + bd0 + ((ba.x & 1) ? e1a : e0a)) * 0.125f - ((ba.x & 2) ? 1e30f : 0.f);
                sc[ch][nt * 4 + 1] = (accA[nt][1] + bd1 + ((ba.y & 1) ? e1a : e0a)) * 0.125f - ((ba.y & 2) ? 1e30f : 0.f);
                sc[ch][nt * 4 + 2] = (accA[nt][2] + bd2 + ((bb.x & 1) ? e1b : e0b)) * 0.125f - ((bb.x & 2) ? 1e30f : 0.f);
                sc[ch][nt * 4 + 3] = (accA[nt][3] + bd3 + ((bb.y & 1) ? e1b : e0b)) * 0.125f - ((bb.y & 2) ? 1e30f : 0.f);
            }
            __syncwarp();
        }
        __syncthreads();
        if (cb + 1 < CL / 128) { loadKR(c0 + 128); CP_COMMIT(); }

        float rmax0 = -3.0e38f, rmax1 = -3.0e38f;
#pragma unroll
        for (int ch = 0; ch < 4; ch++)
#pragma unroll
            for (int nt = 0; nt < 4; nt++) {
                rmax0 = fmaxf(rmax0, fmaxf(sc[ch][nt * 4], sc[ch][nt * 4 + 1]));
                rmax1 = fmaxf(rmax1, fmaxf(sc[ch][nt * 4 + 2], sc[ch][nt * 4 + 3]));
            }
        rmax0 = fmaxf(rmax0, __shfl_xor_sync(0xffffffffu, rmax0, 1));
        rmax0 = fmaxf(rmax0, __shfl_xor_sync(0xffffffffu, rmax0, 2));
        rmax1 = fmaxf(rmax1, __shfl_xor_sync(0xffffffffu, rmax1, 1));
        rmax1 = fmaxf(rmax1, __shfl_xor_sync(0xffffffffu, rmax1, 2));
        const float mn0 = fmaxf(m0r, rmax0), mn1 = fmaxf(m1r, rmax1);
        const float s0s = __expf(m0r - mn0), s1s = __expf(m1r - mn1);
        m0r = mn0; m1r = mn1;
        float cs0 = 0.f, cs1 = 0.f;
#pragma unroll
        for (int ch = 0; ch < 4; ch++) {
            const uint32_t pofs = (ch < 2 ? F_P0 : F_P1);
            const int cofs = (ch & 1) * 32;
#pragma unroll
            for (int nt = 0; nt < 4; nt++) {
                float p0 = __expf(sc[ch][nt * 4 + 0] - mn0);
                float p1 = __expf(sc[ch][nt * 4 + 1] - mn0);
                float p2 = __expf(sc[ch][nt * 4 + 2] - mn1);
                float p3 = __expf(sc[ch][nt * 4 + 3] - mn1);
                cs0 += p0 + p1; cs1 += p2 + p3;
                const uint32_t col2 = (uint32_t)(cofs + nt * 8 + 2 * tig) * 2;
                *(half2_t*)(smem + pofs + SWZ((uint32_t)(w0 + g) * 128 + col2)) =
                    __floats2half2_rn(p0, p1);
                *(half2_t*)(smem + pofs + SWZ((uint32_t)(w0 + g + 8) * 128 + col2)) =
                    __floats2half2_rn(p2, p3);
            }
        }
        cs0 += __shfl_xor_sync(0xffffffffu, cs0, 1);
        cs0 += __shfl_xor_sync(0xffffffffu, cs0, 2);
        cs1 += __shfl_xor_sync(0xffffffffu, cs1, 1);
        cs1 += __shfl_xor_sync(0xffffffffu, cs1, 2);
        l0r = l0r * s0s + cs0;
        l1r = l1r * s1s + cs1;
#pragma unroll
        for (int t = 0; t < 8; t++) {
            accO[t][0] *= s0s; accO[t][1] *= s0s;
            accO[t][2] *= s1s; accO[t][3] *= s1s;
        }
        __syncwarp();
        CP_WAIT(1);
        if (cb + 1 >= CL / 128) CP_WAIT(0);

#pragma unroll
        for (int ks = 0; ks < 8; ks++) {
            const uint32_t pb = sbase + (ks < 4 ? F_P0 : F_P1);
            const int kk = (ks & 3) * 16;
            uint32_t aP[4];
            ldm4(aP, pb, w0, kk, lane);
            uint32_t bt[4][4];
#pragma unroll
            for (int p = 0; p < 4; p++)
                ldm4t(bt[p], sbase + F_V, ks * 16, p * 16, lane);
#pragma unroll
            for (int t = 0; t < 8; t++) {
                const int p = t >> 1, o = t & 1;
                uint32_t fb[2] = { bt[p][2 * o], bt[p][2 * o + 1] };
                mma_f16(accO[t], aP, fb);
            }
        }
        __syncthreads();
        if (cb + 1 < CL / 128) { loadV(c0 + 128); CP_COMMIT(); }
    }

    const float li0 = 1.0f / l0r, li1 = 1.0f / l1r;
#pragma unroll
    for (int t = 0; t < 8; t++) {
        const int dloc = (t >> 1) * 16 + (t & 1) * 8 + 2 * tig;
        const long long col = (long long)n * 64 + dloc;
        wone2(g_ath, (long long)(q0 + w0 + g) * HD + col, accO[t][0] * li0, accO[t][1] * li0);
        wone2(g_ath, (long long)(q0 + w0 + g + 8) * HD + col, accO[t][2] * li1, accO[t][3] * li1);
    }
}

// ---------------- eseg ----------------
__global__ void __launch_bounds__(256) eseg_kernel(
    const float* __restrict__ cb, const float* __restrict__ sb, const float* __restrict__ seg)
{
    int idx = blockIdx.x * 256 + threadIdx.x;
    if (idx >= 2 * NH * QL) return;
    int s = idx / (NH * QL), n = (idx / QL) % NH, qi = idx % QL;
    const half_t* qh = g_qch + (long long)qi * HD + n * DH;
    const float* cbr = cb + n * DH;
    const float* sbr = sb + n * DH;
    const float* sg = seg + s * (NH * DH) + n * DH;
    float acc = 0.f;
#pragma unroll
    for (int d = 0; d < DH; d++) {
        float q = __half2float(qh[d]) - cbr[d] + sbr[d];
        acc += q * sg[d];
    }
    g_eseg[idx] = acc;
}

// ---------------- residual + LN ----------------
__global__ void __launch_bounds__(256) ln_kernel(
    const float* __restrict__ x, const float* __restrict__ res,
    const float* __restrict__ g, const float* __restrict__ b,
    float* __restrict__ out, half_t* __restrict__ oh)
{
    const int row = blockIdx.x;
    __shared__ float buf[HD];
    __shared__ float red[8];
    __shared__ float s_mean, s_rstd;
    const int tid = threadIdx.x;
    float lsum = 0.f;
    for (int i = tid; i < HD; i += 256) {
        float v = x[(long long)row * HD + i] + res[(long long)row * HD + i];
        buf[i] = v; lsum += v;
    }
    lsum = warpSum(lsum);
    if ((tid & 31) == 0) red[tid >> 5] = lsum;
    __syncthreads();
    if (tid == 0) {
        float s = 0.f;
#pragma unroll
        for (int i = 0; i < 8; i++) s += red[i];
        s_mean = s * (1.0f / HD);
    }
    __syncthreads();
    const float m = s_mean;
    float lv = 0.f;
    for (int i = tid; i < HD; i += 256) { float d = buf[i] - m; lv += d * d; }
    lv = warpSum(lv);
    __syncthreads();
    if ((tid & 31) == 0) red[tid >> 5] = lv;
    __syncthreads();
    if (tid == 0) {
        float s = 0.f;
#pragma unroll
        for (int i = 0; i < 8; i++) s += red[i];
        s_rstd = rsqrtf(s * (1.0f / HD) + 1e-12f);
    }
    __syncthreads();
    const float rs = s_rstd;
    for (int i = tid; i < HD; i += 256) {
        float o = (buf[i] - m) * rs * g[i] + b[i];
        if (out) out[(long long)row * HD + i] = o;
        if (oh) oh[(long long)row * HD + i] = __float2half_rn(o);
    }
}

// ---------------- launch ----------------
extern "C" void kernel_launch(void* const* d_in, const int* in_sizes, int n_in,
                              void* d_out, int out_size)
{
    const float* cs = (const float*)d_in[0];
    const float* mask = (const float*)d_in[1];
    const float* ctx = (const float*)d_in[2];
    const float* pos = (const float*)d_in[3];
    const float* cb = (const float*)d_in[4];
    const float* pb = (const float*)d_in[5];
    const float* seg = (const float*)d_in[6];
    const unsigned char* segm = (const unsigned char*)d_in[7];
    const float* sbb = (const float*)d_in[8];
    const float* Wq = (const float*)d_in[9];
    const float* Wk = (const float*)d_in[10];
    const float* Wv = (const float*)d_in[11];
    const float* Wr = (const float*)d_in[12];
    const float* Wo = (const float*)d_in[13];
    const float* g1 = (const float*)d_in[14];
    const float* be1 = (const float*)d_in[15];
    const float* W1 = (const float*)d_in[16];
    const float* bf1 = (const float*)d_in[17];
    const float* W2 = (const float*)d_in[18];
    const float* bf2 = (const float*)d_in[19];
    const float* g2 = (const float*)d_in[20];
    const float* be2 = (const float*)d_in[21];
    float* out = (float*)d_out;

#define SYM(T, name, sym) T* name; cudaGetSymbolAddress((void**)&name, sym)
    SYM(float, pao, g_attnout);
    SYM(float, pfi, g_ffnin); SYM(float, pfo, g_ffnout);
    SYM(unsigned char, msk, g_msk);
    SYM(half_t, csh, g_csh); SYM(half_t, ctxh, g_ctxh); SYM(half_t, posh, g_posh);
    SYM(half_t, qch, g_qch); SYM(half_t, qph, g_qph);
    SYM(half_t, kh, g_kh); SYM(half_t, rh, g_rh); SYM(half_t, vh, g_vh);
    SYM(half_t, ath, g_ath); SYM(half_t, fih, g_fih); SYM(half_t, fhh, g_fhh);
    SYM(half_t, wqh, g_wqh); SYM(half_t, wkh, g_wkh); SYM(half_t, wvh, g_wvh);
    SYM(half_t, wrh, g_wrh); SYM(half_t, woh, g_woh);
    SYM(half_t, w1h, g_w1h); SYM(half_t, w2h, g_w2h);
#undef SYM

    cudaFuncSetAttribute(hmma_gemm_kernel<false>, cudaFuncAttributeMaxDynamicSharedMemorySize, GM_SMEM);
    cudaFuncSetAttribute(hmma_gemm_kernel<true>, cudaFuncAttributeMaxDynamicSharedMemorySize, GM_SMEM);
    cudaFuncSetAttribute(proj_gemm_kernel, cudaFuncAttributeMaxDynamicSharedMemorySize, GM_SMEM);
    cudaFuncSetAttribute(flash_kernel, cudaFuncAttributeMaxDynamicSharedMemorySize, F_SMEM);

    dim3 blk(256);
    CvtTab t;
    const float* srcs[NSEG] = { cs, ctx, pos, Wq, Wk, Wv, Wr, Wo, W1, W2 };
    half_t* dsts[NSEG] = { csh, ctxh, posh, wqh, wkh, wvh, wrh, woh, w1h, w2h };
    const int elems[NSEG] = { QL * HD, CL * HD, RL * HD, HD * HD, HD * HD,
                              HD * HD, HD * HD, HD * HD, HD * FF, FF * HD };
    int acc = 0;
    for (int i = 0; i < NSEG; i++) {
        t.src[i] = srcs[i]; t.dst[i] = dsts[i];
        t.blk_start[i] = acc;
        acc += elems[i] / 4096;
    }
    t.blk_start[NSEG] = acc;
    cvtall_kernel<<<acc, blk>>>(t);
    msk_kernel<<<(QL * CL / 16) / 256, blk>>>(mask, segm, msk);

    // batched projections: q (2 outs), k, v, r
    ProjTab pt;
    pt.A[0] = csh;  pt.B[0] = wqh; pt.O1[0] = qch; pt.b1[0] = cb;      pt.O2[0] = qph;     pt.b2[0] = pb;
    pt.A[1] = ctxh; pt.B[1] = wkh; pt.O1[1] = kh;  pt.b1[1] = nullptr; pt.O2[1] = nullptr; pt.b2[1] = nullptr;
    pt.A[2] = ctxh; pt.B[2] = wvh; pt.O1[2] = vh;  pt.b1[2] = nullptr; pt.O2[2] = nullptr; pt.b2[2] = nullptr;
    pt.A[3] = posh; pt.B[3] = wrh; pt.O1[3] = rh;  pt.b1[3] = nullptr; pt.O2[3] = nullptr; pt.b2[3] = nullptr;
    const int mblk[PSEG] = { QL / 128, CL / 128, CL / 128, RL / 128 };
    int pacc = 0;
    for (int i = 0; i < PSEG; i++) { pt.blk_start[i] = pacc; pacc += mblk[i]; }
    pt.blk_start[PSEG] = pacc;
    proj_gemm_kernel<<<dim3(HD / 64, pacc), blk, GM_SMEM>>>(pt);

    eseg_kernel<<<(2 * NH * QL) / 256, blk>>>(cb, sbb, seg);

    flash_kernel<<<dim3(QL / 128, NH), blk, F_SMEM>>>();

    hmma_gemm_kernel<false><<<dim3(HD / 64, QL / 128), blk, GM_SMEM>>>(
        ath, woh, pao, nullptr, nullptr, nullptr, 0, nullptr, nullptr, HD, HD, HD, HD);

    ln_kernel<<<QL, blk>>>(pao, cs, g1, be1, pfi, fih);

    hmma_gemm_kernel<true><<<dim3(FF / 64, QL / 128), blk, GM_SMEM>>>(
        fih, w1h, nullptr, nullptr, fhh, bf1, 1, nullptr, nullptr, HD, HD, FF, FF);
    hmma_gemm_kernel<true><<<dim3(HD / 64, QL / 128), blk, GM_SMEM>>>(
        fhh, w2h, pfo, bf2, nullptr, nullptr, 0, nullptr, nullptr, FF, FF, HD, HD);

    ln_kernel<<<QL, blk>>>(pfo, pfi, g2, be2, out, nullptr);
}